// round 1
// baseline (speedup 1.0000x reference)
#include <cuda_runtime.h>
#include <cstdint>
#include <cstddef>

#define NN 50000
#define DD 512

// Scratch: two N x 512 fp32 buffers (102.4 MB each). Device globals — no runtime alloc.
__device__ float g_bufU[(size_t)NN * DD];
__device__ float g_bufV[(size_t)NN * DD];

// ---------------------------------------------------------------------------
// SGEMM: C[M x 512] = A[M x 512] @ B[512 x 512] + bias, row-major, variable lda/ldc.
// 128x128 block, BK=8, 256 threads, 8x8 per thread (two 4x4 quadrants, conflict-free).
// ---------------------------------------------------------------------------
__global__ __launch_bounds__(256, 2)
void sgemm_bias(const float* __restrict__ A, int lda,
                const float* __restrict__ B,
                const float* __restrict__ bias,
                float* __restrict__ C, int ldc, int M)
{
    __shared__ float As[8][128];
    __shared__ float Bs[8][128];

    const int tid = threadIdx.x;
    const int tx  = tid & 15;          // 0..15 -> N quadrant base
    const int ty  = tid >> 4;          // 0..15 -> M quadrant base
    const int bm  = blockIdx.y * 128;
    const int bn  = blockIdx.x * 128;

    // A-tile load mapping: each thread loads 4 consecutive k's of one row.
    const int am = tid >> 1;           // 0..127
    const int ak = (tid & 1) * 4;      // 0 or 4
    // B-tile load mapping: one float4 per thread.
    const int bk  = tid >> 5;          // 0..7
    const int bn4 = (tid & 31) * 4;    // 0..124

    float acc[8][8];
    #pragma unroll
    for (int i = 0; i < 8; i++) {
        #pragma unroll
        for (int j = 0; j < 8; j++) acc[i][j] = 0.f;
    }

    const bool a_ok = (bm + am) < M;
    const float* Aptr = A + (size_t)(bm + am) * lda + ak;
    const float* Bptr = B + (size_t)bk * DD + bn + bn4;

    for (int k0 = 0; k0 < DD; k0 += 8) {
        if (a_ok) {
            #pragma unroll
            for (int j = 0; j < 4; j++)
                As[ak + j][am] = Aptr[k0 + j];
        } else {
            #pragma unroll
            for (int j = 0; j < 4; j++)
                As[ak + j][am] = 0.f;
        }
        float4 bv = *(const float4*)(Bptr + (size_t)k0 * DD);
        *(float4*)&Bs[bk][bn4] = bv;
        __syncthreads();

        #pragma unroll
        for (int kk = 0; kk < 8; kk++) {
            float a[8], b[8];
            *(float4*)&a[0] = *(const float4*)&As[kk][ty * 4];
            *(float4*)&a[4] = *(const float4*)&As[kk][64 + ty * 4];
            *(float4*)&b[0] = *(const float4*)&Bs[kk][tx * 4];
            *(float4*)&b[4] = *(const float4*)&Bs[kk][64 + tx * 4];
            #pragma unroll
            for (int i = 0; i < 8; i++) {
                #pragma unroll
                for (int j = 0; j < 8; j++)
                    acc[i][j] += a[i] * b[j];
            }
        }
        __syncthreads();
    }

    // Epilogue: bias add + float4 stores (all targets 16B-aligned).
    #pragma unroll
    for (int i = 0; i < 8; i++) {
        int m = bm + ((i < 4) ? (ty * 4 + i) : (64 + ty * 4 + (i - 4)));
        if (m >= M) continue;
        #pragma unroll
        for (int jh = 0; jh < 2; jh++) {
            int n = bn + jh * 64 + tx * 4;
            float4 o;
            o.x = acc[i][jh * 4 + 0] + bias[n + 0];
            o.y = acc[i][jh * 4 + 1] + bias[n + 1];
            o.z = acc[i][jh * 4 + 2] + bias[n + 2];
            o.w = acc[i][jh * 4 + 3] + bias[n + 3];
            *(float4*)(C + (size_t)m * ldc + n) = o;
        }
    }
}

// ---------------------------------------------------------------------------
// SpMM: out[rows[e], :] += vals[e] * in[cols[e], :]. One warp per edge.
// Vector red.global.add.v4.f32 (sm_90+) -> 4 RED.128/lane instead of 16 scalar REDs.
// ---------------------------------------------------------------------------
__global__ void spmm_kernel(const int* __restrict__ rows, const int* __restrict__ cols,
                            const float* __restrict__ vals,
                            const float* __restrict__ in, int ldi,
                            float* __restrict__ out, int ldo, int E)
{
    int e = (int)(((size_t)blockIdx.x * blockDim.x + threadIdx.x) >> 5);
    if (e >= E) return;
    const int lane = threadIdx.x & 31;
    const int r = rows[e];
    const int c = cols[e];
    const float v = vals[e];

    const float4* src = (const float4*)(in + (size_t)c * ldi);
    float* dst = out + (size_t)r * ldo;

    #pragma unroll
    for (int i = 0; i < 4; i++) {
        float4 x = src[lane + 32 * i];
        float* p = dst + (size_t)(lane + 32 * i) * 4;
        asm volatile("red.global.add.v4.f32 [%0], {%1,%2,%3,%4};"
                     :: "l"(p), "f"(v * x.x), "f"(v * x.y), "f"(v * x.z), "f"(v * x.w)
                     : "memory");
    }
}

// ---------------------------------------------------------------------------
// x1 = a0 * n + s * (1 - n); a0 read from out[:, 512:1024).
// ---------------------------------------------------------------------------
__global__ void mix_kernel(const float* __restrict__ out, const float* __restrict__ nvec,
                           const float* __restrict__ s, float* __restrict__ x1, int M)
{
    size_t idx = (size_t)blockIdx.x * blockDim.x + threadIdx.x;
    size_t total = (size_t)M * (DD / 4);
    if (idx >= total) return;
    size_t row = idx / (DD / 4);
    int c4 = (int)(idx % (DD / 4));

    float nv = nvec[row];
    float one_m = 1.f - nv;
    float4 a  = *(const float4*)(out + row * 1024 + 512 + (size_t)c4 * 4);
    float4 sv = *(const float4*)(s + row * DD + (size_t)c4 * 4);
    float4 r;
    r.x = a.x * nv + sv.x * one_m;
    r.y = a.y * nv + sv.y * one_m;
    r.z = a.z * nv + sv.z * one_m;
    r.w = a.w * nv + sv.w * one_m;
    *(float4*)(x1 + row * DD + (size_t)c4 * 4) = r;
}

// ---------------------------------------------------------------------------
extern "C" void kernel_launch(void* const* d_in, const int* in_sizes, int n_in,
                              void* d_out, int out_size)
{
    const float* A1       = (const float*)d_in[0];   // [N, 513]
    const int*   adj_rows = (const int*)  d_in[1];   // [E]
    const int*   adj_cols = (const int*)  d_in[2];   // [E]
    const float* adj_vals = (const float*)d_in[3];   // [E]
    const float* Lin1     = (const float*)d_in[4];   // [512, 512]
    const float* Lin1_b   = (const float*)d_in[5];   // [512]
    const float* nvec     = (const float*)d_in[6];   // [N]
    const float* W1       = (const float*)d_in[7];
    const float* b1       = (const float*)d_in[8];
    const float* W2       = (const float*)d_in[9];
    const float* b2       = (const float*)d_in[10];
    const float* W3       = (const float*)d_in[11];
    const float* b3       = (const float*)d_in[12];
    float* out = (float*)d_out;

    const int M = in_sizes[6];          // N = 50000
    const int E = in_sizes[1];          // 1,600,000

    float *U, *V;
    cudaGetSymbolAddress((void**)&U, g_bufU);
    cudaGetSymbolAddress((void**)&V, g_bufV);

    dim3 gemm_grid(DD / 128, (M + 127) / 128);
    const int spmm_blocks = (int)(((size_t)E * 32 + 255) / 256);
    const int mix_blocks  = (int)(((size_t)M * (DD / 4) + 255) / 256);

    // Zero output (left half must accumulate to zero-init; right half overwritten by a0 GEMM).
    cudaMemsetAsync(out, 0, (size_t)M * 1024 * sizeof(float), 0);

    // a0 = x @ Lin1 + Lin1_bias -> out[:, 512:1024)
    sgemm_bias<<<gemm_grid, 256>>>(A1 + 1, DD + 1, Lin1, Lin1_b, out + 512, 1024, M);

    // U = x @ W1 + b1
    sgemm_bias<<<gemm_grid, 256>>>(A1 + 1, DD + 1, W1, b1, U, DD, M);

    // V = spmm(U)
    cudaMemsetAsync(V, 0, (size_t)M * DD * sizeof(float), 0);
    spmm_kernel<<<spmm_blocks, 256>>>(adj_rows, adj_cols, adj_vals, U, DD, V, DD, E);

    // U = a0 * n + V * (1 - n)     (x1)
    mix_kernel<<<mix_blocks, 256>>>(out, nvec, V, U, M);

    // V = U @ W2 + b2
    sgemm_bias<<<gemm_grid, 256>>>(U, DD, W2, b2, V, DD, M);

    // U = spmm(V)
    cudaMemsetAsync(U, 0, (size_t)M * DD * sizeof(float), 0);
    spmm_kernel<<<spmm_blocks, 256>>>(adj_rows, adj_cols, adj_vals, V, DD, U, DD, E);

    // V = U @ W3 + b3
    sgemm_bias<<<gemm_grid, 256>>>(U, DD, W3, b3, V, DD, M);

    // out[:, 0:512) = spmm(V)   (left half already zeroed)
    spmm_kernel<<<spmm_blocks, 256>>>(adj_rows, adj_cols, adj_vals, V, DD, out, 1024, E);
}

// round 3
// speedup vs baseline: 1.3465x; 1.3465x over previous
#include <cuda_runtime.h>
#include <cuda_bf16.h>
#include <cstdint>
#include <cstddef>

#define NN 50000
#define DD 512

// ---------------------------------------------------------------------------
// Device scratch (no runtime alloc allowed)
// ---------------------------------------------------------------------------
__device__ __nv_bfloat16 g_Ah[(size_t)NN * DD];          // bf16-hi of GEMM input
__device__ __nv_bfloat16 g_Al[(size_t)NN * DD];          // bf16-lo of GEMM input
__device__ float         g_U [(size_t)NN * DD];          // fp32 activations
__device__ float         g_V [(size_t)NN * DD];          // fp32 activations
__device__ __nv_bfloat16 g_WT[(size_t)4 * 2 * DD * DD];  // 4 weights x {hi,lo}, [N][K]

// ---------------------------------------------------------------------------
// Helpers
// ---------------------------------------------------------------------------
__device__ __forceinline__ uint32_t smem_to_u32(const void* p) {
    uint32_t a;
    asm("{ .reg .u64 t; cvta.to.shared.u64 t, %1; cvt.u32.u64 %0, t; }" : "=r"(a) : "l"(p));
    return a;
}

__device__ __forceinline__ void cp16(uint32_t dst, const void* src, bool valid) {
    int sz = valid ? 16 : 0;
    asm volatile("cp.async.cg.shared.global [%0], [%1], 16, %2;"
                 :: "r"(dst), "l"(src), "r"(sz) : "memory");
}
#define CP_COMMIT() asm volatile("cp.async.commit_group;" ::: "memory")
#define CP_WAIT(n)  asm volatile("cp.async.wait_group %0;" :: "n"(n) : "memory")

__device__ __forceinline__ void mma_bf16(float* d, const uint32_t* a, const uint32_t* b) {
    asm volatile("mma.sync.aligned.m16n8k16.row.col.f32.bf16.bf16.f32 "
                 "{%0,%1,%2,%3}, {%4,%5,%6,%7}, {%8,%9}, {%0,%1,%2,%3};"
                 : "+f"(d[0]), "+f"(d[1]), "+f"(d[2]), "+f"(d[3])
                 : "r"(a[0]), "r"(a[1]), "r"(a[2]), "r"(a[3]), "r"(b[0]), "r"(b[1]));
}

__device__ __forceinline__ void bf16_split(float x, __nv_bfloat16& h, __nv_bfloat16& l) {
    h = __float2bfloat16_rn(x);
    l = __float2bfloat16_rn(x - __bfloat162float(h));
}

// ---------------------------------------------------------------------------
// GEMM: C[M x 512] = (Ah+Al) @ (Bh+Bl)^T + bias      (bf16x3, mma.sync)
// BM=128, BN=128, BK=32. 256 threads, warp tile 64x32, 2-stage cp.async pipe.
// smem row stride = 20 u32 words (80B) -> conflict-free LDS fragment loads.
// ---------------------------------------------------------------------------
#define BK 32
#define RSTRIDE 20
#define TILE_WORDS (128 * RSTRIDE)
#define STAGE_WORDS (4 * TILE_WORDS)      // Ah, Al, Bh, Bl
#define GEMM_SMEM (2 * STAGE_WORDS * 4)   // 81920 bytes

__device__ __forceinline__ void gemm_load_stage(
    uint32_t sbase, int stage,
    const __nv_bfloat16* Ah, const __nv_bfloat16* Al,
    const __nv_bfloat16* Bh, const __nv_bfloat16* Bl,
    int bm, int bn, int kc, int M, int tid)
{
    const uint32_t st = sbase + (uint32_t)stage * STAGE_WORDS * 4;
    const int r0 = tid >> 2;            // 0..63
    const int r1 = r0 + 64;
    const int j  = tid & 3;             // 16B chunk within 64B row
    const uint32_t d0 = st + (uint32_t)(r0 * RSTRIDE + j * 4) * 4;
    const uint32_t d1 = st + (uint32_t)(r1 * RSTRIDE + j * 4) * 4;
    const size_t koff = (size_t)kc * BK + j * 8;
    const bool v0 = (bm + r0) < M;
    const bool v1 = (bm + r1) < M;

    cp16(d0,                  Ah + (size_t)(bm + r0) * DD + koff, v0);
    cp16(d1,                  Ah + (size_t)(bm + r1) * DD + koff, v1);
    cp16(d0 + TILE_WORDS * 4, Al + (size_t)(bm + r0) * DD + koff, v0);
    cp16(d1 + TILE_WORDS * 4, Al + (size_t)(bm + r1) * DD + koff, v1);
    cp16(d0 + TILE_WORDS * 8, Bh + (size_t)(bn + r0) * DD + koff, true);
    cp16(d1 + TILE_WORDS * 8, Bh + (size_t)(bn + r1) * DD + koff, true);
    cp16(d0 + TILE_WORDS * 12, Bl + (size_t)(bn + r0) * DD + koff, true);
    cp16(d1 + TILE_WORDS * 12, Bl + (size_t)(bn + r1) * DD + koff, true);
}

__global__ void __launch_bounds__(256, 1) gemm_bf16x3(
    const __nv_bfloat16* __restrict__ Ah, const __nv_bfloat16* __restrict__ Al,
    const __nv_bfloat16* __restrict__ Bh, const __nv_bfloat16* __restrict__ Bl,
    const float* __restrict__ bias,
    float* __restrict__ C, int ldc, int M)
{
    extern __shared__ uint32_t s[];
    const uint32_t sbase = smem_to_u32(s);
    const int tid  = threadIdx.x;
    const int warp = tid >> 5;
    const int lane = tid & 31;
    const int wm   = (warp & 1) * 64;       // warp M offset (2 warps along M)
    const int wn   = (warp >> 1) * 32;      // warp N offset (4 warps along N)
    const int grp  = lane >> 2;             // 0..7
    const int qd   = lane & 3;              // 0..3
    const int bm = blockIdx.y * 128;
    const int n0 = blockIdx.x * 128;

    float acc[4][4][4];
    #pragma unroll
    for (int i = 0; i < 4; i++)
        #pragma unroll
        for (int j = 0; j < 4; j++)
            #pragma unroll
            for (int q = 0; q < 4; q++) acc[i][j][q] = 0.f;

    gemm_load_stage(sbase, 0, Ah, Al, Bh, Bl, bm, n0, 0, M, tid);
    CP_COMMIT();

    #pragma unroll 1
    for (int kc = 0; kc < DD / BK; kc++) {
        if (kc + 1 < DD / BK) {
            gemm_load_stage(sbase, (kc + 1) & 1, Ah, Al, Bh, Bl, bm, n0, kc + 1, M, tid);
            CP_COMMIT();
            CP_WAIT(1);
        } else {
            CP_WAIT(0);
        }
        __syncthreads();

        const uint32_t* As_h = s + (kc & 1) * STAGE_WORDS;
        const uint32_t* As_l = As_h + TILE_WORDS;
        const uint32_t* Bs_h = As_h + 2 * TILE_WORDS;
        const uint32_t* Bs_l = As_h + 3 * TILE_WORDS;

        #pragma unroll
        for (int ks = 0; ks < 2; ks++) {
            const int kw = ks * 8;
            uint32_t ah[4][4], al[4][4], bh[4][2], bl[4][2];
            #pragma unroll
            for (int mi = 0; mi < 4; mi++) {
                const int base = (wm + mi * 16 + grp) * RSTRIDE + kw + qd;
                ah[mi][0] = As_h[base];
                ah[mi][1] = As_h[base + 8 * RSTRIDE];
                ah[mi][2] = As_h[base + 4];
                ah[mi][3] = As_h[base + 8 * RSTRIDE + 4];
                al[mi][0] = As_l[base];
                al[mi][1] = As_l[base + 8 * RSTRIDE];
                al[mi][2] = As_l[base + 4];
                al[mi][3] = As_l[base + 8 * RSTRIDE + 4];
            }
            #pragma unroll
            for (int nj = 0; nj < 4; nj++) {
                const int base = (wn + nj * 8 + grp) * RSTRIDE + kw + qd;
                bh[nj][0] = Bs_h[base];
                bh[nj][1] = Bs_h[base + 4];
                bl[nj][0] = Bs_l[base];
                bl[nj][1] = Bs_l[base + 4];
            }
            #pragma unroll
            for (int mi = 0; mi < 4; mi++)
                #pragma unroll
                for (int nj = 0; nj < 4; nj++) {
                    mma_bf16(acc[mi][nj], ah[mi], bh[nj]);   // hi*hi
                    mma_bf16(acc[mi][nj], al[mi], bh[nj]);   // lo*hi
                    mma_bf16(acc[mi][nj], ah[mi], bl[nj]);   // hi*lo
                }
        }
        __syncthreads();
    }

    // Epilogue: bias + store (float2 per fragment half-row)
    #pragma unroll
    for (int mi = 0; mi < 4; mi++) {
        const int gr = bm + wm + mi * 16 + grp;
        #pragma unroll
        for (int nj = 0; nj < 4; nj++) {
            const int gc = n0 + wn + nj * 8 + qd * 2;
            const float2 bz = *(const float2*)(bias + gc);
            if (gr < M) {
                float2 o = {acc[mi][nj][0] + bz.x, acc[mi][nj][1] + bz.y};
                *(float2*)(C + (size_t)gr * ldc + gc) = o;
            }
            if (gr + 8 < M) {
                float2 o = {acc[mi][nj][2] + bz.x, acc[mi][nj][3] + bz.y};
                *(float2*)(C + (size_t)(gr + 8) * ldc + gc) = o;
            }
        }
    }
}

// ---------------------------------------------------------------------------
// Split / prep / mix kernels
// ---------------------------------------------------------------------------
__global__ void split_strided(const float* __restrict__ A1,
                              __nv_bfloat16* __restrict__ hi,
                              __nv_bfloat16* __restrict__ lo, int M)
{
    size_t i = (size_t)blockIdx.x * blockDim.x + threadIdx.x;
    if (i >= (size_t)M * DD) return;
    size_t r = i >> 9;
    int c = (int)(i & 511);
    float x = A1[r * 513 + 1 + c];
    bf16_split(x, hi[i], lo[i]);
}

__global__ void split_mat(const float* __restrict__ X,
                          __nv_bfloat16* __restrict__ hi,
                          __nv_bfloat16* __restrict__ lo, int M)
{
    size_t i = (size_t)blockIdx.x * blockDim.x + threadIdx.x;
    if (i >= (size_t)M * (DD / 4)) return;
    float4 x = ((const float4*)X)[i];
    __nv_bfloat16 h[4], l[4];
    bf16_split(x.x, h[0], l[0]);
    bf16_split(x.y, h[1], l[1]);
    bf16_split(x.z, h[2], l[2]);
    bf16_split(x.w, h[3], l[3]);
    ((uint2*)hi)[i] = *(uint2*)h;
    ((uint2*)lo)[i] = *(uint2*)l;
}

// x1 = a0 * n + s * (1-n), emitted directly as bf16 hi/lo.
__global__ void mix_split(const float* __restrict__ out, const float* __restrict__ nvec,
                          const float* __restrict__ sv,
                          __nv_bfloat16* __restrict__ hi,
                          __nv_bfloat16* __restrict__ lo, int M)
{
    size_t i = (size_t)blockIdx.x * blockDim.x + threadIdx.x;
    if (i >= (size_t)M * (DD / 4)) return;
    size_t row = i >> 7;
    int c4 = (int)(i & 127);
    float nv = nvec[row];
    float om = 1.f - nv;
    float4 a = *(const float4*)(out + row * 1024 + 512 + (size_t)c4 * 4);
    float4 s4 = ((const float4*)sv)[i];
    float x0 = a.x * nv + s4.x * om;
    float x1 = a.y * nv + s4.y * om;
    float x2 = a.z * nv + s4.z * om;
    float x3 = a.w * nv + s4.w * om;
    __nv_bfloat16 h[4], l[4];
    bf16_split(x0, h[0], l[0]);
    bf16_split(x1, h[1], l[1]);
    bf16_split(x2, h[2], l[2]);
    bf16_split(x3, h[3], l[3]);
    ((uint2*)hi)[i] = *(uint2*)h;
    ((uint2*)lo)[i] = *(uint2*)l;
}

// Transpose + bf16-split a 512x512 weight: Wt[n][k] = W[k][n]
__global__ void prep_weight(const float* __restrict__ W,
                            __nv_bfloat16* __restrict__ hi,
                            __nv_bfloat16* __restrict__ lo)
{
    int i = blockIdx.x * blockDim.x + threadIdx.x;
    if (i >= DD * DD) return;
    int n = i >> 9, k = i & 511;
    float v = W[k * DD + n];
    bf16_split(v, hi[i], lo[i]);
}

// ---------------------------------------------------------------------------
// SpMM: out[rows[e], :] += vals[e] * in[cols[e], :]. One warp per edge, RED.128.
// ---------------------------------------------------------------------------
__global__ void spmm_kernel(const int* __restrict__ rows, const int* __restrict__ cols,
                            const float* __restrict__ vals,
                            const float* __restrict__ in, int ldi,
                            float* __restrict__ out, int ldo, int E)
{
    int e = (int)(((size_t)blockIdx.x * blockDim.x + threadIdx.x) >> 5);
    if (e >= E) return;
    const int lane = threadIdx.x & 31;
    const int r = rows[e];
    const int c = cols[e];
    const float v = vals[e];

    const float4* src = (const float4*)(in + (size_t)c * ldi);
    float* dst = out + (size_t)r * ldo;

    #pragma unroll
    for (int i = 0; i < 4; i++) {
        float4 x = src[lane + 32 * i];
        float* p = dst + (size_t)(lane + 32 * i) * 4;
        asm volatile("red.global.add.v4.f32 [%0], {%1,%2,%3,%4};"
                     :: "l"(p), "f"(v * x.x), "f"(v * x.y), "f"(v * x.z), "f"(v * x.w)
                     : "memory");
    }
}

// ---------------------------------------------------------------------------
// Host driver
// ---------------------------------------------------------------------------
extern "C" void kernel_launch(void* const* d_in, const int* in_sizes, int n_in,
                              void* d_out, int out_size)
{
    const float* A1       = (const float*)d_in[0];
    const int*   adj_rows = (const int*)  d_in[1];
    const int*   adj_cols = (const int*)  d_in[2];
    const float* adj_vals = (const float*)d_in[3];
    const float* Lin1     = (const float*)d_in[4];
    const float* Lin1_b   = (const float*)d_in[5];
    const float* nvec     = (const float*)d_in[6];
    const float* W1       = (const float*)d_in[7];
    const float* b1       = (const float*)d_in[8];
    const float* W2       = (const float*)d_in[9];
    const float* b2       = (const float*)d_in[10];
    const float* W3       = (const float*)d_in[11];
    const float* b3       = (const float*)d_in[12];
    float* out = (float*)d_out;

    const int M = in_sizes[6];   // 50000
    const int E = in_sizes[1];   // 1,600,000

    __nv_bfloat16 *Ah, *Al, *WT;
    float *U, *V;
    cudaGetSymbolAddress((void**)&Ah, g_Ah);
    cudaGetSymbolAddress((void**)&Al, g_Al);
    cudaGetSymbolAddress((void**)&U,  g_U);
    cudaGetSymbolAddress((void**)&V,  g_V);
    cudaGetSymbolAddress((void**)&WT, g_WT);

    cudaFuncSetAttribute(gemm_bf16x3, cudaFuncAttributeMaxDynamicSharedMemorySize, GEMM_SMEM);

    const __nv_bfloat16* Wh[4];
    const __nv_bfloat16* Wl[4];
    const float* Wsrc[4] = {Lin1, W1, W2, W3};
    for (int w = 0; w < 4; w++) {
        Wh[w] = WT + (size_t)(w * 2)     * DD * DD;
        Wl[w] = WT + (size_t)(w * 2 + 1) * DD * DD;
    }

    const dim3 ggrid(DD / 128, (M + 127) / 128);
    const int spmm_blocks  = (int)(((size_t)E * 32 + 255) / 256);
    const int split_blocks = (int)(((size_t)M * DD + 255) / 256);
    const int vec_blocks   = (int)(((size_t)M * (DD / 4) + 255) / 256);

    // Zero output: left half accumulates final SpMM, right half overwritten by a0 GEMM.
    cudaMemsetAsync(out, 0, (size_t)M * 1024 * sizeof(float), 0);

    // Weight transpose + bf16 split
    for (int w = 0; w < 4; w++)
        prep_weight<<<(DD * DD + 255) / 256, 256>>>(
            Wsrc[w], (__nv_bfloat16*)Wh[w], (__nv_bfloat16*)Wl[w]);

    // x = A1[:, 1:] -> bf16 hi/lo
    split_strided<<<split_blocks, 256>>>(A1, Ah, Al, M);

    // a0 = x @ Lin1 + bias -> out[:, 512:1024)
    gemm_bf16x3<<<ggrid, 256, GEMM_SMEM>>>(Ah, Al, Wh[0], Wl[0], Lin1_b, out + 512, 1024, M);
    // U = x @ W1 + b1
    gemm_bf16x3<<<ggrid, 256, GEMM_SMEM>>>(Ah, Al, Wh[1], Wl[1], b1, U, DD, M);

    // V = spmm(U)
    cudaMemsetAsync(V, 0, (size_t)M * DD * sizeof(float), 0);
    spmm_kernel<<<spmm_blocks, 256>>>(adj_rows, adj_cols, adj_vals, U, DD, V, DD, E);

    // x1 = a0*n + V*(1-n) -> bf16 hi/lo
    mix_split<<<vec_blocks, 256>>>(out, nvec, V, Ah, Al, M);

    // U = x1 @ W2 + b2
    gemm_bf16x3<<<ggrid, 256, GEMM_SMEM>>>(Ah, Al, Wh[2], Wl[2], b2, U, DD, M);

    // V = spmm(U)
    cudaMemsetAsync(V, 0, (size_t)M * DD * sizeof(float), 0);
    spmm_kernel<<<spmm_blocks, 256>>>(adj_rows, adj_cols, adj_vals, U, DD, V, DD, E);

    // split(V) -> bf16 hi/lo
    split_mat<<<vec_blocks, 256>>>(V, Ah, Al, M);

    // U = x2 @ W3 + b3
    gemm_bf16x3<<<ggrid, 256, GEMM_SMEM>>>(Ah, Al, Wh[3], Wl[3], b3, U, DD, M);

    // out[:, 0:512) = spmm(U)
    spmm_kernel<<<spmm_blocks, 256>>>(adj_rows, adj_cols, adj_vals, U, DD, out, 1024, E);
}

// round 4
// speedup vs baseline: 2.5877x; 1.9218x over previous
#include <cuda_runtime.h>
#include <cuda_bf16.h>
#include <cstdint>
#include <cstddef>

#define NN 50000
#define EE 1600000
#define DD 512

// ---------------------------------------------------------------------------
// Device scratch (no runtime alloc allowed)
// ---------------------------------------------------------------------------
__device__ __nv_bfloat16 g_Ah[(size_t)NN * DD];          // bf16-hi of GEMM input
__device__ __nv_bfloat16 g_Al[(size_t)NN * DD];          // bf16-lo of GEMM input
__device__ float         g_U [(size_t)NN * DD];          // fp32 activations
__device__ float         g_V [(size_t)NN * DD];          // fp32 activations
__device__ __nv_bfloat16 g_WT[(size_t)4 * 2 * DD * DD];  // 4 weights x {hi,lo}, [N][K]
// CSR scratch
__device__ int   g_cnt[NN];
__device__ int   g_rowptr[NN + 1];
__device__ int   g_cursor[NN];
__device__ int   g_colS[EE];
__device__ float g_valS[EE];

// ---------------------------------------------------------------------------
// Helpers
// ---------------------------------------------------------------------------
__device__ __forceinline__ uint32_t smem_to_u32(const void* p) {
    uint32_t a;
    asm("{ .reg .u64 t; cvta.to.shared.u64 t, %1; cvt.u32.u64 %0, t; }" : "=r"(a) : "l"(p));
    return a;
}

__device__ __forceinline__ void cp16(uint32_t dst, const void* src, bool valid) {
    int sz = valid ? 16 : 0;
    asm volatile("cp.async.cg.shared.global [%0], [%1], 16, %2;"
                 :: "r"(dst), "l"(src), "r"(sz) : "memory");
}
#define CP_COMMIT() asm volatile("cp.async.commit_group;" ::: "memory")
#define CP_WAIT(n)  asm volatile("cp.async.wait_group %0;" :: "n"(n) : "memory")

__device__ __forceinline__ void mma_bf16(float* d, const uint32_t* a, const uint32_t* b) {
    asm volatile("mma.sync.aligned.m16n8k16.row.col.f32.bf16.bf16.f32 "
                 "{%0,%1,%2,%3}, {%4,%5,%6,%7}, {%8,%9}, {%0,%1,%2,%3};"
                 : "+f"(d[0]), "+f"(d[1]), "+f"(d[2]), "+f"(d[3])
                 : "r"(a[0]), "r"(a[1]), "r"(a[2]), "r"(a[3]), "r"(b[0]), "r"(b[1]));
}

__device__ __forceinline__ void bf16_split(float x, __nv_bfloat16& h, __nv_bfloat16& l) {
    h = __float2bfloat16_rn(x);
    l = __float2bfloat16_rn(x - __bfloat162float(h));
}

// ---------------------------------------------------------------------------
// GEMM: C[M x 512] = (Ah+Al) @ (Bh+Bl)^T + bias      (bf16x3, mma.sync)
// (unchanged from round 3 — isolating the SpMM change)
// ---------------------------------------------------------------------------
#define BK 32
#define RSTRIDE 20
#define TILE_WORDS (128 * RSTRIDE)
#define STAGE_WORDS (4 * TILE_WORDS)
#define GEMM_SMEM (2 * STAGE_WORDS * 4)

__device__ __forceinline__ void gemm_load_stage(
    uint32_t sbase, int stage,
    const __nv_bfloat16* Ah, const __nv_bfloat16* Al,
    const __nv_bfloat16* Bh, const __nv_bfloat16* Bl,
    int bm, int bn, int kc, int M, int tid)
{
    const uint32_t st = sbase + (uint32_t)stage * STAGE_WORDS * 4;
    const int r0 = tid >> 2;
    const int r1 = r0 + 64;
    const int j  = tid & 3;
    const uint32_t d0 = st + (uint32_t)(r0 * RSTRIDE + j * 4) * 4;
    const uint32_t d1 = st + (uint32_t)(r1 * RSTRIDE + j * 4) * 4;
    const size_t koff = (size_t)kc * BK + j * 8;
    const bool v0 = (bm + r0) < M;
    const bool v1 = (bm + r1) < M;

    cp16(d0,                   Ah + (size_t)(bm + r0) * DD + koff, v0);
    cp16(d1,                   Ah + (size_t)(bm + r1) * DD + koff, v1);
    cp16(d0 + TILE_WORDS * 4,  Al + (size_t)(bm + r0) * DD + koff, v0);
    cp16(d1 + TILE_WORDS * 4,  Al + (size_t)(bm + r1) * DD + koff, v1);
    cp16(d0 + TILE_WORDS * 8,  Bh + (size_t)(bn + r0) * DD + koff, true);
    cp16(d1 + TILE_WORDS * 8,  Bh + (size_t)(bn + r1) * DD + koff, true);
    cp16(d0 + TILE_WORDS * 12, Bl + (size_t)(bn + r0) * DD + koff, true);
    cp16(d1 + TILE_WORDS * 12, Bl + (size_t)(bn + r1) * DD + koff, true);
}

__global__ void __launch_bounds__(256, 1) gemm_bf16x3(
    const __nv_bfloat16* __restrict__ Ah, const __nv_bfloat16* __restrict__ Al,
    const __nv_bfloat16* __restrict__ Bh, const __nv_bfloat16* __restrict__ Bl,
    const float* __restrict__ bias,
    float* __restrict__ C, int ldc, int M)
{
    extern __shared__ uint32_t s[];
    const uint32_t sbase = smem_to_u32(s);
    const int tid  = threadIdx.x;
    const int warp = tid >> 5;
    const int lane = tid & 31;
    const int wm   = (warp & 1) * 64;
    const int wn   = (warp >> 1) * 32;
    const int grp  = lane >> 2;
    const int qd   = lane & 3;
    const int bm = blockIdx.y * 128;
    const int n0 = blockIdx.x * 128;

    float acc[4][4][4];
    #pragma unroll
    for (int i = 0; i < 4; i++)
        #pragma unroll
        for (int j = 0; j < 4; j++)
            #pragma unroll
            for (int q = 0; q < 4; q++) acc[i][j][q] = 0.f;

    gemm_load_stage(sbase, 0, Ah, Al, Bh, Bl, bm, n0, 0, M, tid);
    CP_COMMIT();

    #pragma unroll 1
    for (int kc = 0; kc < DD / BK; kc++) {
        if (kc + 1 < DD / BK) {
            gemm_load_stage(sbase, (kc + 1) & 1, Ah, Al, Bh, Bl, bm, n0, kc + 1, M, tid);
            CP_COMMIT();
            CP_WAIT(1);
        } else {
            CP_WAIT(0);
        }
        __syncthreads();

        const uint32_t* As_h = s + (kc & 1) * STAGE_WORDS;
        const uint32_t* As_l = As_h + TILE_WORDS;
        const uint32_t* Bs_h = As_h + 2 * TILE_WORDS;
        const uint32_t* Bs_l = As_h + 3 * TILE_WORDS;

        #pragma unroll
        for (int ks = 0; ks < 2; ks++) {
            const int kw = ks * 8;
            uint32_t ah[4][4], al[4][4], bh[4][2], bl[4][2];
            #pragma unroll
            for (int mi = 0; mi < 4; mi++) {
                const int base = (wm + mi * 16 + grp) * RSTRIDE + kw + qd;
                ah[mi][0] = As_h[base];
                ah[mi][1] = As_h[base + 8 * RSTRIDE];
                ah[mi][2] = As_h[base + 4];
                ah[mi][3] = As_h[base + 8 * RSTRIDE + 4];
                al[mi][0] = As_l[base];
                al[mi][1] = As_l[base + 8 * RSTRIDE];
                al[mi][2] = As_l[base + 4];
                al[mi][3] = As_l[base + 8 * RSTRIDE + 4];
            }
            #pragma unroll
            for (int nj = 0; nj < 4; nj++) {
                const int base = (wn + nj * 8 + grp) * RSTRIDE + kw + qd;
                bh[nj][0] = Bs_h[base];
                bh[nj][1] = Bs_h[base + 4];
                bl[nj][0] = Bs_l[base];
                bl[nj][1] = Bs_l[base + 4];
            }
            #pragma unroll
            for (int mi = 0; mi < 4; mi++)
                #pragma unroll
                for (int nj = 0; nj < 4; nj++) {
                    mma_bf16(acc[mi][nj], ah[mi], bh[nj]);
                    mma_bf16(acc[mi][nj], al[mi], bh[nj]);
                    mma_bf16(acc[mi][nj], ah[mi], bl[nj]);
                }
        }
        __syncthreads();
    }

    #pragma unroll
    for (int mi = 0; mi < 4; mi++) {
        const int gr = bm + wm + mi * 16 + grp;
        #pragma unroll
        for (int nj = 0; nj < 4; nj++) {
            const int gc = n0 + wn + nj * 8 + qd * 2;
            const float2 bz = *(const float2*)(bias + gc);
            if (gr < M) {
                float2 o = {acc[mi][nj][0] + bz.x, acc[mi][nj][1] + bz.y};
                *(float2*)(C + (size_t)gr * ldc + gc) = o;
            }
            if (gr + 8 < M) {
                float2 o = {acc[mi][nj][2] + bz.x, acc[mi][nj][3] + bz.y};
                *(float2*)(C + (size_t)(gr + 8) * ldc + gc) = o;
            }
        }
    }
}

// ---------------------------------------------------------------------------
// CSR build: histogram -> 1-block scan -> scatter (runs once per launch)
// ---------------------------------------------------------------------------
__global__ void hist_rows(const int* __restrict__ rows, int* __restrict__ cnt, int E)
{
    int e = blockIdx.x * blockDim.x + threadIdx.x;
    if (e < E) atomicAdd(&cnt[rows[e]], 1);
}

__global__ void __launch_bounds__(1024) scan_rows(
    const int* __restrict__ cnt, int* __restrict__ row_ptr,
    int* __restrict__ cursor, int M, int E)
{
    __shared__ int sm[1024];
    const int tid = threadIdx.x;
    const int chunk = (M + 1023) >> 10;
    const int base = tid * chunk;

    int local = 0;
    for (int i = 0; i < chunk; i++) {
        int r = base + i;
        if (r < M) local += cnt[r];
    }
    sm[tid] = local;
    __syncthreads();
    // Hillis-Steele inclusive scan
    for (int off = 1; off < 1024; off <<= 1) {
        int v = (tid >= off) ? sm[tid - off] : 0;
        __syncthreads();
        sm[tid] += v;
        __syncthreads();
    }
    int run = sm[tid] - local;  // exclusive prefix of this thread's chunk
    for (int i = 0; i < chunk; i++) {
        int r = base + i;
        if (r < M) {
            row_ptr[r] = run;
            cursor[r]  = run;
            run += cnt[r];
        }
    }
    if (tid == 0) row_ptr[M] = E;
}

__global__ void scatter_edges(const int* __restrict__ rows, const int* __restrict__ cols,
                              const float* __restrict__ vals,
                              int* __restrict__ cursor,
                              int* __restrict__ colS, float* __restrict__ valS, int E)
{
    int e = blockIdx.x * blockDim.x + threadIdx.x;
    if (e >= E) return;
    int r = rows[e];
    int p = atomicAdd(&cursor[r], 1);
    colS[p] = cols[e];
    valS[p] = vals[e];
}

// ---------------------------------------------------------------------------
// CSR SpMM: one block (128 threads) per output row; register accumulation,
// no atomics. out[r, 0:512) = sum_e vals[e] * in[cols[e], :].
// ---------------------------------------------------------------------------
__global__ void __launch_bounds__(128) spmm_csr(
    const int* __restrict__ row_ptr,
    const int* __restrict__ colS, const float* __restrict__ valS,
    const float* __restrict__ in, float* __restrict__ out, int ldo)
{
    const int r   = blockIdx.x;
    const int tid = threadIdx.x;
    const size_t off = (size_t)tid * 4;

    int e = row_ptr[r];
    const int end = row_ptr[r + 1];
    float4 acc = {0.f, 0.f, 0.f, 0.f};

    for (; e + 2 <= end; e += 2) {
        const int   c0 = __ldg(colS + e);
        const int   c1 = __ldg(colS + e + 1);
        const float v0 = __ldg(valS + e);
        const float v1 = __ldg(valS + e + 1);
        const float4 x0 = *(const float4*)(in + (size_t)c0 * DD + off);
        const float4 x1 = *(const float4*)(in + (size_t)c1 * DD + off);
        acc.x = fmaf(v0, x0.x, acc.x); acc.y = fmaf(v0, x0.y, acc.y);
        acc.z = fmaf(v0, x0.z, acc.z); acc.w = fmaf(v0, x0.w, acc.w);
        acc.x = fmaf(v1, x1.x, acc.x); acc.y = fmaf(v1, x1.y, acc.y);
        acc.z = fmaf(v1, x1.z, acc.z); acc.w = fmaf(v1, x1.w, acc.w);
    }
    if (e < end) {
        const int   c0 = __ldg(colS + e);
        const float v0 = __ldg(valS + e);
        const float4 x0 = *(const float4*)(in + (size_t)c0 * DD + off);
        acc.x = fmaf(v0, x0.x, acc.x); acc.y = fmaf(v0, x0.y, acc.y);
        acc.z = fmaf(v0, x0.z, acc.z); acc.w = fmaf(v0, x0.w, acc.w);
    }
    *(float4*)(out + (size_t)r * ldo + off) = acc;
}

// ---------------------------------------------------------------------------
// Split / prep / mix kernels
// ---------------------------------------------------------------------------
__global__ void split_strided(const float* __restrict__ A1,
                              __nv_bfloat16* __restrict__ hi,
                              __nv_bfloat16* __restrict__ lo, int M)
{
    size_t i = (size_t)blockIdx.x * blockDim.x + threadIdx.x;
    if (i >= (size_t)M * DD) return;
    size_t r = i >> 9;
    int c = (int)(i & 511);
    float x = A1[r * 513 + 1 + c];
    bf16_split(x, hi[i], lo[i]);
}

__global__ void split_mat(const float* __restrict__ X,
                          __nv_bfloat16* __restrict__ hi,
                          __nv_bfloat16* __restrict__ lo, int M)
{
    size_t i = (size_t)blockIdx.x * blockDim.x + threadIdx.x;
    if (i >= (size_t)M * (DD / 4)) return;
    float4 x = ((const float4*)X)[i];
    __nv_bfloat16 h[4], l[4];
    bf16_split(x.x, h[0], l[0]);
    bf16_split(x.y, h[1], l[1]);
    bf16_split(x.z, h[2], l[2]);
    bf16_split(x.w, h[3], l[3]);
    ((uint2*)hi)[i] = *(uint2*)h;
    ((uint2*)lo)[i] = *(uint2*)l;
}

__global__ void mix_split(const float* __restrict__ out, const float* __restrict__ nvec,
                          const float* __restrict__ sv,
                          __nv_bfloat16* __restrict__ hi,
                          __nv_bfloat16* __restrict__ lo, int M)
{
    size_t i = (size_t)blockIdx.x * blockDim.x + threadIdx.x;
    if (i >= (size_t)M * (DD / 4)) return;
    size_t row = i >> 7;
    int c4 = (int)(i & 127);
    float nv = nvec[row];
    float om = 1.f - nv;
    float4 a = *(const float4*)(out + row * 1024 + 512 + (size_t)c4 * 4);
    float4 s4 = ((const float4*)sv)[i];
    float x0 = a.x * nv + s4.x * om;
    float x1 = a.y * nv + s4.y * om;
    float x2 = a.z * nv + s4.z * om;
    float x3 = a.w * nv + s4.w * om;
    __nv_bfloat16 h[4], l[4];
    bf16_split(x0, h[0], l[0]);
    bf16_split(x1, h[1], l[1]);
    bf16_split(x2, h[2], l[2]);
    bf16_split(x3, h[3], l[3]);
    ((uint2*)hi)[i] = *(uint2*)h;
    ((uint2*)lo)[i] = *(uint2*)l;
}

__global__ void prep_weight(const float* __restrict__ W,
                            __nv_bfloat16* __restrict__ hi,
                            __nv_bfloat16* __restrict__ lo)
{
    int i = blockIdx.x * blockDim.x + threadIdx.x;
    if (i >= DD * DD) return;
    int n = i >> 9, k = i & 511;
    float v = W[k * DD + n];
    bf16_split(v, hi[i], lo[i]);
}

// ---------------------------------------------------------------------------
// Host driver
// ---------------------------------------------------------------------------
extern "C" void kernel_launch(void* const* d_in, const int* in_sizes, int n_in,
                              void* d_out, int out_size)
{
    const float* A1       = (const float*)d_in[0];
    const int*   adj_rows = (const int*)  d_in[1];
    const int*   adj_cols = (const int*)  d_in[2];
    const float* adj_vals = (const float*)d_in[3];
    const float* Lin1     = (const float*)d_in[4];
    const float* Lin1_b   = (const float*)d_in[5];
    const float* nvec     = (const float*)d_in[6];
    const float* W1       = (const float*)d_in[7];
    const float* b1       = (const float*)d_in[8];
    const float* W2       = (const float*)d_in[9];
    const float* b2       = (const float*)d_in[10];
    const float* W3       = (const float*)d_in[11];
    const float* b3       = (const float*)d_in[12];
    float* out = (float*)d_out;

    const int M = in_sizes[6];   // 50000
    const int E = in_sizes[1];   // 1,600,000

    __nv_bfloat16 *Ah, *Al, *WT;
    float *U, *V, *valS;
    int *cnt, *rowptr, *cursor, *colS;
    cudaGetSymbolAddress((void**)&Ah, g_Ah);
    cudaGetSymbolAddress((void**)&Al, g_Al);
    cudaGetSymbolAddress((void**)&U,  g_U);
    cudaGetSymbolAddress((void**)&V,  g_V);
    cudaGetSymbolAddress((void**)&WT, g_WT);
    cudaGetSymbolAddress((void**)&cnt,    g_cnt);
    cudaGetSymbolAddress((void**)&rowptr, g_rowptr);
    cudaGetSymbolAddress((void**)&cursor, g_cursor);
    cudaGetSymbolAddress((void**)&colS,   g_colS);
    cudaGetSymbolAddress((void**)&valS,   g_valS);

    cudaFuncSetAttribute(gemm_bf16x3, cudaFuncAttributeMaxDynamicSharedMemorySize, GEMM_SMEM);

    const __nv_bfloat16* Wh[4];
    const __nv_bfloat16* Wl[4];
    const float* Wsrc[4] = {Lin1, W1, W2, W3};
    for (int w = 0; w < 4; w++) {
        Wh[w] = WT + (size_t)(w * 2)     * DD * DD;
        Wl[w] = WT + (size_t)(w * 2 + 1) * DD * DD;
    }

    const dim3 ggrid(DD / 128, (M + 127) / 128);
    const int eblk = (E + 255) / 256;
    const int split_blocks = (int)(((size_t)M * DD + 255) / 256);
    const int vec_blocks   = (int)(((size_t)M * (DD / 4) + 255) / 256);

    // ---- CSR build (once per launch; all graph-capturable) ----
    cudaMemsetAsync(cnt, 0, (size_t)M * sizeof(int), 0);
    hist_rows<<<eblk, 256>>>(adj_rows, cnt, E);
    scan_rows<<<1, 1024>>>(cnt, rowptr, cursor, M, E);
    scatter_edges<<<eblk, 256>>>(adj_rows, adj_cols, adj_vals, cursor, colS, valS, E);

    // ---- Weight prep + input split ----
    for (int w = 0; w < 4; w++)
        prep_weight<<<(DD * DD + 255) / 256, 256>>>(
            Wsrc[w], (__nv_bfloat16*)Wh[w], (__nv_bfloat16*)Wl[w]);
    split_strided<<<split_blocks, 256>>>(A1, Ah, Al, M);

    // a0 = x @ Lin1 + bias -> out[:, 512:1024)   (writes all rows/cols of right half)
    gemm_bf16x3<<<ggrid, 256, GEMM_SMEM>>>(Ah, Al, Wh[0], Wl[0], Lin1_b, out + 512, 1024, M);
    // U = x @ W1 + b1
    gemm_bf16x3<<<ggrid, 256, GEMM_SMEM>>>(Ah, Al, Wh[1], Wl[1], b1, U, DD, M);

    // V = spmm(U)    (CSR: every row fully written, no memset needed)
    spmm_csr<<<M, 128>>>(rowptr, colS, valS, U, V, DD);

    // x1 = a0*n + V*(1-n) -> bf16 hi/lo
    mix_split<<<vec_blocks, 256>>>(out, nvec, V, Ah, Al, M);

    // U = x1 @ W2 + b2
    gemm_bf16x3<<<ggrid, 256, GEMM_SMEM>>>(Ah, Al, Wh[2], Wl[2], b2, U, DD, M);

    // V = spmm(U)
    spmm_csr<<<M, 128>>>(rowptr, colS, valS, U, V, DD);

    // split(V) -> bf16 hi/lo
    split_mat<<<vec_blocks, 256>>>(V, Ah, Al, M);

    // U = x2 @ W3 + b3
    gemm_bf16x3<<<ggrid, 256, GEMM_SMEM>>>(Ah, Al, Wh[3], Wl[3], b3, U, DD, M);

    // out[:, 0:512) = spmm(U)   (every row written; right half untouched)
    spmm_csr<<<M, 128>>>(rowptr, colS, valS, U, out, 1024);
}

// round 5
// speedup vs baseline: 2.8267x; 1.0924x over previous
#include <cuda_runtime.h>
#include <cuda_bf16.h>
#include <cstdint>
#include <cstddef>

#define NN 50000
#define EE 1600000
#define DD 512

// ---------------------------------------------------------------------------
// Device scratch (no runtime alloc allowed)
// ---------------------------------------------------------------------------
__device__ __nv_bfloat16 g_Ah[(size_t)NN * DD];          // bf16-hi of GEMM input
__device__ __nv_bfloat16 g_Al[(size_t)NN * DD];          // bf16-lo of GEMM input
__device__ float         g_U [(size_t)NN * DD];          // fp32 activations
__device__ float         g_V [(size_t)NN * DD];          // fp32 activations
__device__ __nv_bfloat16 g_WT[(size_t)3 * 2 * DD * DD];  // 3 weights x {hi,lo}, [N][K]
__device__ float         g_W23[(size_t)DD * DD];         // W2 @ W3 (fp32)
__device__ float         g_uvec[DD];                      // b2 @ W3
// CSR scratch
__device__ int   g_cnt[NN];
__device__ int   g_rowptr[NN + 1];
__device__ int   g_cursor[NN];
__device__ int   g_colS[EE];
__device__ float g_valS[EE];
__device__ float g_d[NN];                                 // d = S·1
__device__ float g_e[NN];                                 // e = S·d

// ---------------------------------------------------------------------------
// Helpers
// ---------------------------------------------------------------------------
__device__ __forceinline__ uint32_t smem_to_u32(const void* p) {
    uint32_t a;
    asm("{ .reg .u64 t; cvta.to.shared.u64 t, %1; cvt.u32.u64 %0, t; }" : "=r"(a) : "l"(p));
    return a;
}

__device__ __forceinline__ void cp16(uint32_t dst, const void* src, bool valid) {
    int sz = valid ? 16 : 0;
    asm volatile("cp.async.cg.shared.global [%0], [%1], 16, %2;"
                 :: "r"(dst), "l"(src), "r"(sz) : "memory");
}
#define CP_COMMIT() asm volatile("cp.async.commit_group;" ::: "memory")
#define CP_WAIT(n)  asm volatile("cp.async.wait_group %0;" :: "n"(n) : "memory")

__device__ __forceinline__ void mma_bf16(float* d, const uint32_t* a, const uint32_t* b) {
    asm volatile("mma.sync.aligned.m16n8k16.row.col.f32.bf16.bf16.f32 "
                 "{%0,%1,%2,%3}, {%4,%5,%6,%7}, {%8,%9}, {%0,%1,%2,%3};"
                 : "+f"(d[0]), "+f"(d[1]), "+f"(d[2]), "+f"(d[3])
                 : "r"(a[0]), "r"(a[1]), "r"(a[2]), "r"(a[3]), "r"(b[0]), "r"(b[1]));
}

__device__ __forceinline__ void bf16_split(float x, __nv_bfloat16& h, __nv_bfloat16& l) {
    h = __float2bfloat16_rn(x);
    l = __float2bfloat16_rn(x - __bfloat162float(h));
}

// ---------------------------------------------------------------------------
// GEMM: C[M x 512] = (Ah+Al) @ (Bh+Bl)^T + epilogue      (bf16x3, mma.sync)
// Epilogue: if rowE != null:  C += rowE[r]*colU[c] + rowD[r]*colB3[c]
//           else:             C += bias[c]
// ---------------------------------------------------------------------------
#define BK 32
#define RSTRIDE 20
#define TILE_WORDS (128 * RSTRIDE)
#define STAGE_WORDS (4 * TILE_WORDS)
#define GEMM_SMEM (2 * STAGE_WORDS * 4)

__device__ __forceinline__ void gemm_load_stage(
    uint32_t sbase, int stage,
    const __nv_bfloat16* Ah, const __nv_bfloat16* Al,
    const __nv_bfloat16* Bh, const __nv_bfloat16* Bl,
    int bm, int bn, int kc, int M, int tid)
{
    const uint32_t st = sbase + (uint32_t)stage * STAGE_WORDS * 4;
    const int r0 = tid >> 2;
    const int r1 = r0 + 64;
    const int j  = tid & 3;
    const uint32_t d0 = st + (uint32_t)(r0 * RSTRIDE + j * 4) * 4;
    const uint32_t d1 = st + (uint32_t)(r1 * RSTRIDE + j * 4) * 4;
    const size_t koff = (size_t)kc * BK + j * 8;
    const bool v0 = (bm + r0) < M;
    const bool v1 = (bm + r1) < M;

    cp16(d0,                   Ah + (size_t)(bm + r0) * DD + koff, v0);
    cp16(d1,                   Ah + (size_t)(bm + r1) * DD + koff, v1);
    cp16(d0 + TILE_WORDS * 4,  Al + (size_t)(bm + r0) * DD + koff, v0);
    cp16(d1 + TILE_WORDS * 4,  Al + (size_t)(bm + r1) * DD + koff, v1);
    cp16(d0 + TILE_WORDS * 8,  Bh + (size_t)(bn + r0) * DD + koff, true);
    cp16(d1 + TILE_WORDS * 8,  Bh + (size_t)(bn + r1) * DD + koff, true);
    cp16(d0 + TILE_WORDS * 12, Bl + (size_t)(bn + r0) * DD + koff, true);
    cp16(d1 + TILE_WORDS * 12, Bl + (size_t)(bn + r1) * DD + koff, true);
}

__global__ void __launch_bounds__(256, 1) gemm_bf16x3(
    const __nv_bfloat16* __restrict__ Ah, const __nv_bfloat16* __restrict__ Al,
    const __nv_bfloat16* __restrict__ Bh, const __nv_bfloat16* __restrict__ Bl,
    const float* __restrict__ bias,
    const float* __restrict__ rowE, const float* __restrict__ colU,
    const float* __restrict__ rowD, const float* __restrict__ colB3,
    float* __restrict__ C, int ldc, int M)
{
    extern __shared__ uint32_t s[];
    const uint32_t sbase = smem_to_u32(s);
    const int tid  = threadIdx.x;
    const int warp = tid >> 5;
    const int lane = tid & 31;
    const int wm   = (warp & 1) * 64;
    const int wn   = (warp >> 1) * 32;
    const int grp  = lane >> 2;
    const int qd   = lane & 3;
    const int bm = blockIdx.y * 128;
    const int n0 = blockIdx.x * 128;

    float acc[4][4][4];
    #pragma unroll
    for (int i = 0; i < 4; i++)
        #pragma unroll
        for (int j = 0; j < 4; j++)
            #pragma unroll
            for (int q = 0; q < 4; q++) acc[i][j][q] = 0.f;

    gemm_load_stage(sbase, 0, Ah, Al, Bh, Bl, bm, n0, 0, M, tid);
    CP_COMMIT();

    #pragma unroll 1
    for (int kc = 0; kc < DD / BK; kc++) {
        if (kc + 1 < DD / BK) {
            gemm_load_stage(sbase, (kc + 1) & 1, Ah, Al, Bh, Bl, bm, n0, kc + 1, M, tid);
            CP_COMMIT();
            CP_WAIT(1);
        } else {
            CP_WAIT(0);
        }
        __syncthreads();

        const uint32_t* As_h = s + (kc & 1) * STAGE_WORDS;
        const uint32_t* As_l = As_h + TILE_WORDS;
        const uint32_t* Bs_h = As_h + 2 * TILE_WORDS;
        const uint32_t* Bs_l = As_h + 3 * TILE_WORDS;

        #pragma unroll
        for (int ks = 0; ks < 2; ks++) {
            const int kw = ks * 8;
            uint32_t ah[4][4], al[4][4], bh[4][2], bl[4][2];
            #pragma unroll
            for (int mi = 0; mi < 4; mi++) {
                const int base = (wm + mi * 16 + grp) * RSTRIDE + kw + qd;
                ah[mi][0] = As_h[base];
                ah[mi][1] = As_h[base + 8 * RSTRIDE];
                ah[mi][2] = As_h[base + 4];
                ah[mi][3] = As_h[base + 8 * RSTRIDE + 4];
                al[mi][0] = As_l[base];
                al[mi][1] = As_l[base + 8 * RSTRIDE];
                al[mi][2] = As_l[base + 4];
                al[mi][3] = As_l[base + 8 * RSTRIDE + 4];
            }
            #pragma unroll
            for (int nj = 0; nj < 4; nj++) {
                const int base = (wn + nj * 8 + grp) * RSTRIDE + kw + qd;
                bh[nj][0] = Bs_h[base];
                bh[nj][1] = Bs_h[base + 4];
                bl[nj][0] = Bs_l[base];
                bl[nj][1] = Bs_l[base + 4];
            }
            #pragma unroll
            for (int mi = 0; mi < 4; mi++)
                #pragma unroll
                for (int nj = 0; nj < 4; nj++) {
                    mma_bf16(acc[mi][nj], ah[mi], bh[nj]);
                    mma_bf16(acc[mi][nj], al[mi], bh[nj]);
                    mma_bf16(acc[mi][nj], ah[mi], bl[nj]);
                }
        }
        __syncthreads();
    }

    #pragma unroll
    for (int mi = 0; mi < 4; mi++) {
        const int gr = bm + wm + mi * 16 + grp;
        float e0 = 0.f, d0v = 0.f, e1 = 0.f, d1v = 0.f;
        if (rowE) {
            if (gr < M)     { e0 = rowE[gr];     d0v = rowD[gr]; }
            if (gr + 8 < M) { e1 = rowE[gr + 8]; d1v = rowD[gr + 8]; }
        }
        #pragma unroll
        for (int nj = 0; nj < 4; nj++) {
            const int gc = n0 + wn + nj * 8 + qd * 2;
            float2 add0, add1;
            if (rowE) {
                const float2 uu = *(const float2*)(colU + gc);
                const float2 b3 = *(const float2*)(colB3 + gc);
                add0 = make_float2(e0 * uu.x + d0v * b3.x, e0 * uu.y + d0v * b3.y);
                add1 = make_float2(e1 * uu.x + d1v * b3.x, e1 * uu.y + d1v * b3.y);
            } else {
                const float2 bz = *(const float2*)(bias + gc);
                add0 = bz; add1 = bz;
            }
            if (gr < M) {
                float2 o = {acc[mi][nj][0] + add0.x, acc[mi][nj][1] + add0.y};
                *(float2*)(C + (size_t)gr * ldc + gc) = o;
            }
            if (gr + 8 < M) {
                float2 o = {acc[mi][nj][2] + add1.x, acc[mi][nj][3] + add1.y};
                *(float2*)(C + (size_t)(gr + 8) * ldc + gc) = o;
            }
        }
    }
}

// ---------------------------------------------------------------------------
// Small fp32 kernels: W23 = W2@W3, u = b2@W3
// ---------------------------------------------------------------------------
__global__ void gemm512_f32(const float* __restrict__ A, const float* __restrict__ B,
                            float* __restrict__ C)
{
    const int n = blockIdx.x * 128 + threadIdx.x;   // col
    const int k = blockIdx.y;                       // row
    float acc = 0.f;
    #pragma unroll 8
    for (int j = 0; j < DD; j++)
        acc = fmaf(A[k * DD + j], B[j * DD + n], acc);
    C[k * DD + n] = acc;
}

__global__ void uvec_f32(const float* __restrict__ b2, const float* __restrict__ W3,
                         float* __restrict__ u)
{
    const int n = blockIdx.x * 128 + threadIdx.x;
    float acc = 0.f;
    #pragma unroll 8
    for (int j = 0; j < DD; j++)
        acc = fmaf(b2[j], W3[j * DD + n], acc);
    u[n] = acc;
}

// ---------------------------------------------------------------------------
// CSR build + d/e vectors
// ---------------------------------------------------------------------------
__global__ void hist_rows(const int* __restrict__ rows, int* __restrict__ cnt, int E)
{
    int e = blockIdx.x * blockDim.x + threadIdx.x;
    if (e < E) atomicAdd(&cnt[rows[e]], 1);
}

__global__ void __launch_bounds__(1024) scan_rows(
    const int* __restrict__ cnt, int* __restrict__ row_ptr,
    int* __restrict__ cursor, int M, int E)
{
    __shared__ int sm[1024];
    const int tid = threadIdx.x;
    const int chunk = (M + 1023) >> 10;
    const int base = tid * chunk;

    int local = 0;
    for (int i = 0; i < chunk; i++) {
        int r = base + i;
        if (r < M) local += cnt[r];
    }
    sm[tid] = local;
    __syncthreads();
    for (int off = 1; off < 1024; off <<= 1) {
        int v = (tid >= off) ? sm[tid - off] : 0;
        __syncthreads();
        sm[tid] += v;
        __syncthreads();
    }
    int run = sm[tid] - local;
    for (int i = 0; i < chunk; i++) {
        int r = base + i;
        if (r < M) {
            row_ptr[r] = run;
            cursor[r]  = run;
            run += cnt[r];
        }
    }
    if (tid == 0) row_ptr[M] = E;
}

__global__ void scatter_edges(const int* __restrict__ rows, const int* __restrict__ cols,
                              const float* __restrict__ vals,
                              int* __restrict__ cursor,
                              int* __restrict__ colS, float* __restrict__ valS, int E)
{
    int e = blockIdx.x * blockDim.x + threadIdx.x;
    if (e >= E) return;
    int r = rows[e];
    int p = atomicAdd(&cursor[r], 1);
    colS[p] = cols[e];
    valS[p] = vals[e];
}

// d[r] = sum of vals in row r (one warp per row)
__global__ void rowsum_d(const int* __restrict__ row_ptr, const float* __restrict__ valS,
                         float* __restrict__ d, int M)
{
    int r = (blockIdx.x * blockDim.x + threadIdx.x) >> 5;
    if (r >= M) return;
    int lane = threadIdx.x & 31;
    float acc = 0.f;
    for (int e = row_ptr[r] + lane; e < row_ptr[r + 1]; e += 32) acc += valS[e];
    #pragma unroll
    for (int o = 16; o; o >>= 1) acc += __shfl_down_sync(0xffffffffu, acc, o);
    if (lane == 0) d[r] = acc;
}

// e[r] = sum val * d[col]  (one warp per row)
__global__ void spmv_e(const int* __restrict__ row_ptr, const int* __restrict__ colS,
                       const float* __restrict__ valS, const float* __restrict__ d,
                       float* __restrict__ evec, int M)
{
    int r = (blockIdx.x * blockDim.x + threadIdx.x) >> 5;
    if (r >= M) return;
    int lane = threadIdx.x & 31;
    float acc = 0.f;
    for (int e = row_ptr[r] + lane; e < row_ptr[r + 1]; e += 32)
        acc = fmaf(valS[e], d[colS[e]], acc);
    #pragma unroll
    for (int o = 16; o; o >>= 1) acc += __shfl_down_sync(0xffffffffu, acc, o);
    if (lane == 0) evec[r] = acc;
}

// ---------------------------------------------------------------------------
// CSR SpMM: one block (128 threads) per output row; no atomics.
// ---------------------------------------------------------------------------
__global__ void __launch_bounds__(128) spmm_csr(
    const int* __restrict__ row_ptr,
    const int* __restrict__ colS, const float* __restrict__ valS,
    const float* __restrict__ in, float* __restrict__ out, int ldo)
{
    const int r   = blockIdx.x;
    const int tid = threadIdx.x;
    const size_t off = (size_t)tid * 4;

    int e = row_ptr[r];
    const int end = row_ptr[r + 1];
    float4 acc = {0.f, 0.f, 0.f, 0.f};

    for (; e + 2 <= end; e += 2) {
        const int   c0 = __ldg(colS + e);
        const int   c1 = __ldg(colS + e + 1);
        const float v0 = __ldg(valS + e);
        const float v1 = __ldg(valS + e + 1);
        const float4 x0 = *(const float4*)(in + (size_t)c0 * DD + off);
        const float4 x1 = *(const float4*)(in + (size_t)c1 * DD + off);
        acc.x = fmaf(v0, x0.x, acc.x); acc.y = fmaf(v0, x0.y, acc.y);
        acc.z = fmaf(v0, x0.z, acc.z); acc.w = fmaf(v0, x0.w, acc.w);
        acc.x = fmaf(v1, x1.x, acc.x); acc.y = fmaf(v1, x1.y, acc.y);
        acc.z = fmaf(v1, x1.z, acc.z); acc.w = fmaf(v1, x1.w, acc.w);
    }
    if (e < end) {
        const int   c0 = __ldg(colS + e);
        const float v0 = __ldg(valS + e);
        const float4 x0 = *(const float4*)(in + (size_t)c0 * DD + off);
        acc.x = fmaf(v0, x0.x, acc.x); acc.y = fmaf(v0, x0.y, acc.y);
        acc.z = fmaf(v0, x0.z, acc.z); acc.w = fmaf(v0, x0.w, acc.w);
    }
    *(float4*)(out + (size_t)r * ldo + off) = acc;
}

// ---------------------------------------------------------------------------
// Split / prep / mix kernels
// ---------------------------------------------------------------------------
__global__ void split_strided(const float* __restrict__ A1,
                              __nv_bfloat16* __restrict__ hi,
                              __nv_bfloat16* __restrict__ lo, int M)
{
    size_t i = (size_t)blockIdx.x * blockDim.x + threadIdx.x;
    if (i >= (size_t)M * DD) return;
    size_t r = i >> 9;
    int c = (int)(i & 511);
    float x = A1[r * 513 + 1 + c];
    bf16_split(x, hi[i], lo[i]);
}

__global__ void split_mat(const float* __restrict__ X,
                          __nv_bfloat16* __restrict__ hi,
                          __nv_bfloat16* __restrict__ lo, int M)
{
    size_t i = (size_t)blockIdx.x * blockDim.x + threadIdx.x;
    if (i >= (size_t)M * (DD / 4)) return;
    float4 x = ((const float4*)X)[i];
    __nv_bfloat16 h[4], l[4];
    bf16_split(x.x, h[0], l[0]);
    bf16_split(x.y, h[1], l[1]);
    bf16_split(x.z, h[2], l[2]);
    bf16_split(x.w, h[3], l[3]);
    ((uint2*)hi)[i] = *(uint2*)h;
    ((uint2*)lo)[i] = *(uint2*)l;
}

// x1 = a0 * n + s * (1-n), fp32 output (feeds SpMM directly now)
__global__ void mix_f32(const float* __restrict__ out, const float* __restrict__ nvec,
                        const float* __restrict__ sv, float* __restrict__ x1, int M)
{
    size_t i = (size_t)blockIdx.x * blockDim.x + threadIdx.x;
    if (i >= (size_t)M * (DD / 4)) return;
    size_t row = i >> 7;
    int c4 = (int)(i & 127);
    float nv = nvec[row];
    float om = 1.f - nv;
    float4 a = *(const float4*)(out + row * 1024 + 512 + (size_t)c4 * 4);
    float4 s4 = ((const float4*)sv)[i];
    float4 r;
    r.x = a.x * nv + s4.x * om;
    r.y = a.y * nv + s4.y * om;
    r.z = a.z * nv + s4.z * om;
    r.w = a.w * nv + s4.w * om;
    ((float4*)x1)[i] = r;
}

__global__ void prep_weight(const float* __restrict__ W,
                            __nv_bfloat16* __restrict__ hi,
                            __nv_bfloat16* __restrict__ lo)
{
    int i = blockIdx.x * blockDim.x + threadIdx.x;
    if (i >= DD * DD) return;
    int n = i >> 9, k = i & 511;
    float v = W[k * DD + n];
    bf16_split(v, hi[i], lo[i]);
}

// ---------------------------------------------------------------------------
// Host driver
// ---------------------------------------------------------------------------
extern "C" void kernel_launch(void* const* d_in, const int* in_sizes, int n_in,
                              void* d_out, int out_size)
{
    const float* A1       = (const float*)d_in[0];
    const int*   adj_rows = (const int*)  d_in[1];
    const int*   adj_cols = (const int*)  d_in[2];
    const float* adj_vals = (const float*)d_in[3];
    const float* Lin1     = (const float*)d_in[4];
    const float* Lin1_b   = (const float*)d_in[5];
    const float* nvec     = (const float*)d_in[6];
    const float* W1       = (const float*)d_in[7];
    const float* b1       = (const float*)d_in[8];
    const float* W2       = (const float*)d_in[9];
    const float* b2       = (const float*)d_in[10];
    const float* W3       = (const float*)d_in[11];
    const float* b3       = (const float*)d_in[12];
    float* out = (float*)d_out;

    const int M = in_sizes[6];   // 50000
    const int E = in_sizes[1];   // 1,600,000

    __nv_bfloat16 *Ah, *Al, *WT;
    float *U, *V, *valS, *W23, *uvec, *dv, *ev;
    int *cnt, *rowptr, *cursor, *colS;
    cudaGetSymbolAddress((void**)&Ah, g_Ah);
    cudaGetSymbolAddress((void**)&Al, g_Al);
    cudaGetSymbolAddress((void**)&U,  g_U);
    cudaGetSymbolAddress((void**)&V,  g_V);
    cudaGetSymbolAddress((void**)&WT, g_WT);
    cudaGetSymbolAddress((void**)&W23,  g_W23);
    cudaGetSymbolAddress((void**)&uvec, g_uvec);
    cudaGetSymbolAddress((void**)&dv,   g_d);
    cudaGetSymbolAddress((void**)&ev,   g_e);
    cudaGetSymbolAddress((void**)&cnt,    g_cnt);
    cudaGetSymbolAddress((void**)&rowptr, g_rowptr);
    cudaGetSymbolAddress((void**)&cursor, g_cursor);
    cudaGetSymbolAddress((void**)&colS,   g_colS);
    cudaGetSymbolAddress((void**)&valS,   g_valS);

    cudaFuncSetAttribute(gemm_bf16x3, cudaFuncAttributeMaxDynamicSharedMemorySize, GEMM_SMEM);

    __nv_bfloat16* Wh[3];
    __nv_bfloat16* Wl[3];
    for (int w = 0; w < 3; w++) {
        Wh[w] = WT + (size_t)(w * 2)     * DD * DD;
        Wl[w] = WT + (size_t)(w * 2 + 1) * DD * DD;
    }

    const dim3 ggrid(DD / 128, (M + 127) / 128);
    const int eblk = (E + 255) / 256;
    const int split_blocks = (int)(((size_t)M * DD + 255) / 256);
    const int vec_blocks   = (int)(((size_t)M * (DD / 4) + 255) / 256);
    const int warp_blocks  = (M * 32 + 255) / 256;

    // ---- Launches 0-4: weight prep + split (keeps gemm at profiled index 5) ----
    prep_weight<<<(DD * DD + 255) / 256, 256>>>(Lin1, Wh[0], Wl[0]);   // 0
    prep_weight<<<(DD * DD + 255) / 256, 256>>>(W1,   Wh[1], Wl[1]);   // 1
    gemm512_f32<<<dim3(4, DD), 128>>>(W2, W3, W23);                    // 2
    prep_weight<<<(DD * DD + 255) / 256, 256>>>(W23, Wh[2], Wl[2]);    // 3
    split_strided<<<split_blocks, 256>>>(A1, Ah, Al, M);               // 4

    // ---- Launch 5 (profiled): a0 = x @ Lin1 + bias -> out[:, 512:1024) ----
    gemm_bf16x3<<<ggrid, 256, GEMM_SMEM>>>(Ah, Al, Wh[0], Wl[0], Lin1_b,
                                           nullptr, nullptr, nullptr, nullptr,
                                           out + 512, 1024, M);
    // U = x @ W1 + b1
    gemm_bf16x3<<<ggrid, 256, GEMM_SMEM>>>(Ah, Al, Wh[1], Wl[1], b1,
                                           nullptr, nullptr, nullptr, nullptr,
                                           U, DD, M);

    // ---- CSR build + bias-correction vectors ----
    cudaMemsetAsync(cnt, 0, (size_t)M * sizeof(int), 0);
    hist_rows<<<eblk, 256>>>(adj_rows, cnt, E);
    scan_rows<<<1, 1024>>>(cnt, rowptr, cursor, M, E);
    scatter_edges<<<eblk, 256>>>(adj_rows, adj_cols, adj_vals, cursor, colS, valS, E);
    rowsum_d<<<warp_blocks, 256>>>(rowptr, valS, dv, M);
    spmv_e<<<warp_blocks, 256>>>(rowptr, colS, valS, dv, ev, M);
    uvec_f32<<<4, 128>>>(b2, W3, uvec);

    // V = spmm(U)
    spmm_csr<<<M, 128>>>(rowptr, colS, valS, U, V, DD);

    // x1 = a0*n + V*(1-n)  (fp32, into U)
    mix_f32<<<vec_blocks, 256>>>(out, nvec, V, U, M);

    // t = S x1 -> V ; t2 = S t -> U
    spmm_csr<<<M, 128>>>(rowptr, colS, valS, U, V, DD);
    spmm_csr<<<M, 128>>>(rowptr, colS, valS, V, U, DD);

    // split(t2) -> bf16 hi/lo
    split_mat<<<vec_blocks, 256>>>(U, Ah, Al, M);

    // out[:, 0:512) = t2 @ W23 + e⊗u + d⊗b3
    gemm_bf16x3<<<ggrid, 256, GEMM_SMEM>>>(Ah, Al, Wh[2], Wl[2], nullptr,
                                           ev, uvec, dv, b3,
                                           out, 1024, M);
}

// round 6
// speedup vs baseline: 3.0515x; 1.0795x over previous
#include <cuda_runtime.h>
#include <cuda_bf16.h>
#include <cstdint>
#include <cstddef>

#define NN 50000
#define EE 1600000
#define DD 512

// ---------------------------------------------------------------------------
// Device scratch (no runtime alloc allowed)
// ---------------------------------------------------------------------------
__device__ __nv_bfloat16 g_Ah[(size_t)NN * DD];
__device__ __nv_bfloat16 g_Al[(size_t)NN * DD];
__device__ float         g_U [(size_t)NN * DD];
__device__ float         g_V [(size_t)NN * DD];
__device__ __nv_bfloat16 g_WT[(size_t)3 * 2 * DD * DD];
__device__ float         g_W23[(size_t)DD * DD];
__device__ float         g_uvec[DD];
// CSR scratch
__device__ int   g_cnt[NN];
__device__ int   g_rowptr[NN + 1];
__device__ int   g_cursor[NN];
__device__ int   g_colS[EE];
__device__ float g_valS[EE];
__device__ float g_d[NN];
__device__ float g_e[NN];

// ---------------------------------------------------------------------------
// Helpers
// ---------------------------------------------------------------------------
__device__ __forceinline__ uint32_t smem_to_u32(const void* p) {
    uint32_t a;
    asm("{ .reg .u64 t; cvta.to.shared.u64 t, %1; cvt.u32.u64 %0, t; }" : "=r"(a) : "l"(p));
    return a;
}

__device__ __forceinline__ void cp16(uint32_t dst, const void* src, bool valid) {
    int sz = valid ? 16 : 0;
    asm volatile("cp.async.cg.shared.global [%0], [%1], 16, %2;"
                 :: "r"(dst), "l"(src), "r"(sz) : "memory");
}
#define CP_COMMIT() asm volatile("cp.async.commit_group;" ::: "memory")
#define CP_WAIT(n)  asm volatile("cp.async.wait_group %0;" :: "n"(n) : "memory")

__device__ __forceinline__ void mma_bf16(float* d, const uint32_t* a, const uint32_t* b) {
    asm volatile("mma.sync.aligned.m16n8k16.row.col.f32.bf16.bf16.f32 "
                 "{%0,%1,%2,%3}, {%4,%5,%6,%7}, {%8,%9}, {%0,%1,%2,%3};"
                 : "+f"(d[0]), "+f"(d[1]), "+f"(d[2]), "+f"(d[3])
                 : "r"(a[0]), "r"(a[1]), "r"(a[2]), "r"(a[3]), "r"(b[0]), "r"(b[1]));
}

__device__ __forceinline__ void bf16_split(float x, __nv_bfloat16& h, __nv_bfloat16& l) {
    h = __float2bfloat16_rn(x);
    l = __float2bfloat16_rn(x - __bfloat162float(h));
}

// ---------------------------------------------------------------------------
// GEMM: C = (Ah+Al) @ (Bh+Bl)^T + epilogue   (bf16x3, mma.sync, occupancy 2)
// ---------------------------------------------------------------------------
#define BK 32
#define RSTRIDE 20
#define TILE_WORDS (128 * RSTRIDE)
#define STAGE_WORDS (4 * TILE_WORDS)
#define GEMM_SMEM (2 * STAGE_WORDS * 4)

__device__ __forceinline__ void gemm_load_stage(
    uint32_t sbase, int stage,
    const __nv_bfloat16* Ah, const __nv_bfloat16* Al,
    const __nv_bfloat16* Bh, const __nv_bfloat16* Bl,
    int bm, int bn, int kc, int M, int tid)
{
    const uint32_t st = sbase + (uint32_t)stage * STAGE_WORDS * 4;
    const int r0 = tid >> 2;
    const int r1 = r0 + 64;
    const int j  = tid & 3;
    const uint32_t d0 = st + (uint32_t)(r0 * RSTRIDE + j * 4) * 4;
    const uint32_t d1 = st + (uint32_t)(r1 * RSTRIDE + j * 4) * 4;
    const size_t koff = (size_t)kc * BK + j * 8;
    const bool v0 = (bm + r0) < M;
    const bool v1 = (bm + r1) < M;

    cp16(d0,                   Ah + (size_t)(bm + r0) * DD + koff, v0);
    cp16(d1,                   Ah + (size_t)(bm + r1) * DD + koff, v1);
    cp16(d0 + TILE_WORDS * 4,  Al + (size_t)(bm + r0) * DD + koff, v0);
    cp16(d1 + TILE_WORDS * 4,  Al + (size_t)(bm + r1) * DD + koff, v1);
    cp16(d0 + TILE_WORDS * 8,  Bh + (size_t)(bn + r0) * DD + koff, true);
    cp16(d1 + TILE_WORDS * 8,  Bh + (size_t)(bn + r1) * DD + koff, true);
    cp16(d0 + TILE_WORDS * 12, Bl + (size_t)(bn + r0) * DD + koff, true);
    cp16(d1 + TILE_WORDS * 12, Bl + (size_t)(bn + r1) * DD + koff, true);
}

__global__ void __launch_bounds__(256, 2) gemm_bf16x3(
    const __nv_bfloat16* __restrict__ Ah, const __nv_bfloat16* __restrict__ Al,
    const __nv_bfloat16* __restrict__ Bh, const __nv_bfloat16* __restrict__ Bl,
    const float* __restrict__ bias,
    const float* __restrict__ rowE, const float* __restrict__ colU,
    const float* __restrict__ rowD, const float* __restrict__ colB3,
    float* __restrict__ C, int ldc, int M)
{
    extern __shared__ uint32_t s[];
    const uint32_t sbase = smem_to_u32(s);
    const int tid  = threadIdx.x;
    const int warp = tid >> 5;
    const int lane = tid & 31;
    const int wm   = (warp & 1) * 64;
    const int wn   = (warp >> 1) * 32;
    const int grp  = lane >> 2;
    const int qd   = lane & 3;
    const int bm = blockIdx.y * 128;
    const int n0 = blockIdx.x * 128;

    float acc[4][4][4];
    #pragma unroll
    for (int i = 0; i < 4; i++)
        #pragma unroll
        for (int j = 0; j < 4; j++)
            #pragma unroll
            for (int q = 0; q < 4; q++) acc[i][j][q] = 0.f;

    gemm_load_stage(sbase, 0, Ah, Al, Bh, Bl, bm, n0, 0, M, tid);
    CP_COMMIT();

    #pragma unroll 1
    for (int kc = 0; kc < DD / BK; kc++) {
        if (kc + 1 < DD / BK) {
            gemm_load_stage(sbase, (kc + 1) & 1, Ah, Al, Bh, Bl, bm, n0, kc + 1, M, tid);
            CP_COMMIT();
            CP_WAIT(1);
        } else {
            CP_WAIT(0);
        }
        __syncthreads();

        const uint32_t* As_h = s + (kc & 1) * STAGE_WORDS;
        const uint32_t* As_l = As_h + TILE_WORDS;
        const uint32_t* Bs_h = As_h + 2 * TILE_WORDS;
        const uint32_t* Bs_l = As_h + 3 * TILE_WORDS;

        #pragma unroll
        for (int ks = 0; ks < 2; ks++) {
            const int kw = ks * 8;
            // Hoist all A fragments (32 regs), then stream B fragments per-nj
            // (4 regs live) — keeps peak liveness under the 128-reg occupancy-2 cap.
            uint32_t ah[4][4], al[4][4];
            #pragma unroll
            for (int mi = 0; mi < 4; mi++) {
                const int base = (wm + mi * 16 + grp) * RSTRIDE + kw + qd;
                ah[mi][0] = As_h[base];
                ah[mi][1] = As_h[base + 8 * RSTRIDE];
                ah[mi][2] = As_h[base + 4];
                ah[mi][3] = As_h[base + 8 * RSTRIDE + 4];
                al[mi][0] = As_l[base];
                al[mi][1] = As_l[base + 8 * RSTRIDE];
                al[mi][2] = As_l[base + 4];
                al[mi][3] = As_l[base + 8 * RSTRIDE + 4];
            }
            #pragma unroll
            for (int nj = 0; nj < 4; nj++) {
                const int base = (wn + nj * 8 + grp) * RSTRIDE + kw + qd;
                uint32_t bh[2], bl[2];
                bh[0] = Bs_h[base];
                bh[1] = Bs_h[base + 4];
                bl[0] = Bs_l[base];
                bl[1] = Bs_l[base + 4];
                #pragma unroll
                for (int mi = 0; mi < 4; mi++) {
                    mma_bf16(acc[mi][nj], ah[mi], bh);
                    mma_bf16(acc[mi][nj], al[mi], bh);
                    mma_bf16(acc[mi][nj], ah[mi], bl);
                }
            }
        }
        __syncthreads();
    }

    #pragma unroll
    for (int mi = 0; mi < 4; mi++) {
        const int gr = bm + wm + mi * 16 + grp;
        float e0 = 0.f, d0v = 0.f, e1 = 0.f, d1v = 0.f;
        if (rowE) {
            if (gr < M)     { e0 = rowE[gr];     d0v = rowD[gr]; }
            if (gr + 8 < M) { e1 = rowE[gr + 8]; d1v = rowD[gr + 8]; }
        }
        #pragma unroll
        for (int nj = 0; nj < 4; nj++) {
            const int gc = n0 + wn + nj * 8 + qd * 2;
            float2 add0, add1;
            if (rowE) {
                const float2 uu = *(const float2*)(colU + gc);
                const float2 b3 = *(const float2*)(colB3 + gc);
                add0 = make_float2(e0 * uu.x + d0v * b3.x, e0 * uu.y + d0v * b3.y);
                add1 = make_float2(e1 * uu.x + d1v * b3.x, e1 * uu.y + d1v * b3.y);
            } else {
                const float2 bz = *(const float2*)(bias + gc);
                add0 = bz; add1 = bz;
            }
            if (gr < M) {
                float2 o = {acc[mi][nj][0] + add0.x, acc[mi][nj][1] + add0.y};
                *(float2*)(C + (size_t)gr * ldc + gc) = o;
            }
            if (gr + 8 < M) {
                float2 o = {acc[mi][nj][2] + add1.x, acc[mi][nj][3] + add1.y};
                *(float2*)(C + (size_t)(gr + 8) * ldc + gc) = o;
            }
        }
    }
}

// ---------------------------------------------------------------------------
// Small fp32 kernels: W23 = W2@W3, u = b2@W3
// ---------------------------------------------------------------------------
__global__ void gemm512_f32(const float* __restrict__ A, const float* __restrict__ B,
                            float* __restrict__ C)
{
    const int n = blockIdx.x * 128 + threadIdx.x;
    const int k = blockIdx.y;
    float acc = 0.f;
    #pragma unroll 8
    for (int j = 0; j < DD; j++)
        acc = fmaf(A[k * DD + j], B[j * DD + n], acc);
    C[k * DD + n] = acc;
}

__global__ void uvec_f32(const float* __restrict__ b2, const float* __restrict__ W3,
                         float* __restrict__ u)
{
    const int n = blockIdx.x * 128 + threadIdx.x;
    float acc = 0.f;
    #pragma unroll 8
    for (int j = 0; j < DD; j++)
        acc = fmaf(b2[j], W3[j * DD + n], acc);
    u[n] = acc;
}

// ---------------------------------------------------------------------------
// CSR build + d/e vectors
// ---------------------------------------------------------------------------
__global__ void hist_rows(const int* __restrict__ rows, int* __restrict__ cnt, int E)
{
    int e = blockIdx.x * blockDim.x + threadIdx.x;
    if (e < E) atomicAdd(&cnt[rows[e]], 1);
}

__global__ void __launch_bounds__(1024) scan_rows(
    const int* __restrict__ cnt, int* __restrict__ row_ptr,
    int* __restrict__ cursor, int M, int E)
{
    __shared__ int sm[1024];
    const int tid = threadIdx.x;
    const int chunk = (M + 1023) >> 10;
    const int base = tid * chunk;

    int local = 0;
    for (int i = 0; i < chunk; i++) {
        int r = base + i;
        if (r < M) local += cnt[r];
    }
    sm[tid] = local;
    __syncthreads();
    for (int off = 1; off < 1024; off <<= 1) {
        int v = (tid >= off) ? sm[tid - off] : 0;
        __syncthreads();
        sm[tid] += v;
        __syncthreads();
    }
    int run = sm[tid] - local;
    for (int i = 0; i < chunk; i++) {
        int r = base + i;
        if (r < M) {
            row_ptr[r] = run;
            cursor[r]  = run;
            run += cnt[r];
        }
    }
    if (tid == 0) row_ptr[M] = E;
}

__global__ void scatter_edges(const int* __restrict__ rows, const int* __restrict__ cols,
                              const float* __restrict__ vals,
                              int* __restrict__ cursor,
                              int* __restrict__ colS, float* __restrict__ valS, int E)
{
    int e = blockIdx.x * blockDim.x + threadIdx.x;
    if (e >= E) return;
    int r = rows[e];
    int p = atomicAdd(&cursor[r], 1);
    colS[p] = cols[e];
    valS[p] = vals[e];
}

__global__ void rowsum_d(const int* __restrict__ row_ptr, const float* __restrict__ valS,
                         float* __restrict__ d, int M)
{
    int r = (blockIdx.x * blockDim.x + threadIdx.x) >> 5;
    if (r >= M) return;
    int lane = threadIdx.x & 31;
    float acc = 0.f;
    for (int e = row_ptr[r] + lane; e < row_ptr[r + 1]; e += 32) acc += valS[e];
    #pragma unroll
    for (int o = 16; o; o >>= 1) acc += __shfl_down_sync(0xffffffffu, acc, o);
    if (lane == 0) d[r] = acc;
}

__global__ void spmv_e(const int* __restrict__ row_ptr, const int* __restrict__ colS,
                       const float* __restrict__ valS, const float* __restrict__ d,
                       float* __restrict__ evec, int M)
{
    int r = (blockIdx.x * blockDim.x + threadIdx.x) >> 5;
    if (r >= M) return;
    int lane = threadIdx.x & 31;
    float acc = 0.f;
    for (int e = row_ptr[r] + lane; e < row_ptr[r + 1]; e += 32)
        acc = fmaf(valS[e], d[colS[e]], acc);
    #pragma unroll
    for (int o = 16; o; o >>= 1) acc += __shfl_down_sync(0xffffffffu, acc, o);
    if (lane == 0) evec[r] = acc;
}

// ---------------------------------------------------------------------------
// CSR SpMM core (block per row, 128 threads, float4 accumulator)
// ---------------------------------------------------------------------------
__device__ __forceinline__ float4 spmm_row_acc(
    const int* __restrict__ row_ptr,
    const int* __restrict__ colS, const float* __restrict__ valS,
    const float* __restrict__ in, int r, size_t off)
{
    int e = row_ptr[r];
    const int end = row_ptr[r + 1];
    float4 acc = {0.f, 0.f, 0.f, 0.f};

    for (; e + 2 <= end; e += 2) {
        const int   c0 = __ldg(colS + e);
        const int   c1 = __ldg(colS + e + 1);
        const float v0 = __ldg(valS + e);
        const float v1 = __ldg(valS + e + 1);
        const float4 x0 = *(const float4*)(in + (size_t)c0 * DD + off);
        const float4 x1 = *(const float4*)(in + (size_t)c1 * DD + off);
        acc.x = fmaf(v0, x0.x, acc.x); acc.y = fmaf(v0, x0.y, acc.y);
        acc.z = fmaf(v0, x0.z, acc.z); acc.w = fmaf(v0, x0.w, acc.w);
        acc.x = fmaf(v1, x1.x, acc.x); acc.y = fmaf(v1, x1.y, acc.y);
        acc.z = fmaf(v1, x1.z, acc.z); acc.w = fmaf(v1, x1.w, acc.w);
    }
    if (e < end) {
        const int   c0 = __ldg(colS + e);
        const float v0 = __ldg(valS + e);
        const float4 x0 = *(const float4*)(in + (size_t)c0 * DD + off);
        acc.x = fmaf(v0, x0.x, acc.x); acc.y = fmaf(v0, x0.y, acc.y);
        acc.z = fmaf(v0, x0.z, acc.z); acc.w = fmaf(v0, x0.w, acc.w);
    }
    return acc;
}

// Plain SpMM: out[r,:] = S·in  (fp32, variable ldo)
__global__ void __launch_bounds__(128) spmm_csr(
    const int* __restrict__ row_ptr,
    const int* __restrict__ colS, const float* __restrict__ valS,
    const float* __restrict__ in, float* __restrict__ out, int ldo)
{
    const int r = blockIdx.x;
    const size_t off = (size_t)threadIdx.x * 4;
    float4 acc = spmm_row_acc(row_ptr, colS, valS, in, r, off);
    *(float4*)(out + (size_t)r * ldo + off) = acc;
}

// SpMM fused with mix: x1[r,:] = a0[r,:]*n[r] + (S·in)[r,:]*(1-n[r])
__global__ void __launch_bounds__(128) spmm_mix(
    const int* __restrict__ row_ptr,
    const int* __restrict__ colS, const float* __restrict__ valS,
    const float* __restrict__ in,
    const float* __restrict__ a0, const float* __restrict__ nvec,
    float* __restrict__ x1)
{
    const int r = blockIdx.x;
    const size_t off = (size_t)threadIdx.x * 4;
    float4 acc = spmm_row_acc(row_ptr, colS, valS, in, r, off);
    const float nv = nvec[r];
    const float om = 1.f - nv;
    const float4 a = *(const float4*)(a0 + (size_t)r * 1024 + off);
    float4 o;
    o.x = a.x * nv + acc.x * om;
    o.y = a.y * nv + acc.y * om;
    o.z = a.z * nv + acc.z * om;
    o.w = a.w * nv + acc.w * om;
    *(float4*)(x1 + (size_t)r * DD + off) = o;
}

// SpMM fused with bf16 hi/lo split (feeds the final GEMM directly)
__global__ void __launch_bounds__(128) spmm_split(
    const int* __restrict__ row_ptr,
    const int* __restrict__ colS, const float* __restrict__ valS,
    const float* __restrict__ in,
    __nv_bfloat16* __restrict__ hi, __nv_bfloat16* __restrict__ lo)
{
    const int r = blockIdx.x;
    const size_t off = (size_t)threadIdx.x * 4;
    float4 acc = spmm_row_acc(row_ptr, colS, valS, in, r, off);
    __nv_bfloat16 h[4], l[4];
    bf16_split(acc.x, h[0], l[0]);
    bf16_split(acc.y, h[1], l[1]);
    bf16_split(acc.z, h[2], l[2]);
    bf16_split(acc.w, h[3], l[3]);
    *(uint2*)(hi + (size_t)r * DD + off) = *(uint2*)h;
    *(uint2*)(lo + (size_t)r * DD + off) = *(uint2*)l;
}

// ---------------------------------------------------------------------------
// Split / prep kernels
// ---------------------------------------------------------------------------
__global__ void split_strided(const float* __restrict__ A1,
                              __nv_bfloat16* __restrict__ hi,
                              __nv_bfloat16* __restrict__ lo, int M)
{
    size_t i = (size_t)blockIdx.x * blockDim.x + threadIdx.x;
    if (i >= (size_t)M * DD) return;
    size_t r = i >> 9;
    int c = (int)(i & 511);
    float x = A1[r * 513 + 1 + c];
    bf16_split(x, hi[i], lo[i]);
}

__global__ void prep_weight(const float* __restrict__ W,
                            __nv_bfloat16* __restrict__ hi,
                            __nv_bfloat16* __restrict__ lo)
{
    int i = blockIdx.x * blockDim.x + threadIdx.x;
    if (i >= DD * DD) return;
    int n = i >> 9, k = i & 511;
    float v = W[k * DD + n];
    bf16_split(v, hi[i], lo[i]);
}

// ---------------------------------------------------------------------------
// Host driver
// ---------------------------------------------------------------------------
extern "C" void kernel_launch(void* const* d_in, const int* in_sizes, int n_in,
                              void* d_out, int out_size)
{
    const float* A1       = (const float*)d_in[0];
    const int*   adj_rows = (const int*)  d_in[1];
    const int*   adj_cols = (const int*)  d_in[2];
    const float* adj_vals = (const float*)d_in[3];
    const float* Lin1     = (const float*)d_in[4];
    const float* Lin1_b   = (const float*)d_in[5];
    const float* nvec     = (const float*)d_in[6];
    const float* W1       = (const float*)d_in[7];
    const float* b1       = (const float*)d_in[8];
    const float* W2       = (const float*)d_in[9];
    const float* b2       = (const float*)d_in[10];
    const float* W3       = (const float*)d_in[11];
    const float* b3       = (const float*)d_in[12];
    float* out = (float*)d_out;

    const int M = in_sizes[6];   // 50000
    const int E = in_sizes[1];   // 1,600,000

    __nv_bfloat16 *Ah, *Al, *WT;
    float *U, *V, *valS, *W23, *uvec, *dv, *ev;
    int *cnt, *rowptr, *cursor, *colS;
    cudaGetSymbolAddress((void**)&Ah, g_Ah);
    cudaGetSymbolAddress((void**)&Al, g_Al);
    cudaGetSymbolAddress((void**)&U,  g_U);
    cudaGetSymbolAddress((void**)&V,  g_V);
    cudaGetSymbolAddress((void**)&WT, g_WT);
    cudaGetSymbolAddress((void**)&W23,  g_W23);
    cudaGetSymbolAddress((void**)&uvec, g_uvec);
    cudaGetSymbolAddress((void**)&dv,   g_d);
    cudaGetSymbolAddress((void**)&ev,   g_e);
    cudaGetSymbolAddress((void**)&cnt,    g_cnt);
    cudaGetSymbolAddress((void**)&rowptr, g_rowptr);
    cudaGetSymbolAddress((void**)&cursor, g_cursor);
    cudaGetSymbolAddress((void**)&colS,   g_colS);
    cudaGetSymbolAddress((void**)&valS,   g_valS);

    cudaFuncSetAttribute(gemm_bf16x3, cudaFuncAttributeMaxDynamicSharedMemorySize, GEMM_SMEM);

    __nv_bfloat16* Wh[3];
    __nv_bfloat16* Wl[3];
    for (int w = 0; w < 3; w++) {
        Wh[w] = WT + (size_t)(w * 2)     * DD * DD;
        Wl[w] = WT + (size_t)(w * 2 + 1) * DD * DD;
    }

    const dim3 ggrid(DD / 128, (M + 127) / 128);
    const int eblk = (E + 255) / 256;
    const int split_blocks = (int)(((size_t)M * DD + 255) / 256);
    const int warp_blocks  = (M * 32 + 255) / 256;

    // ---- Prep: weights, W23, input split ----
    prep_weight<<<(DD * DD + 255) / 256, 256>>>(Lin1, Wh[0], Wl[0]);
    prep_weight<<<(DD * DD + 255) / 256, 256>>>(W1,   Wh[1], Wl[1]);
    gemm512_f32<<<dim3(4, DD), 128>>>(W2, W3, W23);
    prep_weight<<<(DD * DD + 255) / 256, 256>>>(W23, Wh[2], Wl[2]);
    split_strided<<<split_blocks, 256>>>(A1, Ah, Al, M);

    // a0 = x @ Lin1 + bias -> out[:, 512:1024)
    gemm_bf16x3<<<ggrid, 256, GEMM_SMEM>>>(Ah, Al, Wh[0], Wl[0], Lin1_b,
                                           nullptr, nullptr, nullptr, nullptr,
                                           out + 512, 1024, M);
    // U = x @ W1 + b1
    gemm_bf16x3<<<ggrid, 256, GEMM_SMEM>>>(Ah, Al, Wh[1], Wl[1], b1,
                                           nullptr, nullptr, nullptr, nullptr,
                                           U, DD, M);

    // ---- CSR build + correction vectors ----
    cudaMemsetAsync(cnt, 0, (size_t)M * sizeof(int), 0);
    hist_rows<<<eblk, 256>>>(adj_rows, cnt, E);
    scan_rows<<<1, 1024>>>(cnt, rowptr, cursor, M, E);
    scatter_edges<<<eblk, 256>>>(adj_rows, adj_cols, adj_vals, cursor, colS, valS, E);
    rowsum_d<<<warp_blocks, 256>>>(rowptr, valS, dv, M);
    spmv_e<<<warp_blocks, 256>>>(rowptr, colS, valS, dv, ev, M);
    uvec_f32<<<4, 128>>>(b2, W3, uvec);

    // V = x1 = a0*n + (S·U)*(1-n)     [SpMM #1 fused with mix]
    spmm_mix<<<M, 128>>>(rowptr, colS, valS, U, out + 512, nvec, V);

    // U = S·x1                        [SpMM #2]
    spmm_csr<<<M, 128>>>(rowptr, colS, valS, V, U, DD);

    // Ah/Al = split(S·U)              [SpMM #3 fused with bf16 split]
    spmm_split<<<M, 128>>>(rowptr, colS, valS, U, Ah, Al);

    // out[:, 0:512) = t2 @ W23 + e⊗u + d⊗b3
    gemm_bf16x3<<<ggrid, 256, GEMM_SMEM>>>(Ah, Al, Wh[2], Wl[2], nullptr,
                                           ev, uvec, dv, b3,
                                           out, 1024, M);
}

// round 7
// speedup vs baseline: 3.5455x; 1.1619x over previous
#include <cuda_runtime.h>
#include <cuda_bf16.h>
#include <cuda_fp16.h>
#include <cstdint>
#include <cstddef>

#define NN 50000
#define EE 1600000
#define DD 512

// ---------------------------------------------------------------------------
// Device scratch (no runtime alloc allowed)
// ---------------------------------------------------------------------------
__device__ __nv_bfloat16 g_Ah[(size_t)NN * DD];
__device__ __nv_bfloat16 g_Al[(size_t)NN * DD];
__device__ __half        g_H1[(size_t)NN * DD];          // fp16 activations
__device__ __half        g_H2[(size_t)NN * DD];          // fp16 activations
__device__ __nv_bfloat16 g_WT[(size_t)3 * 2 * DD * DD];
__device__ float         g_W23[(size_t)DD * DD];
__device__ float         g_uvec[DD];
// CSR scratch
__device__ int   g_cnt[NN];
__device__ int   g_rowptr[NN + 1];
__device__ int   g_cursor[NN];
__device__ int   g_colS[EE];
__device__ float g_valS[EE];
__device__ float g_d[NN];
__device__ float g_e[NN];

// ---------------------------------------------------------------------------
// Helpers
// ---------------------------------------------------------------------------
__device__ __forceinline__ uint32_t smem_to_u32(const void* p) {
    uint32_t a;
    asm("{ .reg .u64 t; cvta.to.shared.u64 t, %1; cvt.u32.u64 %0, t; }" : "=r"(a) : "l"(p));
    return a;
}

__device__ __forceinline__ void cp16(uint32_t dst, const void* src, bool valid) {
    int sz = valid ? 16 : 0;
    asm volatile("cp.async.cg.shared.global [%0], [%1], 16, %2;"
                 :: "r"(dst), "l"(src), "r"(sz) : "memory");
}
#define CP_COMMIT() asm volatile("cp.async.commit_group;" ::: "memory")
#define CP_WAIT(n)  asm volatile("cp.async.wait_group %0;" :: "n"(n) : "memory")

__device__ __forceinline__ void mma_bf16(float* d, const uint32_t* a, const uint32_t* b) {
    asm volatile("mma.sync.aligned.m16n8k16.row.col.f32.bf16.bf16.f32 "
                 "{%0,%1,%2,%3}, {%4,%5,%6,%7}, {%8,%9}, {%0,%1,%2,%3};"
                 : "+f"(d[0]), "+f"(d[1]), "+f"(d[2]), "+f"(d[3])
                 : "r"(a[0]), "r"(a[1]), "r"(a[2]), "r"(a[3]), "r"(b[0]), "r"(b[1]));
}

__device__ __forceinline__ void bf16_split(float x, __nv_bfloat16& h, __nv_bfloat16& l) {
    h = __float2bfloat16_rn(x);
    l = __float2bfloat16_rn(x - __bfloat162float(h));
}

// ---------------------------------------------------------------------------
// GEMM: C = (Ah+Al) @ (Bh+Bl)^T + epilogue   (bf16x3, mma.sync, occupancy 2)
// Output: fp32 C (ldc), or fp16 C16 when C16 != nullptr.
// ---------------------------------------------------------------------------
#define BK 32
#define RSTRIDE 20
#define TILE_WORDS (128 * RSTRIDE)
#define STAGE_WORDS (4 * TILE_WORDS)
#define GEMM_SMEM (2 * STAGE_WORDS * 4)

__device__ __forceinline__ void gemm_load_stage(
    uint32_t sbase, int stage,
    const __nv_bfloat16* Ah, const __nv_bfloat16* Al,
    const __nv_bfloat16* Bh, const __nv_bfloat16* Bl,
    int bm, int bn, int kc, int M, int tid)
{
    const uint32_t st = sbase + (uint32_t)stage * STAGE_WORDS * 4;
    const int r0 = tid >> 2;
    const int r1 = r0 + 64;
    const int j  = tid & 3;
    const uint32_t d0 = st + (uint32_t)(r0 * RSTRIDE + j * 4) * 4;
    const uint32_t d1 = st + (uint32_t)(r1 * RSTRIDE + j * 4) * 4;
    const size_t koff = (size_t)kc * BK + j * 8;
    const bool v0 = (bm + r0) < M;
    const bool v1 = (bm + r1) < M;

    cp16(d0,                   Ah + (size_t)(bm + r0) * DD + koff, v0);
    cp16(d1,                   Ah + (size_t)(bm + r1) * DD + koff, v1);
    cp16(d0 + TILE_WORDS * 4,  Al + (size_t)(bm + r0) * DD + koff, v0);
    cp16(d1 + TILE_WORDS * 4,  Al + (size_t)(bm + r1) * DD + koff, v1);
    cp16(d0 + TILE_WORDS * 8,  Bh + (size_t)(bn + r0) * DD + koff, true);
    cp16(d1 + TILE_WORDS * 8,  Bh + (size_t)(bn + r1) * DD + koff, true);
    cp16(d0 + TILE_WORDS * 12, Bl + (size_t)(bn + r0) * DD + koff, true);
    cp16(d1 + TILE_WORDS * 12, Bl + (size_t)(bn + r1) * DD + koff, true);
}

__global__ void __launch_bounds__(256, 2) gemm_bf16x3(
    const __nv_bfloat16* __restrict__ Ah, const __nv_bfloat16* __restrict__ Al,
    const __nv_bfloat16* __restrict__ Bh, const __nv_bfloat16* __restrict__ Bl,
    const float* __restrict__ bias,
    const float* __restrict__ rowE, const float* __restrict__ colU,
    const float* __restrict__ rowD, const float* __restrict__ colB3,
    float* __restrict__ C, __half* __restrict__ C16, int ldc, int M)
{
    extern __shared__ uint32_t s[];
    const uint32_t sbase = smem_to_u32(s);
    const int tid  = threadIdx.x;
    const int warp = tid >> 5;
    const int lane = tid & 31;
    const int wm   = (warp & 1) * 64;
    const int wn   = (warp >> 1) * 32;
    const int grp  = lane >> 2;
    const int qd   = lane & 3;
    const int bm = blockIdx.y * 128;
    const int n0 = blockIdx.x * 128;

    float acc[4][4][4];
    #pragma unroll
    for (int i = 0; i < 4; i++)
        #pragma unroll
        for (int j = 0; j < 4; j++)
            #pragma unroll
            for (int q = 0; q < 4; q++) acc[i][j][q] = 0.f;

    gemm_load_stage(sbase, 0, Ah, Al, Bh, Bl, bm, n0, 0, M, tid);
    CP_COMMIT();

    #pragma unroll 1
    for (int kc = 0; kc < DD / BK; kc++) {
        if (kc + 1 < DD / BK) {
            gemm_load_stage(sbase, (kc + 1) & 1, Ah, Al, Bh, Bl, bm, n0, kc + 1, M, tid);
            CP_COMMIT();
            CP_WAIT(1);
        } else {
            CP_WAIT(0);
        }
        __syncthreads();

        const uint32_t* As_h = s + (kc & 1) * STAGE_WORDS;
        const uint32_t* As_l = As_h + TILE_WORDS;
        const uint32_t* Bs_h = As_h + 2 * TILE_WORDS;
        const uint32_t* Bs_l = As_h + 3 * TILE_WORDS;

        #pragma unroll
        for (int ks = 0; ks < 2; ks++) {
            const int kw = ks * 8;
            uint32_t ah[4][4], al[4][4];
            #pragma unroll
            for (int mi = 0; mi < 4; mi++) {
                const int base = (wm + mi * 16 + grp) * RSTRIDE + kw + qd;
                ah[mi][0] = As_h[base];
                ah[mi][1] = As_h[base + 8 * RSTRIDE];
                ah[mi][2] = As_h[base + 4];
                ah[mi][3] = As_h[base + 8 * RSTRIDE + 4];
                al[mi][0] = As_l[base];
                al[mi][1] = As_l[base + 8 * RSTRIDE];
                al[mi][2] = As_l[base + 4];
                al[mi][3] = As_l[base + 8 * RSTRIDE + 4];
            }
            #pragma unroll
            for (int nj = 0; nj < 4; nj++) {
                const int base = (wn + nj * 8 + grp) * RSTRIDE + kw + qd;
                uint32_t bh[2], bl[2];
                bh[0] = Bs_h[base];
                bh[1] = Bs_h[base + 4];
                bl[0] = Bs_l[base];
                bl[1] = Bs_l[base + 4];
                #pragma unroll
                for (int mi = 0; mi < 4; mi++) {
                    mma_bf16(acc[mi][nj], ah[mi], bh);
                    mma_bf16(acc[mi][nj], al[mi], bh);
                    mma_bf16(acc[mi][nj], ah[mi], bl);
                }
            }
        }
        __syncthreads();
    }

    #pragma unroll
    for (int mi = 0; mi < 4; mi++) {
        const int gr = bm + wm + mi * 16 + grp;
        float e0 = 0.f, d0v = 0.f, e1 = 0.f, d1v = 0.f;
        if (rowE) {
            if (gr < M)     { e0 = rowE[gr];     d0v = rowD[gr]; }
            if (gr + 8 < M) { e1 = rowE[gr + 8]; d1v = rowD[gr + 8]; }
        }
        #pragma unroll
        for (int nj = 0; nj < 4; nj++) {
            const int gc = n0 + wn + nj * 8 + qd * 2;
            float2 add0, add1;
            if (rowE) {
                const float2 uu = *(const float2*)(colU + gc);
                const float2 b3 = *(const float2*)(colB3 + gc);
                add0 = make_float2(e0 * uu.x + d0v * b3.x, e0 * uu.y + d0v * b3.y);
                add1 = make_float2(e1 * uu.x + d1v * b3.x, e1 * uu.y + d1v * b3.y);
            } else {
                const float2 bz = *(const float2*)(bias + gc);
                add0 = bz; add1 = bz;
            }
            float2 o0 = {acc[mi][nj][0] + add0.x, acc[mi][nj][1] + add0.y};
            float2 o1 = {acc[mi][nj][2] + add1.x, acc[mi][nj][3] + add1.y};
            if (C16) {
                if (gr < M)
                    *(__half2*)(C16 + (size_t)gr * ldc + gc) = __float22half2_rn(o0);
                if (gr + 8 < M)
                    *(__half2*)(C16 + (size_t)(gr + 8) * ldc + gc) = __float22half2_rn(o1);
            } else {
                if (gr < M)     *(float2*)(C + (size_t)gr * ldc + gc) = o0;
                if (gr + 8 < M) *(float2*)(C + (size_t)(gr + 8) * ldc + gc) = o1;
            }
        }
    }
}

// ---------------------------------------------------------------------------
// Small fp32 kernels: W23 = W2@W3, u = b2@W3
// ---------------------------------------------------------------------------
__global__ void gemm512_f32(const float* __restrict__ A, const float* __restrict__ B,
                            float* __restrict__ C)
{
    const int n = blockIdx.x * 128 + threadIdx.x;
    const int k = blockIdx.y;
    float acc = 0.f;
    #pragma unroll 8
    for (int j = 0; j < DD; j++)
        acc = fmaf(A[k * DD + j], B[j * DD + n], acc);
    C[k * DD + n] = acc;
}

__global__ void uvec_f32(const float* __restrict__ b2, const float* __restrict__ W3,
                         float* __restrict__ u)
{
    const int n = blockIdx.x * 128 + threadIdx.x;
    float acc = 0.f;
    #pragma unroll 8
    for (int j = 0; j < DD; j++)
        acc = fmaf(b2[j], W3[j * DD + n], acc);
    u[n] = acc;
}

// ---------------------------------------------------------------------------
// CSR build + d/e vectors
// ---------------------------------------------------------------------------
__global__ void hist_rows(const int* __restrict__ rows, int* __restrict__ cnt, int E)
{
    int e = blockIdx.x * blockDim.x + threadIdx.x;
    if (e < E) atomicAdd(&cnt[rows[e]], 1);
}

__global__ void __launch_bounds__(1024) scan_rows(
    const int* __restrict__ cnt, int* __restrict__ row_ptr,
    int* __restrict__ cursor, int M, int E)
{
    __shared__ int sm[1024];
    const int tid = threadIdx.x;
    const int chunk = (M + 1023) >> 10;
    const int base = tid * chunk;

    int local = 0;
    for (int i = 0; i < chunk; i++) {
        int r = base + i;
        if (r < M) local += cnt[r];
    }
    sm[tid] = local;
    __syncthreads();
    for (int off = 1; off < 1024; off <<= 1) {
        int v = (tid >= off) ? sm[tid - off] : 0;
        __syncthreads();
        sm[tid] += v;
        __syncthreads();
    }
    int run = sm[tid] - local;
    for (int i = 0; i < chunk; i++) {
        int r = base + i;
        if (r < M) {
            row_ptr[r] = run;
            cursor[r]  = run;
            run += cnt[r];
        }
    }
    if (tid == 0) row_ptr[M] = E;
}

__global__ void scatter_edges(const int* __restrict__ rows, const int* __restrict__ cols,
                              const float* __restrict__ vals,
                              int* __restrict__ cursor,
                              int* __restrict__ colS, float* __restrict__ valS, int E)
{
    int e = blockIdx.x * blockDim.x + threadIdx.x;
    if (e >= E) return;
    int r = rows[e];
    int p = atomicAdd(&cursor[r], 1);
    colS[p] = cols[e];
    valS[p] = vals[e];
}

__global__ void rowsum_d(const int* __restrict__ row_ptr, const float* __restrict__ valS,
                         float* __restrict__ d, int M)
{
    int r = (blockIdx.x * blockDim.x + threadIdx.x) >> 5;
    if (r >= M) return;
    int lane = threadIdx.x & 31;
    float acc = 0.f;
    for (int e = row_ptr[r] + lane; e < row_ptr[r + 1]; e += 32) acc += valS[e];
    #pragma unroll
    for (int o = 16; o; o >>= 1) acc += __shfl_down_sync(0xffffffffu, acc, o);
    if (lane == 0) d[r] = acc;
}

__global__ void spmv_e(const int* __restrict__ row_ptr, const int* __restrict__ colS,
                       const float* __restrict__ valS, const float* __restrict__ d,
                       float* __restrict__ evec, int M)
{
    int r = (blockIdx.x * blockDim.x + threadIdx.x) >> 5;
    if (r >= M) return;
    int lane = threadIdx.x & 31;
    float acc = 0.f;
    for (int e = row_ptr[r] + lane; e < row_ptr[r + 1]; e += 32)
        acc = fmaf(valS[e], d[colS[e]], acc);
    #pragma unroll
    for (int o = 16; o; o >>= 1) acc += __shfl_down_sync(0xffffffffu, acc, o);
    if (lane == 0) evec[r] = acc;
}

// ---------------------------------------------------------------------------
// fp16 CSR SpMM core: block per row, 128 threads x 4 features, fp32 accumulate
// ---------------------------------------------------------------------------
__device__ __forceinline__ float4 spmm_row_acc_h(
    const int* __restrict__ row_ptr,
    const int* __restrict__ colS, const float* __restrict__ valS,
    const __half* __restrict__ in, int r, int tid)
{
    const size_t off = (size_t)tid * 4;
    int e = row_ptr[r];
    const int end = row_ptr[r + 1];
    float4 acc = {0.f, 0.f, 0.f, 0.f};

    for (; e + 2 <= end; e += 2) {
        const int   c0 = __ldg(colS + e);
        const int   c1 = __ldg(colS + e + 1);
        const float v0 = __ldg(valS + e);
        const float v1 = __ldg(valS + e + 1);
        const uint2 r0 = *(const uint2*)(in + (size_t)c0 * DD + off);
        const uint2 r1 = *(const uint2*)(in + (size_t)c1 * DD + off);
        const float2 a0 = __half22float2(*(const __half2*)&r0.x);
        const float2 a1 = __half22float2(*(const __half2*)&r0.y);
        const float2 b0 = __half22float2(*(const __half2*)&r1.x);
        const float2 b1 = __half22float2(*(const __half2*)&r1.y);
        acc.x = fmaf(v0, a0.x, acc.x); acc.y = fmaf(v0, a0.y, acc.y);
        acc.z = fmaf(v0, a1.x, acc.z); acc.w = fmaf(v0, a1.y, acc.w);
        acc.x = fmaf(v1, b0.x, acc.x); acc.y = fmaf(v1, b0.y, acc.y);
        acc.z = fmaf(v1, b1.x, acc.z); acc.w = fmaf(v1, b1.y, acc.w);
    }
    if (e < end) {
        const int   c0 = __ldg(colS + e);
        const float v0 = __ldg(valS + e);
        const uint2 r0 = *(const uint2*)(in + (size_t)c0 * DD + off);
        const float2 a0 = __half22float2(*(const __half2*)&r0.x);
        const float2 a1 = __half22float2(*(const __half2*)&r0.y);
        acc.x = fmaf(v0, a0.x, acc.x); acc.y = fmaf(v0, a0.y, acc.y);
        acc.z = fmaf(v0, a1.x, acc.z); acc.w = fmaf(v0, a1.y, acc.w);
    }
    return acc;
}

__device__ __forceinline__ void store_h4(__half* dst, float4 v) {
    uint2 o;
    *(__half2*)&o.x = __float22half2_rn(make_float2(v.x, v.y));
    *(__half2*)&o.y = __float22half2_rn(make_float2(v.z, v.w));
    *(uint2*)dst = o;
}

// SpMM #1 fused with mix: x1 = a0*n + (S·in)*(1-n), fp16 in/out
__global__ void __launch_bounds__(128) spmm_mix_h(
    const int* __restrict__ row_ptr,
    const int* __restrict__ colS, const float* __restrict__ valS,
    const __half* __restrict__ in,
    const float* __restrict__ a0, const float* __restrict__ nvec,
    __half* __restrict__ x1)
{
    const int r = blockIdx.x;
    const int tid = threadIdx.x;
    float4 acc = spmm_row_acc_h(row_ptr, colS, valS, in, r, tid);
    const float nv = nvec[r];
    const float om = 1.f - nv;
    const float4 a = *(const float4*)(a0 + (size_t)r * 1024 + (size_t)tid * 4);
    float4 o;
    o.x = a.x * nv + acc.x * om;
    o.y = a.y * nv + acc.y * om;
    o.z = a.z * nv + acc.z * om;
    o.w = a.w * nv + acc.w * om;
    store_h4(x1 + (size_t)r * DD + (size_t)tid * 4, o);
}

// SpMM #2: fp16 -> fp16
__global__ void __launch_bounds__(128) spmm_csr_h(
    const int* __restrict__ row_ptr,
    const int* __restrict__ colS, const float* __restrict__ valS,
    const __half* __restrict__ in, __half* __restrict__ out)
{
    const int r = blockIdx.x;
    const int tid = threadIdx.x;
    float4 acc = spmm_row_acc_h(row_ptr, colS, valS, in, r, tid);
    store_h4(out + (size_t)r * DD + (size_t)tid * 4, acc);
}

// SpMM #3 fused with bf16 hi/lo split (feeds final GEMM)
__global__ void __launch_bounds__(128) spmm_split_h(
    const int* __restrict__ row_ptr,
    const int* __restrict__ colS, const float* __restrict__ valS,
    const __half* __restrict__ in,
    __nv_bfloat16* __restrict__ hi, __nv_bfloat16* __restrict__ lo)
{
    const int r = blockIdx.x;
    const int tid = threadIdx.x;
    float4 acc = spmm_row_acc_h(row_ptr, colS, valS, in, r, tid);
    __nv_bfloat16 h[4], l[4];
    bf16_split(acc.x, h[0], l[0]);
    bf16_split(acc.y, h[1], l[1]);
    bf16_split(acc.z, h[2], l[2]);
    bf16_split(acc.w, h[3], l[3]);
    *(uint2*)(hi + (size_t)r * DD + (size_t)tid * 4) = *(uint2*)h;
    *(uint2*)(lo + (size_t)r * DD + (size_t)tid * 4) = *(uint2*)l;
}

// ---------------------------------------------------------------------------
// Split / prep kernels
// ---------------------------------------------------------------------------
__global__ void split_strided(const float* __restrict__ A1,
                              __nv_bfloat16* __restrict__ hi,
                              __nv_bfloat16* __restrict__ lo, int M)
{
    size_t i = (size_t)blockIdx.x * blockDim.x + threadIdx.x;
    if (i >= (size_t)M * DD) return;
    size_t r = i >> 9;
    int c = (int)(i & 511);
    float x = A1[r * 513 + 1 + c];
    bf16_split(x, hi[i], lo[i]);
}

__global__ void prep_weight(const float* __restrict__ W,
                            __nv_bfloat16* __restrict__ hi,
                            __nv_bfloat16* __restrict__ lo)
{
    int i = blockIdx.x * blockDim.x + threadIdx.x;
    if (i >= DD * DD) return;
    int n = i >> 9, k = i & 511;
    float v = W[k * DD + n];
    bf16_split(v, hi[i], lo[i]);
}

// ---------------------------------------------------------------------------
// Host driver
// ---------------------------------------------------------------------------
extern "C" void kernel_launch(void* const* d_in, const int* in_sizes, int n_in,
                              void* d_out, int out_size)
{
    const float* A1       = (const float*)d_in[0];
    const int*   adj_rows = (const int*)  d_in[1];
    const int*   adj_cols = (const int*)  d_in[2];
    const float* adj_vals = (const float*)d_in[3];
    const float* Lin1     = (const float*)d_in[4];
    const float* Lin1_b   = (const float*)d_in[5];
    const float* nvec     = (const float*)d_in[6];
    const float* W1       = (const float*)d_in[7];
    const float* b1       = (const float*)d_in[8];
    const float* W2       = (const float*)d_in[9];
    const float* b2       = (const float*)d_in[10];
    const float* W3       = (const float*)d_in[11];
    const float* b3       = (const float*)d_in[12];
    float* out = (float*)d_out;

    const int M = in_sizes[6];   // 50000
    const int E = in_sizes[1];   // 1,600,000

    __nv_bfloat16 *Ah, *Al, *WT;
    __half *H1, *H2;
    float *valS, *W23, *uvec, *dv, *ev;
    int *cnt, *rowptr, *cursor, *colS;
    cudaGetSymbolAddress((void**)&Ah, g_Ah);
    cudaGetSymbolAddress((void**)&Al, g_Al);
    cudaGetSymbolAddress((void**)&H1, g_H1);
    cudaGetSymbolAddress((void**)&H2, g_H2);
    cudaGetSymbolAddress((void**)&WT, g_WT);
    cudaGetSymbolAddress((void**)&W23,  g_W23);
    cudaGetSymbolAddress((void**)&uvec, g_uvec);
    cudaGetSymbolAddress((void**)&dv,   g_d);
    cudaGetSymbolAddress((void**)&ev,   g_e);
    cudaGetSymbolAddress((void**)&cnt,    g_cnt);
    cudaGetSymbolAddress((void**)&rowptr, g_rowptr);
    cudaGetSymbolAddress((void**)&cursor, g_cursor);
    cudaGetSymbolAddress((void**)&colS,   g_colS);
    cudaGetSymbolAddress((void**)&valS,   g_valS);

    cudaFuncSetAttribute(gemm_bf16x3, cudaFuncAttributeMaxDynamicSharedMemorySize, GEMM_SMEM);

    __nv_bfloat16* Wh[3];
    __nv_bfloat16* Wl[3];
    for (int w = 0; w < 3; w++) {
        Wh[w] = WT + (size_t)(w * 2)     * DD * DD;
        Wl[w] = WT + (size_t)(w * 2 + 1) * DD * DD;
    }

    const dim3 ggrid(DD / 128, (M + 127) / 128);
    const int eblk = (E + 255) / 256;
    const int split_blocks = (int)(((size_t)M * DD + 255) / 256);
    const int warp_blocks  = (M * 32 + 255) / 256;

    // ---- Prep: weights, W23, input split ----
    prep_weight<<<(DD * DD + 255) / 256, 256>>>(Lin1, Wh[0], Wl[0]);
    prep_weight<<<(DD * DD + 255) / 256, 256>>>(W1,   Wh[1], Wl[1]);
    gemm512_f32<<<dim3(4, DD), 128>>>(W2, W3, W23);
    prep_weight<<<(DD * DD + 255) / 256, 256>>>(W23, Wh[2], Wl[2]);
    split_strided<<<split_blocks, 256>>>(A1, Ah, Al, M);

    // a0 = x @ Lin1 + bias -> out[:, 512:1024)  (fp32)
    gemm_bf16x3<<<ggrid, 256, GEMM_SMEM>>>(Ah, Al, Wh[0], Wl[0], Lin1_b,
                                           nullptr, nullptr, nullptr, nullptr,
                                           out + 512, nullptr, 1024, M);
    // H1 = x @ W1 + b1   (fp16 output)
    gemm_bf16x3<<<ggrid, 256, GEMM_SMEM>>>(Ah, Al, Wh[1], Wl[1], b1,
                                           nullptr, nullptr, nullptr, nullptr,
                                           nullptr, H1, DD, M);

    // ---- CSR build + correction vectors ----
    cudaMemsetAsync(cnt, 0, (size_t)M * sizeof(int), 0);
    hist_rows<<<eblk, 256>>>(adj_rows, cnt, E);
    scan_rows<<<1, 1024>>>(cnt, rowptr, cursor, M, E);
    scatter_edges<<<eblk, 256>>>(adj_rows, adj_cols, adj_vals, cursor, colS, valS, E);
    rowsum_d<<<warp_blocks, 256>>>(rowptr, valS, dv, M);
    spmv_e<<<warp_blocks, 256>>>(rowptr, colS, valS, dv, ev, M);
    uvec_f32<<<4, 128>>>(b2, W3, uvec);

    // H2 = x1 = a0*n + (S·H1)*(1-n)    [SpMM #1, fp16]
    spmm_mix_h<<<M, 128>>>(rowptr, colS, valS, H1, out + 512, nvec, H2);

    // H1 = S·H2                        [SpMM #2, fp16]
    spmm_csr_h<<<M, 128>>>(rowptr, colS, valS, H2, H1);

    // Ah/Al = split(S·H1)              [SpMM #3 + bf16 split]
    spmm_split_h<<<M, 128>>>(rowptr, colS, valS, H1, Ah, Al);

    // out[:, 0:512) = t2 @ W23 + e⊗u + d⊗b3
    gemm_bf16x3<<<ggrid, 256, GEMM_SMEM>>>(Ah, Al, Wh[2], Wl[2], nullptr,
                                           ev, uvec, dv, b3,
                                           out, nullptr, 1024, M);
}

// round 8
// speedup vs baseline: 5.0078x; 1.4124x over previous
#include <cuda_runtime.h>
#include <cuda_bf16.h>
#include <cuda_fp16.h>
#include <cstdint>
#include <cstddef>

#define NN 50000
#define EE 1600000
#define DD 512

// ---------------------------------------------------------------------------
// Device scratch (no runtime alloc allowed)
// ---------------------------------------------------------------------------
__device__ __half g_A16[(size_t)NN * DD];        // fp16 GEMM input activations
__device__ __half g_H1[(size_t)NN * DD];         // fp16 activations
__device__ __half g_H2[(size_t)NN * DD];         // fp16 activations
__device__ __half g_W16[(size_t)3 * DD * DD];    // 3 weights, fp16, [N][K]
__device__ float  g_W23[(size_t)DD * DD];
__device__ float  g_uvec[DD];
// CSR scratch
__device__ int   g_cnt[NN];
__device__ int   g_rowptr[NN + 1];
__device__ int   g_cursor[NN];
__device__ int   g_colS[EE];
__device__ float g_valS[EE];
__device__ float g_d[NN];
__device__ float g_e[NN];

// ---------------------------------------------------------------------------
// Helpers
// ---------------------------------------------------------------------------
__device__ __forceinline__ uint32_t smem_to_u32(const void* p) {
    uint32_t a;
    asm("{ .reg .u64 t; cvta.to.shared.u64 t, %1; cvt.u32.u64 %0, t; }" : "=r"(a) : "l"(p));
    return a;
}

__device__ __forceinline__ void cp16(uint32_t dst, const void* src, bool valid) {
    int sz = valid ? 16 : 0;
    asm volatile("cp.async.cg.shared.global [%0], [%1], 16, %2;"
                 :: "r"(dst), "l"(src), "r"(sz) : "memory");
}
#define CP_COMMIT() asm volatile("cp.async.commit_group;" ::: "memory")
#define CP_WAIT(n)  asm volatile("cp.async.wait_group %0;" :: "n"(n) : "memory")

__device__ __forceinline__ void mma_f16(float* d, const uint32_t* a, const uint32_t* b) {
    asm volatile("mma.sync.aligned.m16n8k16.row.col.f32.f16.f16.f32 "
                 "{%0,%1,%2,%3}, {%4,%5,%6,%7}, {%8,%9}, {%0,%1,%2,%3};"
                 : "+f"(d[0]), "+f"(d[1]), "+f"(d[2]), "+f"(d[3])
                 : "r"(a[0]), "r"(a[1]), "r"(a[2]), "r"(a[3]), "r"(b[0]), "r"(b[1]));
}

// ---------------------------------------------------------------------------
// GEMM: C[Mx512] = A16 @ B16^T + epilogue   (fp16 mma, fp32 accum, occ 2)
// BM=128, BN=128, BK=32, 256 threads, warp tile 64x32, 2-stage cp.async.
// ---------------------------------------------------------------------------
#define BK 32
#define RSTRIDE 20
#define TILE_WORDS (128 * RSTRIDE)
#define STAGE_WORDS (2 * TILE_WORDS)        // A16, B16
#define GEMM_SMEM (2 * STAGE_WORDS * 4)     // 40960 bytes

__device__ __forceinline__ void gemm_load_stage(
    uint32_t sbase, int stage,
    const __half* A, const __half* B,
    int bm, int bn, int kc, int M, int tid)
{
    const uint32_t st = sbase + (uint32_t)stage * STAGE_WORDS * 4;
    const int r0 = tid >> 2;
    const int r1 = r0 + 64;
    const int j  = tid & 3;
    const uint32_t d0 = st + (uint32_t)(r0 * RSTRIDE + j * 4) * 4;
    const uint32_t d1 = st + (uint32_t)(r1 * RSTRIDE + j * 4) * 4;
    const size_t koff = (size_t)kc * BK + j * 8;
    const bool v0 = (bm + r0) < M;
    const bool v1 = (bm + r1) < M;

    cp16(d0,                  A + (size_t)(bm + r0) * DD + koff, v0);
    cp16(d1,                  A + (size_t)(bm + r1) * DD + koff, v1);
    cp16(d0 + TILE_WORDS * 4, B + (size_t)(bn + r0) * DD + koff, true);
    cp16(d1 + TILE_WORDS * 4, B + (size_t)(bn + r1) * DD + koff, true);
}

__global__ void __launch_bounds__(256, 2) gemm_f16(
    const __half* __restrict__ A, const __half* __restrict__ B,
    const float* __restrict__ bias,
    const float* __restrict__ rowE, const float* __restrict__ colU,
    const float* __restrict__ rowD, const float* __restrict__ colB3,
    float* __restrict__ C, __half* __restrict__ C16, int ldc, int M)
{
    extern __shared__ uint32_t s[];
    const uint32_t sbase = smem_to_u32(s);
    const int tid  = threadIdx.x;
    const int warp = tid >> 5;
    const int lane = tid & 31;
    const int wm   = (warp & 1) * 64;
    const int wn   = (warp >> 1) * 32;
    const int grp  = lane >> 2;
    const int qd   = lane & 3;
    const int bm = blockIdx.y * 128;
    const int n0 = blockIdx.x * 128;

    float acc[4][4][4];
    #pragma unroll
    for (int i = 0; i < 4; i++)
        #pragma unroll
        for (int j = 0; j < 4; j++)
            #pragma unroll
            for (int q = 0; q < 4; q++) acc[i][j][q] = 0.f;

    gemm_load_stage(sbase, 0, A, B, bm, n0, 0, M, tid);
    CP_COMMIT();

    #pragma unroll 1
    for (int kc = 0; kc < DD / BK; kc++) {
        if (kc + 1 < DD / BK) {
            gemm_load_stage(sbase, (kc + 1) & 1, A, B, bm, n0, kc + 1, M, tid);
            CP_COMMIT();
            CP_WAIT(1);
        } else {
            CP_WAIT(0);
        }
        __syncthreads();

        const uint32_t* As = s + (kc & 1) * STAGE_WORDS;
        const uint32_t* Bs = As + TILE_WORDS;

        #pragma unroll
        for (int ks = 0; ks < 2; ks++) {
            const int kw = ks * 8;
            uint32_t ah[4][4];
            #pragma unroll
            for (int mi = 0; mi < 4; mi++) {
                const int base = (wm + mi * 16 + grp) * RSTRIDE + kw + qd;
                ah[mi][0] = As[base];
                ah[mi][1] = As[base + 8 * RSTRIDE];
                ah[mi][2] = As[base + 4];
                ah[mi][3] = As[base + 8 * RSTRIDE + 4];
            }
            #pragma unroll
            for (int nj = 0; nj < 4; nj++) {
                const int base = (wn + nj * 8 + grp) * RSTRIDE + kw + qd;
                uint32_t bh[2];
                bh[0] = Bs[base];
                bh[1] = Bs[base + 4];
                #pragma unroll
                for (int mi = 0; mi < 4; mi++)
                    mma_f16(acc[mi][nj], ah[mi], bh);
            }
        }
        __syncthreads();
    }

    #pragma unroll
    for (int mi = 0; mi < 4; mi++) {
        const int gr = bm + wm + mi * 16 + grp;
        float e0 = 0.f, d0v = 0.f, e1 = 0.f, d1v = 0.f;
        if (rowE) {
            if (gr < M)     { e0 = rowE[gr];     d0v = rowD[gr]; }
            if (gr + 8 < M) { e1 = rowE[gr + 8]; d1v = rowD[gr + 8]; }
        }
        #pragma unroll
        for (int nj = 0; nj < 4; nj++) {
            const int gc = n0 + wn + nj * 8 + qd * 2;
            float2 add0, add1;
            if (rowE) {
                const float2 uu = *(const float2*)(colU + gc);
                const float2 b3 = *(const float2*)(colB3 + gc);
                add0 = make_float2(e0 * uu.x + d0v * b3.x, e0 * uu.y + d0v * b3.y);
                add1 = make_float2(e1 * uu.x + d1v * b3.x, e1 * uu.y + d1v * b3.y);
            } else {
                const float2 bz = *(const float2*)(bias + gc);
                add0 = bz; add1 = bz;
            }
            float2 o0 = {acc[mi][nj][0] + add0.x, acc[mi][nj][1] + add0.y};
            float2 o1 = {acc[mi][nj][2] + add1.x, acc[mi][nj][3] + add1.y};
            if (C16) {
                if (gr < M)
                    *(__half2*)(C16 + (size_t)gr * ldc + gc) = __float22half2_rn(o0);
                if (gr + 8 < M)
                    *(__half2*)(C16 + (size_t)(gr + 8) * ldc + gc) = __float22half2_rn(o1);
            } else {
                if (gr < M)     *(float2*)(C + (size_t)gr * ldc + gc) = o0;
                if (gr + 8 < M) *(float2*)(C + (size_t)(gr + 8) * ldc + gc) = o1;
            }
        }
    }
}

// ---------------------------------------------------------------------------
// Small fp32 kernels: W23 = W2@W3, u = b2@W3
// ---------------------------------------------------------------------------
__global__ void gemm512_f32(const float* __restrict__ A, const float* __restrict__ B,
                            float* __restrict__ C)
{
    const int n = blockIdx.x * 128 + threadIdx.x;
    const int k = blockIdx.y;
    float acc = 0.f;
    #pragma unroll 8
    for (int j = 0; j < DD; j++)
        acc = fmaf(A[k * DD + j], B[j * DD + n], acc);
    C[k * DD + n] = acc;
}

__global__ void uvec_f32(const float* __restrict__ b2, const float* __restrict__ W3,
                         float* __restrict__ u)
{
    const int n = blockIdx.x * 128 + threadIdx.x;
    float acc = 0.f;
    #pragma unroll 8
    for (int j = 0; j < DD; j++)
        acc = fmaf(b2[j], W3[j * DD + n], acc);
    u[n] = acc;
}

// ---------------------------------------------------------------------------
// CSR build + d/e vectors
// ---------------------------------------------------------------------------
__global__ void hist_rows(const int* __restrict__ rows, int* __restrict__ cnt, int E)
{
    int e = blockIdx.x * blockDim.x + threadIdx.x;
    if (e < E) atomicAdd(&cnt[rows[e]], 1);
}

__global__ void __launch_bounds__(1024) scan_rows(
    const int* __restrict__ cnt, int* __restrict__ row_ptr,
    int* __restrict__ cursor, int M, int E)
{
    __shared__ int sm[1024];
    const int tid = threadIdx.x;
    const int chunk = (M + 1023) >> 10;
    const int base = tid * chunk;

    int local = 0;
    for (int i = 0; i < chunk; i++) {
        int r = base + i;
        if (r < M) local += cnt[r];
    }
    sm[tid] = local;
    __syncthreads();
    for (int off = 1; off < 1024; off <<= 1) {
        int v = (tid >= off) ? sm[tid - off] : 0;
        __syncthreads();
        sm[tid] += v;
        __syncthreads();
    }
    int run = sm[tid] - local;
    for (int i = 0; i < chunk; i++) {
        int r = base + i;
        if (r < M) {
            row_ptr[r] = run;
            cursor[r]  = run;
            run += cnt[r];
        }
    }
    if (tid == 0) row_ptr[M] = E;
}

__global__ void scatter_edges(const int* __restrict__ rows, const int* __restrict__ cols,
                              const float* __restrict__ vals,
                              int* __restrict__ cursor,
                              int* __restrict__ colS, float* __restrict__ valS, int E)
{
    int e = blockIdx.x * blockDim.x + threadIdx.x;
    if (e >= E) return;
    int r = rows[e];
    int p = atomicAdd(&cursor[r], 1);
    colS[p] = cols[e];
    valS[p] = vals[e];
}

__global__ void rowsum_d(const int* __restrict__ row_ptr, const float* __restrict__ valS,
                         float* __restrict__ d, int M)
{
    int r = (blockIdx.x * blockDim.x + threadIdx.x) >> 5;
    if (r >= M) return;
    int lane = threadIdx.x & 31;
    float acc = 0.f;
    for (int e = row_ptr[r] + lane; e < row_ptr[r + 1]; e += 32) acc += valS[e];
    #pragma unroll
    for (int o = 16; o; o >>= 1) acc += __shfl_down_sync(0xffffffffu, acc, o);
    if (lane == 0) d[r] = acc;
}

__global__ void spmv_e(const int* __restrict__ row_ptr, const int* __restrict__ colS,
                       const float* __restrict__ valS, const float* __restrict__ d,
                       float* __restrict__ evec, int M)
{
    int r = (blockIdx.x * blockDim.x + threadIdx.x) >> 5;
    if (r >= M) return;
    int lane = threadIdx.x & 31;
    float acc = 0.f;
    for (int e = row_ptr[r] + lane; e < row_ptr[r + 1]; e += 32)
        acc = fmaf(valS[e], d[colS[e]], acc);
    #pragma unroll
    for (int o = 16; o; o >>= 1) acc += __shfl_down_sync(0xffffffffu, acc, o);
    if (lane == 0) evec[r] = acc;
}

// ---------------------------------------------------------------------------
// fp16 CSR SpMM core: block per row, 128 threads x 4 features, fp32 accumulate
// ---------------------------------------------------------------------------
__device__ __forceinline__ float4 spmm_row_acc_h(
    const int* __restrict__ row_ptr,
    const int* __restrict__ colS, const float* __restrict__ valS,
    const __half* __restrict__ in, int r, int tid)
{
    const size_t off = (size_t)tid * 4;
    int e = row_ptr[r];
    const int end = row_ptr[r + 1];
    float4 acc = {0.f, 0.f, 0.f, 0.f};

    for (; e + 2 <= end; e += 2) {
        const int   c0 = __ldg(colS + e);
        const int   c1 = __ldg(colS + e + 1);
        const float v0 = __ldg(valS + e);
        const float v1 = __ldg(valS + e + 1);
        const uint2 r0 = *(const uint2*)(in + (size_t)c0 * DD + off);
        const uint2 r1 = *(const uint2*)(in + (size_t)c1 * DD + off);
        const float2 a0 = __half22float2(*(const __half2*)&r0.x);
        const float2 a1 = __half22float2(*(const __half2*)&r0.y);
        const float2 b0 = __half22float2(*(const __half2*)&r1.x);
        const float2 b1 = __half22float2(*(const __half2*)&r1.y);
        acc.x = fmaf(v0, a0.x, acc.x); acc.y = fmaf(v0, a0.y, acc.y);
        acc.z = fmaf(v0, a1.x, acc.z); acc.w = fmaf(v0, a1.y, acc.w);
        acc.x = fmaf(v1, b0.x, acc.x); acc.y = fmaf(v1, b0.y, acc.y);
        acc.z = fmaf(v1, b1.x, acc.z); acc.w = fmaf(v1, b1.y, acc.w);
    }
    if (e < end) {
        const int   c0 = __ldg(colS + e);
        const float v0 = __ldg(valS + e);
        const uint2 r0 = *(const uint2*)(in + (size_t)c0 * DD + off);
        const float2 a0 = __half22float2(*(const __half2*)&r0.x);
        const float2 a1 = __half22float2(*(const __half2*)&r0.y);
        acc.x = fmaf(v0, a0.x, acc.x); acc.y = fmaf(v0, a0.y, acc.y);
        acc.z = fmaf(v0, a1.x, acc.z); acc.w = fmaf(v0, a1.y, acc.w);
    }
    return acc;
}

__device__ __forceinline__ void store_h4(__half* dst, float4 v) {
    uint2 o;
    *(__half2*)&o.x = __float22half2_rn(make_float2(v.x, v.y));
    *(__half2*)&o.y = __float22half2_rn(make_float2(v.z, v.w));
    *(uint2*)dst = o;
}

// SpMM #1 fused with mix: x1 = a0*n + (S·in)*(1-n), fp16 in/out
__global__ void __launch_bounds__(128) spmm_mix_h(
    const int* __restrict__ row_ptr,
    const int* __restrict__ colS, const float* __restrict__ valS,
    const __half* __restrict__ in,
    const float* __restrict__ a0, const float* __restrict__ nvec,
    __half* __restrict__ x1)
{
    const int r = blockIdx.x;
    const int tid = threadIdx.x;
    float4 acc = spmm_row_acc_h(row_ptr, colS, valS, in, r, tid);
    const float nv = nvec[r];
    const float om = 1.f - nv;
    const float4 a = *(const float4*)(a0 + (size_t)r * 1024 + (size_t)tid * 4);
    float4 o;
    o.x = a.x * nv + acc.x * om;
    o.y = a.y * nv + acc.y * om;
    o.z = a.z * nv + acc.z * om;
    o.w = a.w * nv + acc.w * om;
    store_h4(x1 + (size_t)r * DD + (size_t)tid * 4, o);
}

// Plain fp16 SpMM: out = S·in
__global__ void __launch_bounds__(128) spmm_csr_h(
    const int* __restrict__ row_ptr,
    const int* __restrict__ colS, const float* __restrict__ valS,
    const __half* __restrict__ in, __half* __restrict__ out)
{
    const int r = blockIdx.x;
    const int tid = threadIdx.x;
    float4 acc = spmm_row_acc_h(row_ptr, colS, valS, in, r, tid);
    store_h4(out + (size_t)r * DD + (size_t)tid * 4, acc);
}

// ---------------------------------------------------------------------------
// Split / prep kernels (fp16 outputs)
// ---------------------------------------------------------------------------
__global__ void split_strided_h(const float* __restrict__ A1,
                                __half* __restrict__ o, int M)
{
    size_t i = (size_t)blockIdx.x * blockDim.x + threadIdx.x;
    if (i >= (size_t)M * DD) return;
    size_t r = i >> 9;
    int c = (int)(i & 511);
    o[i] = __float2half_rn(A1[r * 513 + 1 + c]);
}

__global__ void prep_weight_h(const float* __restrict__ W, __half* __restrict__ o)
{
    int i = blockIdx.x * blockDim.x + threadIdx.x;
    if (i >= DD * DD) return;
    int n = i >> 9, k = i & 511;
    o[i] = __float2half_rn(W[k * DD + n]);
}

// ---------------------------------------------------------------------------
// Host driver
// ---------------------------------------------------------------------------
extern "C" void kernel_launch(void* const* d_in, const int* in_sizes, int n_in,
                              void* d_out, int out_size)
{
    const float* A1       = (const float*)d_in[0];
    const int*   adj_rows = (const int*)  d_in[1];
    const int*   adj_cols = (const int*)  d_in[2];
    const float* adj_vals = (const float*)d_in[3];
    const float* Lin1     = (const float*)d_in[4];
    const float* Lin1_b   = (const float*)d_in[5];
    const float* nvec     = (const float*)d_in[6];
    const float* W1       = (const float*)d_in[7];
    const float* b1       = (const float*)d_in[8];
    const float* W2       = (const float*)d_in[9];
    const float* b2       = (const float*)d_in[10];
    const float* W3       = (const float*)d_in[11];
    const float* b3       = (const float*)d_in[12];
    float* out = (float*)d_out;

    const int M = in_sizes[6];   // 50000
    const int E = in_sizes[1];   // 1,600,000

    __half *A16, *H1, *H2, *W16;
    float *valS, *W23, *uvec, *dv, *ev;
    int *cnt, *rowptr, *cursor, *colS;
    cudaGetSymbolAddress((void**)&A16, g_A16);
    cudaGetSymbolAddress((void**)&H1,  g_H1);
    cudaGetSymbolAddress((void**)&H2,  g_H2);
    cudaGetSymbolAddress((void**)&W16, g_W16);
    cudaGetSymbolAddress((void**)&W23,  g_W23);
    cudaGetSymbolAddress((void**)&uvec, g_uvec);
    cudaGetSymbolAddress((void**)&dv,   g_d);
    cudaGetSymbolAddress((void**)&ev,   g_e);
    cudaGetSymbolAddress((void**)&cnt,    g_cnt);
    cudaGetSymbolAddress((void**)&rowptr, g_rowptr);
    cudaGetSymbolAddress((void**)&cursor, g_cursor);
    cudaGetSymbolAddress((void**)&colS,   g_colS);
    cudaGetSymbolAddress((void**)&valS,   g_valS);

    cudaFuncSetAttribute(gemm_f16, cudaFuncAttributeMaxDynamicSharedMemorySize, GEMM_SMEM);

    __half* Wp[3] = {W16, W16 + (size_t)DD * DD, W16 + (size_t)2 * DD * DD};

    const dim3 ggrid(DD / 128, (M + 127) / 128);
    const int eblk = (E + 255) / 256;
    const int split_blocks = (int)(((size_t)M * DD + 255) / 256);
    const int warp_blocks  = (M * 32 + 255) / 256;

    // ---- Prep (launches 0-4; keeps first gemm at profiled index 5) ----
    prep_weight_h<<<(DD * DD + 255) / 256, 256>>>(Lin1, Wp[0]);        // 0
    prep_weight_h<<<(DD * DD + 255) / 256, 256>>>(W1,   Wp[1]);        // 1
    gemm512_f32<<<dim3(4, DD), 128>>>(W2, W3, W23);                    // 2
    prep_weight_h<<<(DD * DD + 255) / 256, 256>>>(W23, Wp[2]);         // 3
    split_strided_h<<<split_blocks, 256>>>(A1, A16, M);                // 4

    // a0 = x @ Lin1 + bias -> out[:, 512:1024)  (fp32)
    gemm_f16<<<ggrid, 256, GEMM_SMEM>>>(A16, Wp[0], Lin1_b,
                                        nullptr, nullptr, nullptr, nullptr,
                                        out + 512, nullptr, 1024, M);
    // H1 = x @ W1 + b1   (fp16 output)
    gemm_f16<<<ggrid, 256, GEMM_SMEM>>>(A16, Wp[1], b1,
                                        nullptr, nullptr, nullptr, nullptr,
                                        nullptr, H1, DD, M);

    // ---- CSR build + correction vectors ----
    cudaMemsetAsync(cnt, 0, (size_t)M * sizeof(int), 0);
    hist_rows<<<eblk, 256>>>(adj_rows, cnt, E);
    scan_rows<<<1, 1024>>>(cnt, rowptr, cursor, M, E);
    scatter_edges<<<eblk, 256>>>(adj_rows, adj_cols, adj_vals, cursor, colS, valS, E);
    rowsum_d<<<warp_blocks, 256>>>(rowptr, valS, dv, M);
    spmv_e<<<warp_blocks, 256>>>(rowptr, colS, valS, dv, ev, M);
    uvec_f32<<<4, 128>>>(b2, W3, uvec);

    // H2 = x1 = a0*n + (S·H1)*(1-n)    [SpMM #1]
    spmm_mix_h<<<M, 128>>>(rowptr, colS, valS, H1, out + 512, nvec, H2);

    // H1 = S·H2                        [SpMM #2]
    spmm_csr_h<<<M, 128>>>(rowptr, colS, valS, H2, H1);

    // A16 = S·H1                       [SpMM #3]
    spmm_csr_h<<<M, 128>>>(rowptr, colS, valS, H1, A16);

    // out[:, 0:512) = t2 @ W23 + e⊗u + d⊗b3
    gemm_f16<<<ggrid, 256, GEMM_SMEM>>>(A16, Wp[2], nullptr,
                                        ev, uvec, dv, b3,
                                        out, nullptr, 1024, M);
}

// round 9
// speedup vs baseline: 5.3102x; 1.0604x over previous
#include <cuda_runtime.h>
#include <cuda_fp16.h>
#include <cstdint>
#include <cstddef>

#define NN 50000
#define EE 1600000
#define DD 512

// ---------------------------------------------------------------------------
// Device scratch (no runtime alloc allowed)
// ---------------------------------------------------------------------------
__device__ __half g_A16[(size_t)NN * DD];
__device__ __half g_H1[(size_t)NN * DD];
__device__ __half g_H2[(size_t)NN * DD];
__device__ __half g_W16[(size_t)3 * DD * DD];
__device__ float  g_W23[(size_t)DD * DD];
__device__ float  g_uvec[DD];
// CSR scratch
__device__ int   g_cnt[NN];
__device__ int   g_rowptr[NN + 1];
__device__ int   g_cursor[NN];
__device__ int2  g_edge[EE];          // packed {col, val_bits}
__device__ float g_d[NN];
__device__ float g_e[NN];

// ---------------------------------------------------------------------------
// Helpers
// ---------------------------------------------------------------------------
__device__ __forceinline__ uint32_t smem_to_u32(const void* p) {
    uint32_t a;
    asm("{ .reg .u64 t; cvta.to.shared.u64 t, %1; cvt.u32.u64 %0, t; }" : "=r"(a) : "l"(p));
    return a;
}

__device__ __forceinline__ void cp16(uint32_t dst, const void* src, bool valid) {
    int sz = valid ? 16 : 0;
    asm volatile("cp.async.cg.shared.global [%0], [%1], 16, %2;"
                 :: "r"(dst), "l"(src), "r"(sz) : "memory");
}
#define CP_COMMIT() asm volatile("cp.async.commit_group;" ::: "memory")
#define CP_WAIT(n)  asm volatile("cp.async.wait_group %0;" :: "n"(n) : "memory")

__device__ __forceinline__ void mma_f16(float* d, const uint32_t* a, const uint32_t* b) {
    asm volatile("mma.sync.aligned.m16n8k16.row.col.f32.f16.f16.f32 "
                 "{%0,%1,%2,%3}, {%4,%5,%6,%7}, {%8,%9}, {%0,%1,%2,%3};"
                 : "+f"(d[0]), "+f"(d[1]), "+f"(d[2]), "+f"(d[3])
                 : "r"(a[0]), "r"(a[1]), "r"(a[2]), "r"(a[3]), "r"(b[0]), "r"(b[1]));
}

// ---------------------------------------------------------------------------
// GEMM CTA body (device function, dispatched from fused kernels)
// C[Mx512] = A16 @ B16^T + epilogue, fp16 mma, fp32 accum.
// ---------------------------------------------------------------------------
#define BK 32
#define RSTRIDE 20
#define TILE_WORDS (128 * RSTRIDE)
#define STAGE_WORDS (2 * TILE_WORDS)
#define GEMM_SMEM (2 * STAGE_WORDS * 4)   // 40960 bytes
#define NBY ((NN + 127) / 128)            // 391
#define G1  (4 * NBY)                     // gemm CTA count: 1564

__device__ __forceinline__ void gemm_load_stage(
    uint32_t sbase, int stage, const __half* A, const __half* B,
    int bm, int bn, int kc, int M, int tid)
{
    const uint32_t st = sbase + (uint32_t)stage * STAGE_WORDS * 4;
    const int r0 = tid >> 2;
    const int r1 = r0 + 64;
    const int j  = tid & 3;
    const uint32_t d0 = st + (uint32_t)(r0 * RSTRIDE + j * 4) * 4;
    const uint32_t d1 = st + (uint32_t)(r1 * RSTRIDE + j * 4) * 4;
    const size_t koff = (size_t)kc * BK + j * 8;
    const bool v0 = (bm + r0) < M;
    const bool v1 = (bm + r1) < M;

    cp16(d0,                  A + (size_t)(bm + r0) * DD + koff, v0);
    cp16(d1,                  A + (size_t)(bm + r1) * DD + koff, v1);
    cp16(d0 + TILE_WORDS * 4, B + (size_t)(bn + r0) * DD + koff, true);
    cp16(d1 + TILE_WORDS * 4, B + (size_t)(bn + r1) * DD + koff, true);
}

__device__ void gemm_cta(
    int g, uint32_t* s,
    const __half* __restrict__ A, const __half* __restrict__ B,
    const float* __restrict__ bias,
    const float* __restrict__ rowE, const float* __restrict__ colU,
    const float* __restrict__ rowD, const float* __restrict__ colB3,
    float* __restrict__ C, __half* __restrict__ C16, int ldc, int M)
{
    const uint32_t sbase = smem_to_u32(s);
    const int tid  = threadIdx.x;
    const int warp = tid >> 5;
    const int lane = tid & 31;
    const int wm   = (warp & 1) * 64;
    const int wn   = (warp >> 1) * 32;
    const int grp  = lane >> 2;
    const int qd   = lane & 3;
    const int bm = (g >> 2) * 128;
    const int n0 = (g & 3) * 128;

    float acc[4][4][4];
    #pragma unroll
    for (int i = 0; i < 4; i++)
        #pragma unroll
        for (int j = 0; j < 4; j++)
            #pragma unroll
            for (int q = 0; q < 4; q++) acc[i][j][q] = 0.f;

    gemm_load_stage(sbase, 0, A, B, bm, n0, 0, M, tid);
    CP_COMMIT();

    #pragma unroll 1
    for (int kc = 0; kc < DD / BK; kc++) {
        if (kc + 1 < DD / BK) {
            gemm_load_stage(sbase, (kc + 1) & 1, A, B, bm, n0, kc + 1, M, tid);
            CP_COMMIT();
            CP_WAIT(1);
        } else {
            CP_WAIT(0);
        }
        __syncthreads();

        const uint32_t* As = s + (kc & 1) * STAGE_WORDS;
        const uint32_t* Bs = As + TILE_WORDS;

        #pragma unroll
        for (int ks = 0; ks < 2; ks++) {
            const int kw = ks * 8;
            uint32_t ah[4][4];
            #pragma unroll
            for (int mi = 0; mi < 4; mi++) {
                const int base = (wm + mi * 16 + grp) * RSTRIDE + kw + qd;
                ah[mi][0] = As[base];
                ah[mi][1] = As[base + 8 * RSTRIDE];
                ah[mi][2] = As[base + 4];
                ah[mi][3] = As[base + 8 * RSTRIDE + 4];
            }
            #pragma unroll
            for (int nj = 0; nj < 4; nj++) {
                const int base = (wn + nj * 8 + grp) * RSTRIDE + kw + qd;
                uint32_t bh[2];
                bh[0] = Bs[base];
                bh[1] = Bs[base + 4];
                #pragma unroll
                for (int mi = 0; mi < 4; mi++)
                    mma_f16(acc[mi][nj], ah[mi], bh);
            }
        }
        __syncthreads();
    }

    #pragma unroll
    for (int mi = 0; mi < 4; mi++) {
        const int gr = bm + wm + mi * 16 + grp;
        float e0 = 0.f, d0v = 0.f, e1 = 0.f, d1v = 0.f;
        if (rowE) {
            if (gr < M)     { e0 = rowE[gr];     d0v = rowD[gr]; }
            if (gr + 8 < M) { e1 = rowE[gr + 8]; d1v = rowD[gr + 8]; }
        }
        #pragma unroll
        for (int nj = 0; nj < 4; nj++) {
            const int gc = n0 + wn + nj * 8 + qd * 2;
            float2 add0, add1;
            if (rowE) {
                const float2 uu = *(const float2*)(colU + gc);
                const float2 b3 = *(const float2*)(colB3 + gc);
                add0 = make_float2(e0 * uu.x + d0v * b3.x, e0 * uu.y + d0v * b3.y);
                add1 = make_float2(e1 * uu.x + d1v * b3.x, e1 * uu.y + d1v * b3.y);
            } else {
                const float2 bz = *(const float2*)(bias + gc);
                add0 = bz; add1 = bz;
            }
            float2 o0 = {acc[mi][nj][0] + add0.x, acc[mi][nj][1] + add0.y};
            float2 o1 = {acc[mi][nj][2] + add1.x, acc[mi][nj][3] + add1.y};
            if (C16) {
                if (gr < M)
                    *(__half2*)(C16 + (size_t)gr * ldc + gc) = __float22half2_rn(o0);
                if (gr + 8 < M)
                    *(__half2*)(C16 + (size_t)(gr + 8) * ldc + gc) = __float22half2_rn(o1);
            } else {
                if (gr < M)     *(float2*)(C + (size_t)gr * ldc + gc) = o0;
                if (gr + 8 < M) *(float2*)(C + (size_t)(gr + 8) * ldc + gc) = o1;
            }
        }
    }
}

// ---------------------------------------------------------------------------
// Fused launches: GEMM CTAs + memory-side worker CTAs in one grid
// ---------------------------------------------------------------------------
// fusedA: gemm (a0) || hist_rows
__global__ void __launch_bounds__(256, 2) fusedA(
    const __half* __restrict__ A, const __half* __restrict__ B,
    const float* __restrict__ bias, float* __restrict__ C, int ldc, int M,
    const int* __restrict__ rows, int* __restrict__ cnt, int E)
{
    extern __shared__ uint32_t s[];
    if (blockIdx.x < G1) {
        gemm_cta(blockIdx.x, s, A, B, bias,
                 nullptr, nullptr, nullptr, nullptr, C, nullptr, ldc, M);
    } else {
        int e = (blockIdx.x - G1) * 256 + threadIdx.x;
        if (e < E) atomicAdd(&cnt[rows[e]], 1);
    }
}

// fusedB: gemm (H1, fp16 out) || scatter_edges
__global__ void __launch_bounds__(256, 2) fusedB(
    const __half* __restrict__ A, const __half* __restrict__ B,
    const float* __restrict__ bias, __half* __restrict__ C16, int ldc, int M,
    const int* __restrict__ rows, const int* __restrict__ cols,
    const float* __restrict__ vals, int* __restrict__ cursor,
    int2* __restrict__ edge, int E)
{
    extern __shared__ uint32_t s[];
    if (blockIdx.x < G1) {
        gemm_cta(blockIdx.x, s, A, B, bias,
                 nullptr, nullptr, nullptr, nullptr, nullptr, C16, ldc, M);
    } else {
        int e = (blockIdx.x - G1) * 256 + threadIdx.x;
        if (e < E) {
            int r = rows[e];
            int p = atomicAdd(&cursor[r], 1);
            edge[p] = make_int2(cols[e], __float_as_int(vals[e]));
        }
    }
}

// ---------------------------------------------------------------------------
// Scan (1 block)
// ---------------------------------------------------------------------------
__global__ void __launch_bounds__(1024) scan_rows(
    const int* __restrict__ cnt, int* __restrict__ row_ptr,
    int* __restrict__ cursor, int M, int E)
{
    __shared__ int sm[1024];
    const int tid = threadIdx.x;
    const int chunk = (M + 1023) >> 10;
    const int base = tid * chunk;

    int local = 0;
    for (int i = 0; i < chunk; i++) {
        int r = base + i;
        if (r < M) local += cnt[r];
    }
    sm[tid] = local;
    __syncthreads();
    for (int off = 1; off < 1024; off <<= 1) {
        int v = (tid >= off) ? sm[tid - off] : 0;
        __syncthreads();
        sm[tid] += v;
        __syncthreads();
    }
    int run = sm[tid] - local;
    for (int i = 0; i < chunk; i++) {
        int r = base + i;
        if (r < M) {
            row_ptr[r] = run;
            cursor[r]  = run;
            run += cnt[r];
        }
    }
    if (tid == 0) row_ptr[M] = E;
}

// ---------------------------------------------------------------------------
// fp16 CSR SpMM core (block-per-row, 128 thr x 4 features, fp32 accum)
// ---------------------------------------------------------------------------
__device__ __forceinline__ float4 spmm_row_acc_h(
    const int* __restrict__ row_ptr, const int2* __restrict__ edge,
    const __half* __restrict__ in, int r, int tid)
{
    const size_t off = (size_t)tid * 4;
    int e = row_ptr[r];
    const int end = row_ptr[r + 1];
    float4 acc = {0.f, 0.f, 0.f, 0.f};

    for (; e + 2 <= end; e += 2) {
        const int2 e0 = __ldg(edge + e);
        const int2 e1 = __ldg(edge + e + 1);
        const float v0 = __int_as_float(e0.y);
        const float v1 = __int_as_float(e1.y);
        const uint2 r0 = *(const uint2*)(in + (size_t)e0.x * DD + off);
        const uint2 r1 = *(const uint2*)(in + (size_t)e1.x * DD + off);
        const float2 a0 = __half22float2(*(const __half2*)&r0.x);
        const float2 a1 = __half22float2(*(const __half2*)&r0.y);
        const float2 b0 = __half22float2(*(const __half2*)&r1.x);
        const float2 b1 = __half22float2(*(const __half2*)&r1.y);
        acc.x = fmaf(v0, a0.x, acc.x); acc.y = fmaf(v0, a0.y, acc.y);
        acc.z = fmaf(v0, a1.x, acc.z); acc.w = fmaf(v0, a1.y, acc.w);
        acc.x = fmaf(v1, b0.x, acc.x); acc.y = fmaf(v1, b0.y, acc.y);
        acc.z = fmaf(v1, b1.x, acc.z); acc.w = fmaf(v1, b1.y, acc.w);
    }
    if (e < end) {
        const int2 e0 = __ldg(edge + e);
        const float v0 = __int_as_float(e0.y);
        const uint2 r0 = *(const uint2*)(in + (size_t)e0.x * DD + off);
        const float2 a0 = __half22float2(*(const __half2*)&r0.x);
        const float2 a1 = __half22float2(*(const __half2*)&r0.y);
        acc.x = fmaf(v0, a0.x, acc.x); acc.y = fmaf(v0, a0.y, acc.y);
        acc.z = fmaf(v0, a1.x, acc.z); acc.w = fmaf(v0, a1.y, acc.w);
    }
    return acc;
}

__device__ __forceinline__ void store_h4(__half* dst, float4 v) {
    uint2 o;
    *(__half2*)&o.x = __float22half2_rn(make_float2(v.x, v.y));
    *(__half2*)&o.y = __float22half2_rn(make_float2(v.z, v.w));
    *(uint2*)dst = o;
}

// fusedC: spmm_mix || rowsum_d
__global__ void __launch_bounds__(128) fusedC(
    const int* __restrict__ row_ptr, const int2* __restrict__ edge,
    const __half* __restrict__ in,
    const float* __restrict__ a0, const float* __restrict__ nvec,
    __half* __restrict__ x1, float* __restrict__ dvec, int M)
{
    const int bid = blockIdx.x;
    const int tid = threadIdx.x;
    if (bid < M) {
        float4 acc = spmm_row_acc_h(row_ptr, edge, in, bid, tid);
        const float nv = nvec[bid];
        const float om = 1.f - nv;
        const float4 a = *(const float4*)(a0 + (size_t)bid * 1024 + (size_t)tid * 4);
        float4 o;
        o.x = a.x * nv + acc.x * om;
        o.y = a.y * nv + acc.y * om;
        o.z = a.z * nv + acc.z * om;
        o.w = a.w * nv + acc.w * om;
        store_h4(x1 + (size_t)bid * DD + (size_t)tid * 4, o);
    } else {
        const int r = (bid - M) * 4 + (tid >> 5);
        if (r >= M) return;
        const int lane = tid & 31;
        float acc = 0.f;
        for (int e = row_ptr[r] + lane; e < row_ptr[r + 1]; e += 32)
            acc += __int_as_float(__ldg(&edge[e].y));
        #pragma unroll
        for (int o = 16; o; o >>= 1) acc += __shfl_down_sync(0xffffffffu, acc, o);
        if (lane == 0) dvec[r] = acc;
    }
}

// fusedD: spmm (H1 = S·H2) || spmv_e || uvec
__global__ void __launch_bounds__(128) fusedD(
    const int* __restrict__ row_ptr, const int2* __restrict__ edge,
    const __half* __restrict__ in, __half* __restrict__ out,
    const float* __restrict__ dvec, float* __restrict__ evec,
    const float* __restrict__ b2, const float* __restrict__ W3,
    float* __restrict__ u, int M)
{
    const int bid = blockIdx.x;
    const int tid = threadIdx.x;
    const int UB = M + (M + 3) / 4;
    if (bid < M) {
        float4 acc = spmm_row_acc_h(row_ptr, edge, in, bid, tid);
        store_h4(out + (size_t)bid * DD + (size_t)tid * 4, acc);
    } else if (bid < UB) {
        const int r = (bid - M) * 4 + (tid >> 5);
        if (r >= M) return;
        const int lane = tid & 31;
        float acc = 0.f;
        for (int e = row_ptr[r] + lane; e < row_ptr[r + 1]; e += 32) {
            const int2 ev2 = __ldg(edge + e);
            acc = fmaf(__int_as_float(ev2.y), dvec[ev2.x], acc);
        }
        #pragma unroll
        for (int o = 16; o; o >>= 1) acc += __shfl_down_sync(0xffffffffu, acc, o);
        if (lane == 0) evec[r] = acc;
    } else {
        const int n = (bid - UB) * 128 + tid;
        float acc = 0.f;
        #pragma unroll 8
        for (int j = 0; j < DD; j++)
            acc = fmaf(b2[j], W3[j * DD + n], acc);
        u[n] = acc;
    }
}

// Plain fp16 SpMM (#3)
__global__ void __launch_bounds__(128) spmm_csr_h(
    const int* __restrict__ row_ptr, const int2* __restrict__ edge,
    const __half* __restrict__ in, __half* __restrict__ out)
{
    float4 acc = spmm_row_acc_h(row_ptr, edge, in, blockIdx.x, threadIdx.x);
    store_h4(out + (size_t)blockIdx.x * DD + (size_t)threadIdx.x * 4, acc);
}

// Final GEMM (standalone)
__global__ void __launch_bounds__(256, 2) gemm_final(
    const __half* __restrict__ A, const __half* __restrict__ B,
    const float* __restrict__ rowE, const float* __restrict__ colU,
    const float* __restrict__ rowD, const float* __restrict__ colB3,
    float* __restrict__ C, int ldc, int M)
{
    extern __shared__ uint32_t s[];
    gemm_cta(blockIdx.x, s, A, B, nullptr, rowE, colU, rowD, colB3,
             C, nullptr, ldc, M);
}

// ---------------------------------------------------------------------------
// W23 = W2@W3 (fp32) ; prep_all: weight casts + input split + cnt zero
// ---------------------------------------------------------------------------
__global__ void gemm512_f32(const float* __restrict__ A, const float* __restrict__ B,
                            float* __restrict__ C)
{
    const int n = blockIdx.x * 128 + threadIdx.x;
    const int k = blockIdx.y;
    float acc = 0.f;
    #pragma unroll 8
    for (int j = 0; j < DD; j++)
        acc = fmaf(A[k * DD + j], B[j * DD + n], acc);
    C[k * DD + n] = acc;
}

#define WN (3 * DD * DD)
__global__ void prep_all(const float* __restrict__ Lin1, const float* __restrict__ W1,
                         const float* __restrict__ W23, const float* __restrict__ A1,
                         __half* __restrict__ W16, __half* __restrict__ A16,
                         int* __restrict__ cnt, int M)
{
    size_t i = (size_t)blockIdx.x * blockDim.x + threadIdx.x;
    if (i < WN) {
        int w = (int)(i / (DD * DD));
        int j = (int)(i % (DD * DD));
        int n = j >> 9, k = j & 511;
        const float* src = (w == 0) ? Lin1 : (w == 1) ? W1 : W23;
        W16[i] = __float2half_rn(src[k * DD + n]);
        return;
    }
    size_t j = i - WN;
    if (j < (size_t)M * DD) {
        size_t r = j >> 9;
        int c = (int)(j & 511);
        A16[j] = __float2half_rn(A1[r * 513 + 1 + c]);
        return;
    }
    size_t z = j - (size_t)M * DD;
    if (z < (size_t)M) cnt[z] = 0;
}

// ---------------------------------------------------------------------------
// Host driver
// ---------------------------------------------------------------------------
extern "C" void kernel_launch(void* const* d_in, const int* in_sizes, int n_in,
                              void* d_out, int out_size)
{
    const float* A1       = (const float*)d_in[0];
    const int*   adj_rows = (const int*)  d_in[1];
    const int*   adj_cols = (const int*)  d_in[2];
    const float* adj_vals = (const float*)d_in[3];
    const float* Lin1     = (const float*)d_in[4];
    const float* Lin1_b   = (const float*)d_in[5];
    const float* nvec     = (const float*)d_in[6];
    const float* W1       = (const float*)d_in[7];
    const float* b1       = (const float*)d_in[8];
    const float* W2       = (const float*)d_in[9];
    const float* b2       = (const float*)d_in[10];
    const float* W3       = (const float*)d_in[11];
    const float* b3       = (const float*)d_in[12];
    float* out = (float*)d_out;

    const int M = in_sizes[6];   // 50000
    const int E = in_sizes[1];   // 1,600,000

    __half *A16, *H1, *H2, *W16;
    float *W23, *uvec, *dv, *ev;
    int *cnt, *rowptr, *cursor;
    int2 *edge;
    cudaGetSymbolAddress((void**)&A16, g_A16);
    cudaGetSymbolAddress((void**)&H1,  g_H1);
    cudaGetSymbolAddress((void**)&H2,  g_H2);
    cudaGetSymbolAddress((void**)&W16, g_W16);
    cudaGetSymbolAddress((void**)&W23,  g_W23);
    cudaGetSymbolAddress((void**)&uvec, g_uvec);
    cudaGetSymbolAddress((void**)&dv,   g_d);
    cudaGetSymbolAddress((void**)&ev,   g_e);
    cudaGetSymbolAddress((void**)&cnt,    g_cnt);
    cudaGetSymbolAddress((void**)&rowptr, g_rowptr);
    cudaGetSymbolAddress((void**)&cursor, g_cursor);
    cudaGetSymbolAddress((void**)&edge,   g_edge);

    cudaFuncSetAttribute(fusedA,     cudaFuncAttributeMaxDynamicSharedMemorySize, GEMM_SMEM);
    cudaFuncSetAttribute(fusedB,     cudaFuncAttributeMaxDynamicSharedMemorySize, GEMM_SMEM);
    cudaFuncSetAttribute(gemm_final, cudaFuncAttributeMaxDynamicSharedMemorySize, GEMM_SMEM);

    __half* Wp[3] = {W16, W16 + (size_t)DD * DD, W16 + (size_t)2 * DD * DD};

    const int eblk = (E + 255) / 256;
    const size_t prep_total = (size_t)WN + (size_t)M * DD + M;
    const int prep_blocks = (int)((prep_total + 255) / 256);
    const int rsB = (M + 3) / 4;                  // rowsum/spmv blocks (4 rows each)

    // 1. W23 = W2 @ W3
    gemm512_f32<<<dim3(4, DD), 128>>>(W2, W3, W23);
    // 2. weight casts + input split + cnt zero
    prep_all<<<prep_blocks, 256>>>(Lin1, W1, W23, A1, W16, A16, cnt, M);
    // 3. a0 GEMM || hist
    fusedA<<<G1 + eblk, 256, GEMM_SMEM>>>(A16, Wp[0], Lin1_b, out + 512, 1024, M,
                                          adj_rows, cnt, E);
    // 4. scan
    scan_rows<<<1, 1024>>>(cnt, rowptr, cursor, M, E);
    // 5. H1 GEMM || scatter
    fusedB<<<G1 + eblk, 256, GEMM_SMEM>>>(A16, Wp[1], b1, H1, DD, M,
                                          adj_rows, adj_cols, adj_vals, cursor, edge, E);
    // 6. spmm_mix || rowsum_d
    fusedC<<<M + rsB, 128>>>(rowptr, edge, H1, out + 512, nvec, H2, dv, M);
    // 7. spmm #2 || spmv_e || uvec
    fusedD<<<M + rsB + 4, 128>>>(rowptr, edge, H2, H1, dv, ev, b2, W3, uvec, M);
    // 8. spmm #3
    spmm_csr_h<<<M, 128>>>(rowptr, edge, H1, A16);
    // 9. final GEMM: out[:,0:512) = t2 @ W23 + e⊗u + d⊗b3
    gemm_final<<<G1, 256, GEMM_SMEM>>>(A16, Wp[2], ev, uvec, dv, b3, out, 1024, M);
}

// round 10
// speedup vs baseline: 5.6692x; 1.0676x over previous
#include <cuda_runtime.h>
#include <cuda_fp16.h>
#include <cstdint>
#include <cstddef>

#define NN 50000
#define EE 1600000
#define DD 512

// ---------------------------------------------------------------------------
// Device scratch (no runtime alloc allowed)
// ---------------------------------------------------------------------------
__device__ __half g_A16[(size_t)NN * DD];
__device__ __half g_H1[(size_t)NN * DD];
__device__ __half g_H2[(size_t)NN * DD];
__device__ __half g_W16[(size_t)3 * DD * DD];
__device__ float  g_W23[(size_t)DD * DD];
__device__ float  g_uvec[DD];
// CSR scratch
__device__ int   g_cnt[NN];
__device__ int   g_rowptr[NN + 1];
__device__ int   g_cursor[NN];
__device__ int   g_partial[256];
__device__ int2  g_edge[EE];          // packed {col, val_bits}
__device__ float g_d[NN];
__device__ float g_e[NN];

// ---------------------------------------------------------------------------
// Helpers
// ---------------------------------------------------------------------------
__device__ __forceinline__ uint32_t smem_to_u32(const void* p) {
    uint32_t a;
    asm("{ .reg .u64 t; cvta.to.shared.u64 t, %1; cvt.u32.u64 %0, t; }" : "=r"(a) : "l"(p));
    return a;
}

__device__ __forceinline__ void cp16(uint32_t dst, const void* src, bool valid) {
    int sz = valid ? 16 : 0;
    asm volatile("cp.async.cg.shared.global [%0], [%1], 16, %2;"
                 :: "r"(dst), "l"(src), "r"(sz) : "memory");
}
#define CP_COMMIT() asm volatile("cp.async.commit_group;" ::: "memory")
#define CP_WAIT(n)  asm volatile("cp.async.wait_group %0;" :: "n"(n) : "memory")

__device__ __forceinline__ void mma_f16(float* d, const uint32_t* a, const uint32_t* b) {
    asm volatile("mma.sync.aligned.m16n8k16.row.col.f32.f16.f16.f32 "
                 "{%0,%1,%2,%3}, {%4,%5,%6,%7}, {%8,%9}, {%0,%1,%2,%3};"
                 : "+f"(d[0]), "+f"(d[1]), "+f"(d[2]), "+f"(d[3])
                 : "r"(a[0]), "r"(a[1]), "r"(a[2]), "r"(a[3]), "r"(b[0]), "r"(b[1]));
}

// ---------------------------------------------------------------------------
// GEMM CTA body (device function, dispatched from fused kernels)
// ---------------------------------------------------------------------------
#define BK 32
#define RSTRIDE 20
#define TILE_WORDS (128 * RSTRIDE)
#define STAGE_WORDS (2 * TILE_WORDS)
#define GEMM_SMEM (2 * STAGE_WORDS * 4)   // 40960 bytes
#define NBY ((NN + 127) / 128)            // 391
#define G1  (4 * NBY)                     // gemm CTA count: 1564

__device__ __forceinline__ void gemm_load_stage(
    uint32_t sbase, int stage, const __half* A, const __half* B,
    int bm, int bn, int kc, int M, int tid)
{
    const uint32_t st = sbase + (uint32_t)stage * STAGE_WORDS * 4;
    const int r0 = tid >> 2;
    const int r1 = r0 + 64;
    const int j  = tid & 3;
    const uint32_t d0 = st + (uint32_t)(r0 * RSTRIDE + j * 4) * 4;
    const uint32_t d1 = st + (uint32_t)(r1 * RSTRIDE + j * 4) * 4;
    const size_t koff = (size_t)kc * BK + j * 8;
    const bool v0 = (bm + r0) < M;
    const bool v1 = (bm + r1) < M;

    cp16(d0,                  A + (size_t)(bm + r0) * DD + koff, v0);
    cp16(d1,                  A + (size_t)(bm + r1) * DD + koff, v1);
    cp16(d0 + TILE_WORDS * 4, B + (size_t)(bn + r0) * DD + koff, true);
    cp16(d1 + TILE_WORDS * 4, B + (size_t)(bn + r1) * DD + koff, true);
}

__device__ void gemm_cta(
    int g, uint32_t* s,
    const __half* __restrict__ A, const __half* __restrict__ B,
    const float* __restrict__ bias,
    const float* __restrict__ rowE, const float* __restrict__ colU,
    const float* __restrict__ rowD, const float* __restrict__ colB3,
    float* __restrict__ C, __half* __restrict__ C16, int ldc, int M)
{
    const uint32_t sbase = smem_to_u32(s);
    const int tid  = threadIdx.x;
    const int warp = tid >> 5;
    const int lane = tid & 31;
    const int wm   = (warp & 1) * 64;
    const int wn   = (warp >> 1) * 32;
    const int grp  = lane >> 2;
    const int qd   = lane & 3;
    const int bm = (g >> 2) * 128;
    const int n0 = (g & 3) * 128;

    float acc[4][4][4];
    #pragma unroll
    for (int i = 0; i < 4; i++)
        #pragma unroll
        for (int j = 0; j < 4; j++)
            #pragma unroll
            for (int q = 0; q < 4; q++) acc[i][j][q] = 0.f;

    gemm_load_stage(sbase, 0, A, B, bm, n0, 0, M, tid);
    CP_COMMIT();

    #pragma unroll 1
    for (int kc = 0; kc < DD / BK; kc++) {
        if (kc + 1 < DD / BK) {
            gemm_load_stage(sbase, (kc + 1) & 1, A, B, bm, n0, kc + 1, M, tid);
            CP_COMMIT();
            CP_WAIT(1);
        } else {
            CP_WAIT(0);
        }
        __syncthreads();

        const uint32_t* As = s + (kc & 1) * STAGE_WORDS;
        const uint32_t* Bs = As + TILE_WORDS;

        #pragma unroll
        for (int ks = 0; ks < 2; ks++) {
            const int kw = ks * 8;
            uint32_t ah[4][4];
            #pragma unroll
            for (int mi = 0; mi < 4; mi++) {
                const int base = (wm + mi * 16 + grp) * RSTRIDE + kw + qd;
                ah[mi][0] = As[base];
                ah[mi][1] = As[base + 8 * RSTRIDE];
                ah[mi][2] = As[base + 4];
                ah[mi][3] = As[base + 8 * RSTRIDE + 4];
            }
            #pragma unroll
            for (int nj = 0; nj < 4; nj++) {
                const int base = (wn + nj * 8 + grp) * RSTRIDE + kw + qd;
                uint32_t bh[2];
                bh[0] = Bs[base];
                bh[1] = Bs[base + 4];
                #pragma unroll
                for (int mi = 0; mi < 4; mi++)
                    mma_f16(acc[mi][nj], ah[mi], bh);
            }
        }
        __syncthreads();
    }

    #pragma unroll
    for (int mi = 0; mi < 4; mi++) {
        const int gr = bm + wm + mi * 16 + grp;
        float e0 = 0.f, d0v = 0.f, e1 = 0.f, d1v = 0.f;
        if (rowE) {
            if (gr < M)     { e0 = rowE[gr];     d0v = rowD[gr]; }
            if (gr + 8 < M) { e1 = rowE[gr + 8]; d1v = rowD[gr + 8]; }
        }
        #pragma unroll
        for (int nj = 0; nj < 4; nj++) {
            const int gc = n0 + wn + nj * 8 + qd * 2;
            float2 add0, add1;
            if (rowE) {
                const float2 uu = *(const float2*)(colU + gc);
                const float2 b3 = *(const float2*)(colB3 + gc);
                add0 = make_float2(e0 * uu.x + d0v * b3.x, e0 * uu.y + d0v * b3.y);
                add1 = make_float2(e1 * uu.x + d1v * b3.x, e1 * uu.y + d1v * b3.y);
            } else {
                const float2 bz = *(const float2*)(bias + gc);
                add0 = bz; add1 = bz;
            }
            float2 o0 = {acc[mi][nj][0] + add0.x, acc[mi][nj][1] + add0.y};
            float2 o1 = {acc[mi][nj][2] + add1.x, acc[mi][nj][3] + add1.y};
            if (C16) {
                if (gr < M)
                    *(__half2*)(C16 + (size_t)gr * ldc + gc) = __float22half2_rn(o0);
                if (gr + 8 < M)
                    *(__half2*)(C16 + (size_t)(gr + 8) * ldc + gc) = __float22half2_rn(o1);
            } else {
                if (gr < M)     *(float2*)(C + (size_t)gr * ldc + gc) = o0;
                if (gr + 8 < M) *(float2*)(C + (size_t)(gr + 8) * ldc + gc) = o1;
            }
        }
    }
}

// ---------------------------------------------------------------------------
// Fused launches: GEMM CTAs + memory-side worker CTAs in one grid
// ---------------------------------------------------------------------------
__global__ void __launch_bounds__(256, 2) fusedA(
    const __half* __restrict__ A, const __half* __restrict__ B,
    const float* __restrict__ bias, float* __restrict__ C, int ldc, int M,
    const int* __restrict__ rows, int* __restrict__ cnt, int E)
{
    extern __shared__ uint32_t s[];
    if (blockIdx.x < G1) {
        gemm_cta(blockIdx.x, s, A, B, bias,
                 nullptr, nullptr, nullptr, nullptr, C, nullptr, ldc, M);
    } else {
        int e = (blockIdx.x - G1) * 256 + threadIdx.x;
        if (e < E) atomicAdd(&cnt[rows[e]], 1);
    }
}

__global__ void __launch_bounds__(256, 2) fusedB(
    const __half* __restrict__ A, const __half* __restrict__ B,
    const float* __restrict__ bias, __half* __restrict__ C16, int ldc, int M,
    const int* __restrict__ rows, const int* __restrict__ cols,
    const float* __restrict__ vals, int* __restrict__ cursor,
    int2* __restrict__ edge, int E)
{
    extern __shared__ uint32_t s[];
    if (blockIdx.x < G1) {
        gemm_cta(blockIdx.x, s, A, B, bias,
                 nullptr, nullptr, nullptr, nullptr, nullptr, C16, ldc, M);
    } else {
        int e = (blockIdx.x - G1) * 256 + threadIdx.x;
        if (e < E) {
            int r = rows[e];
            int p = atomicAdd(&cursor[r], 1);
            edge[p] = make_int2(cols[e], __float_as_int(vals[e]));
        }
    }
}

// ---------------------------------------------------------------------------
// 3-phase parallel scan (replaces single-block scan_rows: was 73.6 us)
// ---------------------------------------------------------------------------
#define SCB 256

// Phase 1: block-local exclusive scan of cnt -> rowptr (unoffset), totals -> partial
__global__ void __launch_bounds__(SCB) scan_part(
    const int* __restrict__ cnt, int* __restrict__ row_ptr,
    int* __restrict__ partial, int M)
{
    __shared__ int sm[SCB];
    const int tid = threadIdx.x;
    const int i = blockIdx.x * SCB + tid;
    int v = (i < M) ? cnt[i] : 0;
    sm[tid] = v;
    __syncthreads();
    #pragma unroll
    for (int off = 1; off < SCB; off <<= 1) {
        int t = (tid >= off) ? sm[tid - off] : 0;
        __syncthreads();
        sm[tid] += t;
        __syncthreads();
    }
    if (i < M) row_ptr[i] = sm[tid] - v;            // exclusive, block-local
    if (tid == SCB - 1) partial[blockIdx.x] = sm[tid];
}

// Phase 2: single block scans the per-block totals (exclusive)
__global__ void __launch_bounds__(256) scan_top(int* __restrict__ partial, int nblk)
{
    __shared__ int sm[256];
    const int tid = threadIdx.x;
    int v = (tid < nblk) ? partial[tid] : 0;
    sm[tid] = v;
    __syncthreads();
    #pragma unroll
    for (int off = 1; off < 256; off <<= 1) {
        int t = (tid >= off) ? sm[tid - off] : 0;
        __syncthreads();
        sm[tid] += t;
        __syncthreads();
    }
    if (tid < nblk) partial[tid] = sm[tid] - v;     // exclusive
}

// Phase 3: add block offsets; emit final rowptr + cursor
__global__ void __launch_bounds__(SCB) scan_add(
    int* __restrict__ row_ptr, int* __restrict__ cursor,
    const int* __restrict__ partial, int M, int E)
{
    const int i = blockIdx.x * SCB + threadIdx.x;
    if (i < M) {
        int v = row_ptr[i] + partial[blockIdx.x];
        row_ptr[i] = v;
        cursor[i]  = v;
    }
    if (i == 0) row_ptr[M] = E;
}

// ---------------------------------------------------------------------------
// fp16 CSR SpMM core (block-per-row, 128 thr x 4 features, fp32 accum)
// ---------------------------------------------------------------------------
__device__ __forceinline__ float4 spmm_row_acc_h(
    const int* __restrict__ row_ptr, const int2* __restrict__ edge,
    const __half* __restrict__ in, int r, int tid)
{
    const size_t off = (size_t)tid * 4;
    int e = row_ptr[r];
    const int end = row_ptr[r + 1];
    float4 acc = {0.f, 0.f, 0.f, 0.f};

    for (; e + 2 <= end; e += 2) {
        const int2 e0 = __ldg(edge + e);
        const int2 e1 = __ldg(edge + e + 1);
        const float v0 = __int_as_float(e0.y);
        const float v1 = __int_as_float(e1.y);
        const uint2 r0 = *(const uint2*)(in + (size_t)e0.x * DD + off);
        const uint2 r1 = *(const uint2*)(in + (size_t)e1.x * DD + off);
        const float2 a0 = __half22float2(*(const __half2*)&r0.x);
        const float2 a1 = __half22float2(*(const __half2*)&r0.y);
        const float2 b0 = __half22float2(*(const __half2*)&r1.x);
        const float2 b1 = __half22float2(*(const __half2*)&r1.y);
        acc.x = fmaf(v0, a0.x, acc.x); acc.y = fmaf(v0, a0.y, acc.y);
        acc.z = fmaf(v0, a1.x, acc.z); acc.w = fmaf(v0, a1.y, acc.w);
        acc.x = fmaf(v1, b0.x, acc.x); acc.y = fmaf(v1, b0.y, acc.y);
        acc.z = fmaf(v1, b1.x, acc.z); acc.w = fmaf(v1, b1.y, acc.w);
    }
    if (e < end) {
        const int2 e0 = __ldg(edge + e);
        const float v0 = __int_as_float(e0.y);
        const uint2 r0 = *(const uint2*)(in + (size_t)e0.x * DD + off);
        const float2 a0 = __half22float2(*(const __half2*)&r0.x);
        const float2 a1 = __half22float2(*(const __half2*)&r0.y);
        acc.x = fmaf(v0, a0.x, acc.x); acc.y = fmaf(v0, a0.y, acc.y);
        acc.z = fmaf(v0, a1.x, acc.z); acc.w = fmaf(v0, a1.y, acc.w);
    }
    return acc;
}

__device__ __forceinline__ void store_h4(__half* dst, float4 v) {
    uint2 o;
    *(__half2*)&o.x = __float22half2_rn(make_float2(v.x, v.y));
    *(__half2*)&o.y = __float22half2_rn(make_float2(v.z, v.w));
    *(uint2*)dst = o;
}

// fusedC: spmm_mix || rowsum_d
__global__ void __launch_bounds__(128) fusedC(
    const int* __restrict__ row_ptr, const int2* __restrict__ edge,
    const __half* __restrict__ in,
    const float* __restrict__ a0, const float* __restrict__ nvec,
    __half* __restrict__ x1, float* __restrict__ dvec, int M)
{
    const int bid = blockIdx.x;
    const int tid = threadIdx.x;
    if (bid < M) {
        float4 acc = spmm_row_acc_h(row_ptr, edge, in, bid, tid);
        const float nv = nvec[bid];
        const float om = 1.f - nv;
        const float4 a = *(const float4*)(a0 + (size_t)bid * 1024 + (size_t)tid * 4);
        float4 o;
        o.x = a.x * nv + acc.x * om;
        o.y = a.y * nv + acc.y * om;
        o.z = a.z * nv + acc.z * om;
        o.w = a.w * nv + acc.w * om;
        store_h4(x1 + (size_t)bid * DD + (size_t)tid * 4, o);
    } else {
        const int r = (bid - M) * 4 + (tid >> 5);
        if (r >= M) return;
        const int lane = tid & 31;
        float acc = 0.f;
        for (int e = row_ptr[r] + lane; e < row_ptr[r + 1]; e += 32)
            acc += __int_as_float(__ldg(&edge[e].y));
        #pragma unroll
        for (int o = 16; o; o >>= 1) acc += __shfl_down_sync(0xffffffffu, acc, o);
        if (lane == 0) dvec[r] = acc;
    }
}

// fusedD: spmm (H1 = S·H2) || spmv_e || uvec
__global__ void __launch_bounds__(128) fusedD(
    const int* __restrict__ row_ptr, const int2* __restrict__ edge,
    const __half* __restrict__ in, __half* __restrict__ out,
    const float* __restrict__ dvec, float* __restrict__ evec,
    const float* __restrict__ b2, const float* __restrict__ W3,
    float* __restrict__ u, int M)
{
    const int bid = blockIdx.x;
    const int tid = threadIdx.x;
    const int UB = M + (M + 3) / 4;
    if (bid < M) {
        float4 acc = spmm_row_acc_h(row_ptr, edge, in, bid, tid);
        store_h4(out + (size_t)bid * DD + (size_t)tid * 4, acc);
    } else if (bid < UB) {
        const int r = (bid - M) * 4 + (tid >> 5);
        if (r >= M) return;
        const int lane = tid & 31;
        float acc = 0.f;
        for (int e = row_ptr[r] + lane; e < row_ptr[r + 1]; e += 32) {
            const int2 ev2 = __ldg(edge + e);
            acc = fmaf(__int_as_float(ev2.y), dvec[ev2.x], acc);
        }
        #pragma unroll
        for (int o = 16; o; o >>= 1) acc += __shfl_down_sync(0xffffffffu, acc, o);
        if (lane == 0) evec[r] = acc;
    } else {
        const int n = (bid - UB) * 128 + tid;
        float acc = 0.f;
        #pragma unroll 8
        for (int j = 0; j < DD; j++)
            acc = fmaf(b2[j], W3[j * DD + n], acc);
        u[n] = acc;
    }
}

// Plain fp16 SpMM (#3)
__global__ void __launch_bounds__(128) spmm_csr_h(
    const int* __restrict__ row_ptr, const int2* __restrict__ edge,
    const __half* __restrict__ in, __half* __restrict__ out)
{
    float4 acc = spmm_row_acc_h(row_ptr, edge, in, blockIdx.x, threadIdx.x);
    store_h4(out + (size_t)blockIdx.x * DD + (size_t)threadIdx.x * 4, acc);
}

// Final GEMM (standalone)
__global__ void __launch_bounds__(256, 2) gemm_final(
    const __half* __restrict__ A, const __half* __restrict__ B,
    const float* __restrict__ rowE, const float* __restrict__ colU,
    const float* __restrict__ rowD, const float* __restrict__ colB3,
    float* __restrict__ C, int ldc, int M)
{
    extern __shared__ uint32_t s[];
    gemm_cta(blockIdx.x, s, A, B, nullptr, rowE, colU, rowD, colB3,
             C, nullptr, ldc, M);
}

// ---------------------------------------------------------------------------
// W23 = W2@W3 (fp32) ; prep_all: weight casts + input split + cnt zero
// ---------------------------------------------------------------------------
__global__ void gemm512_f32(const float* __restrict__ A, const float* __restrict__ B,
                            float* __restrict__ C)
{
    const int n = blockIdx.x * 128 + threadIdx.x;
    const int k = blockIdx.y;
    float acc = 0.f;
    #pragma unroll 8
    for (int j = 0; j < DD; j++)
        acc = fmaf(A[k * DD + j], B[j * DD + n], acc);
    C[k * DD + n] = acc;
}

#define WN (3 * DD * DD)
__global__ void prep_all(const float* __restrict__ Lin1, const float* __restrict__ W1,
                         const float* __restrict__ W23, const float* __restrict__ A1,
                         __half* __restrict__ W16, __half* __restrict__ A16,
                         int* __restrict__ cnt, int M)
{
    size_t i = (size_t)blockIdx.x * blockDim.x + threadIdx.x;
    if (i < WN) {
        int w = (int)(i / (DD * DD));
        int j = (int)(i % (DD * DD));
        int n = j >> 9, k = j & 511;
        const float* src = (w == 0) ? Lin1 : (w == 1) ? W1 : W23;
        W16[i] = __float2half_rn(src[k * DD + n]);
        return;
    }
    size_t j = i - WN;
    if (j < (size_t)M * DD) {
        size_t r = j >> 9;
        int c = (int)(j & 511);
        A16[j] = __float2half_rn(A1[r * 513 + 1 + c]);
        return;
    }
    size_t z = j - (size_t)M * DD;
    if (z < (size_t)M) cnt[z] = 0;
}

// ---------------------------------------------------------------------------
// Host driver
// ---------------------------------------------------------------------------
extern "C" void kernel_launch(void* const* d_in, const int* in_sizes, int n_in,
                              void* d_out, int out_size)
{
    const float* A1       = (const float*)d_in[0];
    const int*   adj_rows = (const int*)  d_in[1];
    const int*   adj_cols = (const int*)  d_in[2];
    const float* adj_vals = (const float*)d_in[3];
    const float* Lin1     = (const float*)d_in[4];
    const float* Lin1_b   = (const float*)d_in[5];
    const float* nvec     = (const float*)d_in[6];
    const float* W1       = (const float*)d_in[7];
    const float* b1       = (const float*)d_in[8];
    const float* W2       = (const float*)d_in[9];
    const float* b2       = (const float*)d_in[10];
    const float* W3       = (const float*)d_in[11];
    const float* b3       = (const float*)d_in[12];
    float* out = (float*)d_out;

    const int M = in_sizes[6];   // 50000
    const int E = in_sizes[1];   // 1,600,000

    __half *A16, *H1, *H2, *W16;
    float *W23, *uvec, *dv, *ev;
    int *cnt, *rowptr, *cursor, *partial;
    int2 *edge;
    cudaGetSymbolAddress((void**)&A16, g_A16);
    cudaGetSymbolAddress((void**)&H1,  g_H1);
    cudaGetSymbolAddress((void**)&H2,  g_H2);
    cudaGetSymbolAddress((void**)&W16, g_W16);
    cudaGetSymbolAddress((void**)&W23,  g_W23);
    cudaGetSymbolAddress((void**)&uvec, g_uvec);
    cudaGetSymbolAddress((void**)&dv,   g_d);
    cudaGetSymbolAddress((void**)&ev,   g_e);
    cudaGetSymbolAddress((void**)&cnt,     g_cnt);
    cudaGetSymbolAddress((void**)&rowptr,  g_rowptr);
    cudaGetSymbolAddress((void**)&cursor,  g_cursor);
    cudaGetSymbolAddress((void**)&partial, g_partial);
    cudaGetSymbolAddress((void**)&edge,    g_edge);

    cudaFuncSetAttribute(fusedA,     cudaFuncAttributeMaxDynamicSharedMemorySize, GEMM_SMEM);
    cudaFuncSetAttribute(fusedB,     cudaFuncAttributeMaxDynamicSharedMemorySize, GEMM_SMEM);
    cudaFuncSetAttribute(gemm_final, cudaFuncAttributeMaxDynamicSharedMemorySize, GEMM_SMEM);

    __half* Wp[3] = {W16, W16 + (size_t)DD * DD, W16 + (size_t)2 * DD * DD};

    const int eblk = (E + 255) / 256;
    const size_t prep_total = (size_t)WN + (size_t)M * DD + M;
    const int prep_blocks = (int)((prep_total + 255) / 256);
    const int rsB = (M + 3) / 4;
    const int scanB = (M + SCB - 1) / SCB;       // 196 blocks (<= 256)

    // 1. W23 = W2 @ W3
    gemm512_f32<<<dim3(4, DD), 128>>>(W2, W3, W23);
    // 2. weight casts + input split + cnt zero
    prep_all<<<prep_blocks, 256>>>(Lin1, W1, W23, A1, W16, A16, cnt, M);
    // 3. a0 GEMM || hist
    fusedA<<<G1 + eblk, 256, GEMM_SMEM>>>(A16, Wp[0], Lin1_b, out + 512, 1024, M,
                                          adj_rows, cnt, E);
    // 4-6. parallel scan (was: 73.6 us single-block; now ~12 us)
    scan_part<<<scanB, SCB>>>(cnt, rowptr, partial, M);
    scan_top<<<1, 256>>>(partial, scanB);
    scan_add<<<scanB, SCB>>>(rowptr, cursor, partial, M, E);
    // 7. H1 GEMM || scatter
    fusedB<<<G1 + eblk, 256, GEMM_SMEM>>>(A16, Wp[1], b1, H1, DD, M,
                                          adj_rows, adj_cols, adj_vals, cursor, edge, E);
    // 8. spmm_mix || rowsum_d
    fusedC<<<M + rsB, 128>>>(rowptr, edge, H1, out + 512, nvec, H2, dv, M);
    // 9. spmm #2 || spmv_e || uvec
    fusedD<<<M + rsB + 4, 128>>>(rowptr, edge, H2, H1, dv, ev, b2, W3, uvec, M);
    // 10. spmm #3
    spmm_csr_h<<<M, 128>>>(rowptr, edge, H1, A16);
    // 11. final GEMM: out[:,0:512) = t2 @ W23 + e⊗u + d⊗b3
    gemm_final<<<G1, 256, GEMM_SMEM>>>(A16, Wp[2], ev, uvec, dv, b3, out, 1024, M);
}

// round 11
// speedup vs baseline: 5.7614x; 1.0163x over previous
#include <cuda_runtime.h>
#include <cuda_fp16.h>
#include <cstdint>
#include <cstddef>

#define NN 50000
#define EE 1600000
#define DD 512

// ---------------------------------------------------------------------------
// Device scratch (no runtime alloc allowed)
// ---------------------------------------------------------------------------
__device__ __half g_A16[(size_t)NN * DD];
__device__ __half g_H1[(size_t)NN * DD];
__device__ __half g_H2[(size_t)NN * DD];
__device__ __half g_W16[(size_t)3 * DD * DD];
__device__ float  g_W23[(size_t)DD * DD];
__device__ float  g_uvec[DD];
// CSR scratch
__device__ int   g_cnt[NN];
__device__ int   g_rowptr[NN + 1];
__device__ int   g_cursor[NN];
__device__ int   g_partial[256];
__device__ int2  g_edge[EE];
__device__ float g_d[NN];
__device__ float g_e[NN];

// ---------------------------------------------------------------------------
// Helpers
// ---------------------------------------------------------------------------
__device__ __forceinline__ uint32_t smem_to_u32(const void* p) {
    uint32_t a;
    asm("{ .reg .u64 t; cvta.to.shared.u64 t, %1; cvt.u32.u64 %0, t; }" : "=r"(a) : "l"(p));
    return a;
}

__device__ __forceinline__ void cp16(uint32_t dst, const void* src, bool valid) {
    int sz = valid ? 16 : 0;
    asm volatile("cp.async.cg.shared.global [%0], [%1], 16, %2;"
                 :: "r"(dst), "l"(src), "r"(sz) : "memory");
}
#define CP_COMMIT() asm volatile("cp.async.commit_group;" ::: "memory")
#define CP_WAIT(n)  asm volatile("cp.async.wait_group %0;" :: "n"(n) : "memory")

__device__ __forceinline__ void mma_f16(float* d, const uint32_t* a, const uint32_t* b) {
    asm volatile("mma.sync.aligned.m16n8k16.row.col.f32.f16.f16.f32 "
                 "{%0,%1,%2,%3}, {%4,%5,%6,%7}, {%8,%9}, {%0,%1,%2,%3};"
                 : "+f"(d[0]), "+f"(d[1]), "+f"(d[2]), "+f"(d[3])
                 : "r"(a[0]), "r"(a[1]), "r"(a[2]), "r"(a[3]), "r"(b[0]), "r"(b[1]));
}

__device__ __forceinline__ void ldsm_x4(uint32_t* r, uint32_t addr) {
    asm volatile("ldmatrix.sync.aligned.m8n8.x4.shared.b16 {%0,%1,%2,%3}, [%4];"
                 : "=r"(r[0]), "=r"(r[1]), "=r"(r[2]), "=r"(r[3]) : "r"(addr));
}
__device__ __forceinline__ void ldsm_x2(uint32_t* r, uint32_t addr) {
    asm volatile("ldmatrix.sync.aligned.m8n8.x2.shared.b16 {%0,%1}, [%2];"
                 : "=r"(r[0]), "=r"(r[1]) : "r"(addr));
}

// ---------------------------------------------------------------------------
// GEMM CTA body: C[128x128 tile] = A16 @ B16^T + epilogue (fp16 mma, fp32 acc)
// Fragment loads via ldmatrix (8 LDSM vs 48 LDS per thread per kc-chunk).
// ---------------------------------------------------------------------------
#define BK 32
#define RSTRIDE 20
#define TILE_WORDS (128 * RSTRIDE)
#define STAGE_WORDS (2 * TILE_WORDS)
#define GEMM_SMEM (2 * STAGE_WORDS * 4)   // 40960 bytes
#define NBY ((NN + 127) / 128)            // 391
#define G1  (4 * NBY)                     // CTAs per N=512 GEMM: 1564

__device__ __forceinline__ void gemm_load_stage(
    uint32_t sbase, int stage, const __half* A, const __half* B,
    int bm, int bn, int kc, int M, int tid)
{
    const uint32_t st = sbase + (uint32_t)stage * STAGE_WORDS * 4;
    const int r0 = tid >> 2;
    const int r1 = r0 + 64;
    const int j  = tid & 3;
    const uint32_t d0 = st + (uint32_t)(r0 * RSTRIDE + j * 4) * 4;
    const uint32_t d1 = st + (uint32_t)(r1 * RSTRIDE + j * 4) * 4;
    const size_t koff = (size_t)kc * BK + j * 8;
    const bool v0 = (bm + r0) < M;
    const bool v1 = (bm + r1) < M;

    cp16(d0,                  A + (size_t)(bm + r0) * DD + koff, v0);
    cp16(d1,                  A + (size_t)(bm + r1) * DD + koff, v1);
    cp16(d0 + TILE_WORDS * 4, B + (size_t)(bn + r0) * DD + koff, true);
    cp16(d1 + TILE_WORDS * 4, B + (size_t)(bn + r1) * DD + koff, true);
}

__device__ void gemm_cta(
    int g, uint32_t* s,
    const __half* __restrict__ A, const __half* __restrict__ B,
    const float* __restrict__ bias,
    const float* __restrict__ rowE, const float* __restrict__ colU,
    const float* __restrict__ rowD, const float* __restrict__ colB3,
    float* __restrict__ C, __half* __restrict__ C16, int ldc, int M)
{
    const uint32_t sbase = smem_to_u32(s);
    const int tid  = threadIdx.x;
    const int warp = tid >> 5;
    const int lane = tid & 31;
    const int wm   = (warp & 1) * 64;
    const int wn   = (warp >> 1) * 32;
    const int grp  = lane >> 2;
    const int qd   = lane & 3;
    const int bm = (g >> 2) * 128;
    const int n0 = (g & 3) * 128;

    // ldmatrix per-lane address components
    const int arow = wm + (lane & 15);          // A row within tile
    const int acol = (lane >> 4) * 4;           // A k-halfword-pair col (words)
    const int brow = wn + (lane & 7);           // B row within tile
    const int bcol = ((lane >> 3) & 1) * 4;     // B col (words)

    float acc[4][4][4];
    #pragma unroll
    for (int i = 0; i < 4; i++)
        #pragma unroll
        for (int j = 0; j < 4; j++)
            #pragma unroll
            for (int q = 0; q < 4; q++) acc[i][j][q] = 0.f;

    gemm_load_stage(sbase, 0, A, B, bm, n0, 0, M, tid);
    CP_COMMIT();

    #pragma unroll 1
    for (int kc = 0; kc < DD / BK; kc++) {
        if (kc + 1 < DD / BK) {
            gemm_load_stage(sbase, (kc + 1) & 1, A, B, bm, n0, kc + 1, M, tid);
            CP_COMMIT();
            CP_WAIT(1);
        } else {
            CP_WAIT(0);
        }
        __syncthreads();

        const uint32_t As_b = sbase + (uint32_t)(kc & 1) * STAGE_WORDS * 4;
        const uint32_t Bs_b = As_b + TILE_WORDS * 4;

        #pragma unroll
        for (int ks = 0; ks < 2; ks++) {
            const int kw = ks * 8;
            uint32_t ah[4][4];
            #pragma unroll
            for (int mi = 0; mi < 4; mi++)
                ldsm_x4(ah[mi], As_b + (uint32_t)((arow + mi * 16) * RSTRIDE + kw + acol) * 4);
            #pragma unroll
            for (int nj = 0; nj < 4; nj++) {
                uint32_t bh[2];
                ldsm_x2(bh, Bs_b + (uint32_t)((brow + nj * 8) * RSTRIDE + kw + bcol) * 4);
                #pragma unroll
                for (int mi = 0; mi < 4; mi++)
                    mma_f16(acc[mi][nj], ah[mi], bh);
            }
        }
        __syncthreads();
    }

    #pragma unroll
    for (int mi = 0; mi < 4; mi++) {
        const int gr = bm + wm + mi * 16 + grp;
        float e0 = 0.f, d0v = 0.f, e1 = 0.f, d1v = 0.f;
        if (rowE) {
            if (gr < M)     { e0 = rowE[gr];     d0v = rowD[gr]; }
            if (gr + 8 < M) { e1 = rowE[gr + 8]; d1v = rowD[gr + 8]; }
        }
        #pragma unroll
        for (int nj = 0; nj < 4; nj++) {
            const int gc = n0 + wn + nj * 8 + qd * 2;
            float2 add0, add1;
            if (rowE) {
                const float2 uu = *(const float2*)(colU + gc);
                const float2 b3 = *(const float2*)(colB3 + gc);
                add0 = make_float2(e0 * uu.x + d0v * b3.x, e0 * uu.y + d0v * b3.y);
                add1 = make_float2(e1 * uu.x + d1v * b3.x, e1 * uu.y + d1v * b3.y);
            } else {
                const float2 bz = *(const float2*)(bias + gc);
                add0 = bz; add1 = bz;
            }
            float2 o0 = {acc[mi][nj][0] + add0.x, acc[mi][nj][1] + add0.y};
            float2 o1 = {acc[mi][nj][2] + add1.x, acc[mi][nj][3] + add1.y};
            if (C16) {
                if (gr < M)
                    *(__half2*)(C16 + (size_t)gr * ldc + gc) = __float22half2_rn(o0);
                if (gr + 8 < M)
                    *(__half2*)(C16 + (size_t)(gr + 8) * ldc + gc) = __float22half2_rn(o1);
            } else {
                if (gr < M)     *(float2*)(C + (size_t)gr * ldc + gc) = o0;
                if (gr + 8 < M) *(float2*)(C + (size_t)(gr + 8) * ldc + gc) = o1;
            }
        }
    }
}

// ---------------------------------------------------------------------------
// fusedAB: a0-GEMM CTAs + H1-GEMM CTAs + scatter CTAs in one grid
// ---------------------------------------------------------------------------
__global__ void __launch_bounds__(256, 2) fusedAB(
    const __half* __restrict__ A, const __half* __restrict__ B0,
    const __half* __restrict__ B1,
    const float* __restrict__ bias0, const float* __restrict__ bias1,
    float* __restrict__ C, __half* __restrict__ H1, int M,
    const int* __restrict__ rows, const int* __restrict__ cols,
    const float* __restrict__ vals, int* __restrict__ cursor,
    int2* __restrict__ edge, int E)
{
    extern __shared__ uint32_t s[];
    const int bid = blockIdx.x;
    if (bid < G1) {
        gemm_cta(bid, s, A, B0, bias0,
                 nullptr, nullptr, nullptr, nullptr, C, nullptr, 1024, M);
    } else if (bid < 2 * G1) {
        gemm_cta(bid - G1, s, A, B1, bias1,
                 nullptr, nullptr, nullptr, nullptr, nullptr, H1, DD, M);
    } else {
        int e = (bid - 2 * G1) * 256 + threadIdx.x;
        if (e < E) {
            int r = rows[e];
            int p = atomicAdd(&cursor[r], 1);
            edge[p] = make_int2(cols[e], __float_as_int(vals[e]));
        }
    }
}

// Final GEMM (standalone, rank-1 epilogue)
__global__ void __launch_bounds__(256, 2) gemm_final(
    const __half* __restrict__ A, const __half* __restrict__ B,
    const float* __restrict__ rowE, const float* __restrict__ colU,
    const float* __restrict__ rowD, const float* __restrict__ colB3,
    float* __restrict__ C, int M)
{
    extern __shared__ uint32_t s[];
    gemm_cta(blockIdx.x, s, A, B, nullptr, rowE, colU, rowD, colB3,
             C, nullptr, 1024, M);
}

// ---------------------------------------------------------------------------
// 3-phase parallel scan
// ---------------------------------------------------------------------------
#define SCB 256

__global__ void __launch_bounds__(SCB) scan_part(
    const int* __restrict__ cnt, int* __restrict__ row_ptr,
    int* __restrict__ partial, int M)
{
    __shared__ int sm[SCB];
    const int tid = threadIdx.x;
    const int i = blockIdx.x * SCB + tid;
    int v = (i < M) ? cnt[i] : 0;
    sm[tid] = v;
    __syncthreads();
    #pragma unroll
    for (int off = 1; off < SCB; off <<= 1) {
        int t = (tid >= off) ? sm[tid - off] : 0;
        __syncthreads();
        sm[tid] += t;
        __syncthreads();
    }
    if (i < M) row_ptr[i] = sm[tid] - v;
    if (tid == SCB - 1) partial[blockIdx.x] = sm[tid];
}

__global__ void __launch_bounds__(256) scan_top(int* __restrict__ partial, int nblk)
{
    __shared__ int sm[256];
    const int tid = threadIdx.x;
    int v = (tid < nblk) ? partial[tid] : 0;
    sm[tid] = v;
    __syncthreads();
    #pragma unroll
    for (int off = 1; off < 256; off <<= 1) {
        int t = (tid >= off) ? sm[tid - off] : 0;
        __syncthreads();
        sm[tid] += t;
        __syncthreads();
    }
    if (tid < nblk) partial[tid] = sm[tid] - v;
}

__global__ void __launch_bounds__(SCB) scan_add(
    int* __restrict__ row_ptr, int* __restrict__ cursor,
    const int* __restrict__ partial, int M, int E)
{
    const int i = blockIdx.x * SCB + threadIdx.x;
    if (i < M) {
        int v = row_ptr[i] + partial[blockIdx.x];
        row_ptr[i] = v;
        cursor[i]  = v;
    }
    if (i == 0) row_ptr[M] = E;
}

// ---------------------------------------------------------------------------
// fp16 CSR SpMM core
// ---------------------------------------------------------------------------
__device__ __forceinline__ float4 spmm_row_acc_h(
    const int* __restrict__ row_ptr, const int2* __restrict__ edge,
    const __half* __restrict__ in, int r, int tid)
{
    const size_t off = (size_t)tid * 4;
    int e = row_ptr[r];
    const int end = row_ptr[r + 1];
    float4 acc = {0.f, 0.f, 0.f, 0.f};

    for (; e + 2 <= end; e += 2) {
        const int2 e0 = __ldg(edge + e);
        const int2 e1 = __ldg(edge + e + 1);
        const float v0 = __int_as_float(e0.y);
        const float v1 = __int_as_float(e1.y);
        const uint2 r0 = *(const uint2*)(in + (size_t)e0.x * DD + off);
        const uint2 r1 = *(const uint2*)(in + (size_t)e1.x * DD + off);
        const float2 a0 = __half22float2(*(const __half2*)&r0.x);
        const float2 a1 = __half22float2(*(const __half2*)&r0.y);
        const float2 b0 = __half22float2(*(const __half2*)&r1.x);
        const float2 b1 = __half22float2(*(const __half2*)&r1.y);
        acc.x = fmaf(v0, a0.x, acc.x); acc.y = fmaf(v0, a0.y, acc.y);
        acc.z = fmaf(v0, a1.x, acc.z); acc.w = fmaf(v0, a1.y, acc.w);
        acc.x = fmaf(v1, b0.x, acc.x); acc.y = fmaf(v1, b0.y, acc.y);
        acc.z = fmaf(v1, b1.x, acc.z); acc.w = fmaf(v1, b1.y, acc.w);
    }
    if (e < end) {
        const int2 e0 = __ldg(edge + e);
        const float v0 = __int_as_float(e0.y);
        const uint2 r0 = *(const uint2*)(in + (size_t)e0.x * DD + off);
        const float2 a0 = __half22float2(*(const __half2*)&r0.x);
        const float2 a1 = __half22float2(*(const __half2*)&r0.y);
        acc.x = fmaf(v0, a0.x, acc.x); acc.y = fmaf(v0, a0.y, acc.y);
        acc.z = fmaf(v0, a1.x, acc.z); acc.w = fmaf(v0, a1.y, acc.w);
    }
    return acc;
}

__device__ __forceinline__ void store_h4(__half* dst, float4 v) {
    uint2 o;
    *(__half2*)&o.x = __float22half2_rn(make_float2(v.x, v.y));
    *(__half2*)&o.y = __float22half2_rn(make_float2(v.z, v.w));
    *(uint2*)dst = o;
}

// fusedC: spmm_mix || rowsum_d
__global__ void __launch_bounds__(128) fusedC(
    const int* __restrict__ row_ptr, const int2* __restrict__ edge,
    const __half* __restrict__ in,
    const float* __restrict__ a0, const float* __restrict__ nvec,
    __half* __restrict__ x1, float* __restrict__ dvec, int M)
{
    const int bid = blockIdx.x;
    const int tid = threadIdx.x;
    if (bid < M) {
        float4 acc = spmm_row_acc_h(row_ptr, edge, in, bid, tid);
        const float nv = nvec[bid];
        const float om = 1.f - nv;
        const float4 a = *(const float4*)(a0 + (size_t)bid * 1024 + (size_t)tid * 4);
        float4 o;
        o.x = a.x * nv + acc.x * om;
        o.y = a.y * nv + acc.y * om;
        o.z = a.z * nv + acc.z * om;
        o.w = a.w * nv + acc.w * om;
        store_h4(x1 + (size_t)bid * DD + (size_t)tid * 4, o);
    } else {
        const int r = (bid - M) * 4 + (tid >> 5);
        if (r >= M) return;
        const int lane = tid & 31;
        float acc = 0.f;
        for (int e = row_ptr[r] + lane; e < row_ptr[r + 1]; e += 32)
            acc += __int_as_float(__ldg(&edge[e].y));
        #pragma unroll
        for (int o = 16; o; o >>= 1) acc += __shfl_down_sync(0xffffffffu, acc, o);
        if (lane == 0) dvec[r] = acc;
    }
}

// fusedD: spmm (H1 = S·H2) || spmv_e || uvec
__global__ void __launch_bounds__(128) fusedD(
    const int* __restrict__ row_ptr, const int2* __restrict__ edge,
    const __half* __restrict__ in, __half* __restrict__ out,
    const float* __restrict__ dvec, float* __restrict__ evec,
    const float* __restrict__ b2, const float* __restrict__ W3,
    float* __restrict__ u, int M)
{
    const int bid = blockIdx.x;
    const int tid = threadIdx.x;
    const int UB = M + (M + 3) / 4;
    if (bid < M) {
        float4 acc = spmm_row_acc_h(row_ptr, edge, in, bid, tid);
        store_h4(out + (size_t)bid * DD + (size_t)tid * 4, acc);
    } else if (bid < UB) {
        const int r = (bid - M) * 4 + (tid >> 5);
        if (r >= M) return;
        const int lane = tid & 31;
        float acc = 0.f;
        for (int e = row_ptr[r] + lane; e < row_ptr[r + 1]; e += 32) {
            const int2 ev2 = __ldg(edge + e);
            acc = fmaf(__int_as_float(ev2.y), dvec[ev2.x], acc);
        }
        #pragma unroll
        for (int o = 16; o; o >>= 1) acc += __shfl_down_sync(0xffffffffu, acc, o);
        if (lane == 0) evec[r] = acc;
    } else {
        const int n = (bid - UB) * 128 + tid;
        float acc = 0.f;
        #pragma unroll 8
        for (int j = 0; j < DD; j++)
            acc = fmaf(b2[j], W3[j * DD + n], acc);
        u[n] = acc;
    }
}

// Plain fp16 SpMM (#3)
__global__ void __launch_bounds__(128) spmm_csr_h(
    const int* __restrict__ row_ptr, const int2* __restrict__ edge,
    const __half* __restrict__ in, __half* __restrict__ out)
{
    float4 acc = spmm_row_acc_h(row_ptr, edge, in, blockIdx.x, threadIdx.x);
    store_h4(out + (size_t)blockIdx.x * DD + (size_t)threadIdx.x * 4, acc);
}

// ---------------------------------------------------------------------------
// L1: W23 = W2@W3 || cnt zeroing
// ---------------------------------------------------------------------------
#define G512 (4 * DD)   // 2048 blocks of 128
__global__ void __launch_bounds__(128) gemm512cnt(
    const float* __restrict__ A, const float* __restrict__ B,
    float* __restrict__ C, int* __restrict__ cnt, int M)
{
    const int bid = blockIdx.x;
    if (bid < G512) {
        const int n = (bid & 3) * 128 + threadIdx.x;
        const int k = bid >> 2;
        float acc = 0.f;
        #pragma unroll 8
        for (int j = 0; j < DD; j++)
            acc = fmaf(A[k * DD + j], B[j * DD + n], acc);
        C[k * DD + n] = acc;
    } else {
        int i = (bid - G512) * 128 + threadIdx.x;
        if (i < M) cnt[i] = 0;
    }
}

// ---------------------------------------------------------------------------
// L2: prep (weight casts + A16 split) || hist
// ---------------------------------------------------------------------------
#define WN (3 * DD * DD)
__global__ void __launch_bounds__(256) prep_hist(
    const float* __restrict__ Lin1, const float* __restrict__ W1,
    const float* __restrict__ W23, const float* __restrict__ A1,
    __half* __restrict__ W16, __half* __restrict__ A16, int M,
    const int* __restrict__ rows, int* __restrict__ cnt, int E, int PB)
{
    const int bid = blockIdx.x;
    if (bid < PB) {
        size_t i = (size_t)bid * 256 + threadIdx.x;
        if (i < WN) {
            int w = (int)(i / (DD * DD));
            int j = (int)(i % (DD * DD));
            int n = j >> 9, k = j & 511;
            const float* src = (w == 0) ? Lin1 : (w == 1) ? W1 : W23;
            W16[i] = __float2half_rn(src[k * DD + n]);
            return;
        }
        size_t j = i - WN;
        if (j < (size_t)M * DD) {
            size_t r = j >> 9;
            int c = (int)(j & 511);
            A16[j] = __float2half_rn(A1[r * 513 + 1 + c]);
        }
    } else {
        int e = (bid - PB) * 256 + threadIdx.x;
        if (e < E) atomicAdd(&cnt[rows[e]], 1);
    }
}

// ---------------------------------------------------------------------------
// Host driver
// ---------------------------------------------------------------------------
extern "C" void kernel_launch(void* const* d_in, const int* in_sizes, int n_in,
                              void* d_out, int out_size)
{
    const float* A1       = (const float*)d_in[0];
    const int*   adj_rows = (const int*)  d_in[1];
    const int*   adj_cols = (const int*)  d_in[2];
    const float* adj_vals = (const float*)d_in[3];
    const float* Lin1     = (const float*)d_in[4];
    const float* Lin1_b   = (const float*)d_in[5];
    const float* nvec     = (const float*)d_in[6];
    const float* W1       = (const float*)d_in[7];
    const float* b1       = (const float*)d_in[8];
    const float* W2       = (const float*)d_in[9];
    const float* b2       = (const float*)d_in[10];
    const float* W3       = (const float*)d_in[11];
    const float* b3       = (const float*)d_in[12];
    float* out = (float*)d_out;

    const int M = in_sizes[6];   // 50000
    const int E = in_sizes[1];   // 1,600,000

    __half *A16, *H1, *H2, *W16;
    float *W23, *uvec, *dv, *ev;
    int *cnt, *rowptr, *cursor, *partial;
    int2 *edge;
    cudaGetSymbolAddress((void**)&A16, g_A16);
    cudaGetSymbolAddress((void**)&H1,  g_H1);
    cudaGetSymbolAddress((void**)&H2,  g_H2);
    cudaGetSymbolAddress((void**)&W16, g_W16);
    cudaGetSymbolAddress((void**)&W23,  g_W23);
    cudaGetSymbolAddress((void**)&uvec, g_uvec);
    cudaGetSymbolAddress((void**)&dv,   g_d);
    cudaGetSymbolAddress((void**)&ev,   g_e);
    cudaGetSymbolAddress((void**)&cnt,     g_cnt);
    cudaGetSymbolAddress((void**)&rowptr,  g_rowptr);
    cudaGetSymbolAddress((void**)&cursor,  g_cursor);
    cudaGetSymbolAddress((void**)&partial, g_partial);
    cudaGetSymbolAddress((void**)&edge,    g_edge);

    cudaFuncSetAttribute(fusedAB,    cudaFuncAttributeMaxDynamicSharedMemorySize, GEMM_SMEM);
    cudaFuncSetAttribute(gemm_final, cudaFuncAttributeMaxDynamicSharedMemorySize, GEMM_SMEM);

    __half* Wp[3] = {W16, W16 + (size_t)DD * DD, W16 + (size_t)2 * DD * DD};

    const int eblk = (E + 255) / 256;
    const int cntB = (M + 127) / 128;
    const size_t prep_total = (size_t)WN + (size_t)M * DD;
    const int PB = (int)((prep_total + 255) / 256);
    const int rsB = (M + 3) / 4;
    const int scanB = (M + SCB - 1) / SCB;

    // L1: W23 = W2@W3 || cnt zero
    gemm512cnt<<<G512 + cntB, 128>>>(W2, W3, W23, cnt, M);
    // L2: weight/input casts || hist
    prep_hist<<<PB + eblk, 256>>>(Lin1, W1, W23, A1, W16, A16, M,
                                  adj_rows, cnt, E, PB);
    // L3-5: parallel scan
    scan_part<<<scanB, SCB>>>(cnt, rowptr, partial, M);
    scan_top<<<1, 256>>>(partial, scanB);
    scan_add<<<scanB, SCB>>>(rowptr, cursor, partial, M, E);
    // L6: a0 GEMM + H1 GEMM || scatter
    fusedAB<<<2 * G1 + eblk, 256, GEMM_SMEM>>>(A16, Wp[0], Wp[1], Lin1_b, b1,
                                               out + 512, H1, M,
                                               adj_rows, adj_cols, adj_vals,
                                               cursor, edge, E);
    // L7: spmm_mix || rowsum_d
    fusedC<<<M + rsB, 128>>>(rowptr, edge, H1, out + 512, nvec, H2, dv, M);
    // L8: spmm #2 || spmv_e || uvec
    fusedD<<<M + rsB + 4, 128>>>(rowptr, edge, H2, H1, dv, ev, b2, W3, uvec, M);
    // L9: spmm #3
    spmm_csr_h<<<M, 128>>>(rowptr, edge, H1, A16);
    // L10: final GEMM: out[:,0:512) = t2 @ W23 + e⊗u + d⊗b3
    gemm_final<<<G1, 256, GEMM_SMEM>>>(A16, Wp[2], ev, uvec, dv, b3, out, M);
}

// round 13
// speedup vs baseline: 5.8000x; 1.0067x over previous
#include <cuda_runtime.h>
#include <cuda_fp16.h>
#include <cstdint>
#include <cstddef>

#define NN 50000
#define EE 1600000
#define DD 512

// ---------------------------------------------------------------------------
// Device scratch (no runtime alloc allowed)
// ---------------------------------------------------------------------------
__device__ __half g_A16[(size_t)NN * DD];
__device__ __half g_H1[(size_t)NN * DD];
__device__ __half g_H2[(size_t)NN * DD];
__device__ __half g_W16[(size_t)3 * DD * DD];
__device__ float  g_W23[(size_t)DD * DD];
__device__ float  g_uvec[DD];
// CSR scratch
__device__ int   g_cnt[NN];
__device__ int   g_rowptr[NN + 1];
__device__ int   g_cursor[NN];
__device__ int   g_partial[256];
__device__ int2  g_edge[EE];
__device__ float g_d[NN];
__device__ float g_e[NN];

// ---------------------------------------------------------------------------
// Helpers
// ---------------------------------------------------------------------------
__device__ __forceinline__ uint32_t smem_to_u32(const void* p) {
    uint32_t a;
    asm("{ .reg .u64 t; cvta.to.shared.u64 t, %1; cvt.u32.u64 %0, t; }" : "=r"(a) : "l"(p));
    return a;
}

__device__ __forceinline__ void cp16(uint32_t dst, const void* src, bool valid) {
    int sz = valid ? 16 : 0;
    asm volatile("cp.async.cg.shared.global [%0], [%1], 16, %2;"
                 :: "r"(dst), "l"(src), "r"(sz) : "memory");
}
#define CP_COMMIT() asm volatile("cp.async.commit_group;" ::: "memory")
#define CP_WAIT(n)  asm volatile("cp.async.wait_group %0;" :: "n"(n) : "memory")

__device__ __forceinline__ void mma_f16(float* d, const uint32_t* a, const uint32_t* b) {
    asm volatile("mma.sync.aligned.m16n8k16.row.col.f32.f16.f16.f32 "
                 "{%0,%1,%2,%3}, {%4,%5,%6,%7}, {%8,%9}, {%0,%1,%2,%3};"
                 : "+f"(d[0]), "+f"(d[1]), "+f"(d[2]), "+f"(d[3])
                 : "r"(a[0]), "r"(a[1]), "r"(a[2]), "r"(a[3]), "r"(b[0]), "r"(b[1]));
}

__device__ __forceinline__ void ldsm_x4(uint32_t* r, uint32_t addr) {
    asm volatile("ldmatrix.sync.aligned.m8n8.x4.shared.b16 {%0,%1,%2,%3}, [%4];"
                 : "=r"(r[0]), "=r"(r[1]), "=r"(r[2]), "=r"(r[3]) : "r"(addr));
}
__device__ __forceinline__ void ldsm_x2(uint32_t* r, uint32_t addr) {
    asm volatile("ldmatrix.sync.aligned.m8n8.x2.shared.b16 {%0,%1}, [%2];"
                 : "=r"(r[0]), "=r"(r[1]) : "r"(addr));
}

// L2 cache policies via createpolicy (portable cache_hint form, any width)
__device__ __forceinline__ uint64_t pol_evict_last() {
    uint64_t p;
    asm("createpolicy.fractional.L2::evict_last.b64 %0, 1.0;" : "=l"(p));
    return p;
}
__device__ __forceinline__ uint64_t pol_evict_first() {
    uint64_t p;
    asm("createpolicy.fractional.L2::evict_first.b64 %0, 1.0;" : "=l"(p));
    return p;
}

// Gather load: keep the feature plane resident in L2.
__device__ __forceinline__ uint2 ldg_gather(const __half* p, uint64_t pol) {
    uint2 v;
    asm volatile("ld.global.nc.L2::cache_hint.v2.u32 {%0,%1}, [%2], %3;"
                 : "=r"(v.x), "=r"(v.y) : "l"(p), "l"(pol));
    return v;
}
// Read-once fp32 stream (a0): don't pollute L2.
__device__ __forceinline__ float4 ldg_once_f4(const float* p, uint64_t pol) {
    float4 v;
    asm volatile("ld.global.L2::cache_hint.v4.f32 {%0,%1,%2,%3}, [%4], %5;"
                 : "=f"(v.x), "=f"(v.y), "=f"(v.z), "=f"(v.w) : "l"(p), "l"(pol));
    return v;
}
// Result store that will be gathered next: keep resident.
__device__ __forceinline__ void stg_resident(__half* p, uint2 v, uint64_t pol) {
    asm volatile("st.global.L2::cache_hint.v2.u32 [%0], {%1,%2}, %3;"
                 :: "l"(p), "r"(v.x), "r"(v.y), "l"(pol) : "memory");
}
__device__ __forceinline__ void stg_resident32(__half* p, uint32_t v, uint64_t pol) {
    asm volatile("st.global.L2::cache_hint.u32 [%0], %1, %2;"
                 :: "l"(p), "r"(v), "l"(pol) : "memory");
}

// ---------------------------------------------------------------------------
// GEMM CTA body (ldmatrix + fp16 mma, fp32 accum)
// ---------------------------------------------------------------------------
#define BK 32
#define RSTRIDE 20
#define TILE_WORDS (128 * RSTRIDE)
#define STAGE_WORDS (2 * TILE_WORDS)
#define GEMM_SMEM (2 * STAGE_WORDS * 4)   // 40960 bytes
#define NBY ((NN + 127) / 128)            // 391
#define G1  (4 * NBY)                     // CTAs per N=512 GEMM: 1564

__device__ __forceinline__ void gemm_load_stage(
    uint32_t sbase, int stage, const __half* A, const __half* B,
    int bm, int bn, int kc, int M, int tid)
{
    const uint32_t st = sbase + (uint32_t)stage * STAGE_WORDS * 4;
    const int r0 = tid >> 2;
    const int r1 = r0 + 64;
    const int j  = tid & 3;
    const uint32_t d0 = st + (uint32_t)(r0 * RSTRIDE + j * 4) * 4;
    const uint32_t d1 = st + (uint32_t)(r1 * RSTRIDE + j * 4) * 4;
    const size_t koff = (size_t)kc * BK + j * 8;
    const bool v0 = (bm + r0) < M;
    const bool v1 = (bm + r1) < M;

    cp16(d0,                  A + (size_t)(bm + r0) * DD + koff, v0);
    cp16(d1,                  A + (size_t)(bm + r1) * DD + koff, v1);
    cp16(d0 + TILE_WORDS * 4, B + (size_t)(bn + r0) * DD + koff, true);
    cp16(d1 + TILE_WORDS * 4, B + (size_t)(bn + r1) * DD + koff, true);
}

__device__ void gemm_cta(
    int g, uint32_t* s,
    const __half* __restrict__ A, const __half* __restrict__ B,
    const float* __restrict__ bias,
    const float* __restrict__ rowE, const float* __restrict__ colU,
    const float* __restrict__ rowD, const float* __restrict__ colB3,
    float* __restrict__ C, __half* __restrict__ C16, int ldc, int M)
{
    const uint32_t sbase = smem_to_u32(s);
    const int tid  = threadIdx.x;
    const int warp = tid >> 5;
    const int lane = tid & 31;
    const int wm   = (warp & 1) * 64;
    const int wn   = (warp >> 1) * 32;
    const int grp  = lane >> 2;
    const int qd   = lane & 3;
    const int bm = (g >> 2) * 128;
    const int n0 = (g & 3) * 128;

    const int arow = wm + (lane & 15);
    const int acol = (lane >> 4) * 4;
    const int brow = wn + (lane & 7);
    const int bcol = ((lane >> 3) & 1) * 4;

    float acc[4][4][4];
    #pragma unroll
    for (int i = 0; i < 4; i++)
        #pragma unroll
        for (int j = 0; j < 4; j++)
            #pragma unroll
            for (int q = 0; q < 4; q++) acc[i][j][q] = 0.f;

    gemm_load_stage(sbase, 0, A, B, bm, n0, 0, M, tid);
    CP_COMMIT();

    #pragma unroll 1
    for (int kc = 0; kc < DD / BK; kc++) {
        if (kc + 1 < DD / BK) {
            gemm_load_stage(sbase, (kc + 1) & 1, A, B, bm, n0, kc + 1, M, tid);
            CP_COMMIT();
            CP_WAIT(1);
        } else {
            CP_WAIT(0);
        }
        __syncthreads();

        const uint32_t As_b = sbase + (uint32_t)(kc & 1) * STAGE_WORDS * 4;
        const uint32_t Bs_b = As_b + TILE_WORDS * 4;

        #pragma unroll
        for (int ks = 0; ks < 2; ks++) {
            const int kw = ks * 8;
            uint32_t ah[4][4];
            #pragma unroll
            for (int mi = 0; mi < 4; mi++)
                ldsm_x4(ah[mi], As_b + (uint32_t)((arow + mi * 16) * RSTRIDE + kw + acol) * 4);
            #pragma unroll
            for (int nj = 0; nj < 4; nj++) {
                uint32_t bh[2];
                ldsm_x2(bh, Bs_b + (uint32_t)((brow + nj * 8) * RSTRIDE + kw + bcol) * 4);
                #pragma unroll
                for (int mi = 0; mi < 4; mi++)
                    mma_f16(acc[mi][nj], ah[mi], bh);
            }
        }
        __syncthreads();
    }

    const uint64_t pl = pol_evict_last();
    #pragma unroll
    for (int mi = 0; mi < 4; mi++) {
        const int gr = bm + wm + mi * 16 + grp;
        float e0 = 0.f, d0v = 0.f, e1 = 0.f, d1v = 0.f;
        if (rowE) {
            if (gr < M)     { e0 = rowE[gr];     d0v = rowD[gr]; }
            if (gr + 8 < M) { e1 = rowE[gr + 8]; d1v = rowD[gr + 8]; }
        }
        #pragma unroll
        for (int nj = 0; nj < 4; nj++) {
            const int gc = n0 + wn + nj * 8 + qd * 2;
            float2 add0, add1;
            if (rowE) {
                const float2 uu = *(const float2*)(colU + gc);
                const float2 b3 = *(const float2*)(colB3 + gc);
                add0 = make_float2(e0 * uu.x + d0v * b3.x, e0 * uu.y + d0v * b3.y);
                add1 = make_float2(e1 * uu.x + d1v * b3.x, e1 * uu.y + d1v * b3.y);
            } else {
                const float2 bz = *(const float2*)(bias + gc);
                add0 = bz; add1 = bz;
            }
            float2 o0 = {acc[mi][nj][0] + add0.x, acc[mi][nj][1] + add0.y};
            float2 o1 = {acc[mi][nj][2] + add1.x, acc[mi][nj][3] + add1.y};
            if (C16) {
                __half2 h0 = __float22half2_rn(o0);
                __half2 h1 = __float22half2_rn(o1);
                // fp16 GEMM output is gathered by the next SpMM — keep resident
                if (gr < M)
                    stg_resident32(C16 + (size_t)gr * ldc + gc, *(uint32_t*)&h0, pl);
                if (gr + 8 < M)
                    stg_resident32(C16 + (size_t)(gr + 8) * ldc + gc, *(uint32_t*)&h1, pl);
            } else {
                if (gr < M)     *(float2*)(C + (size_t)gr * ldc + gc) = o0;
                if (gr + 8 < M) *(float2*)(C + (size_t)(gr + 8) * ldc + gc) = o1;
            }
        }
    }
}

// ---------------------------------------------------------------------------
// fusedAB: a0-GEMM CTAs + H1-GEMM CTAs + scatter CTAs in one grid
// ---------------------------------------------------------------------------
__global__ void __launch_bounds__(256, 2) fusedAB(
    const __half* __restrict__ A, const __half* __restrict__ B0,
    const __half* __restrict__ B1,
    const float* __restrict__ bias0, const float* __restrict__ bias1,
    float* __restrict__ C, __half* __restrict__ H1, int M,
    const int* __restrict__ rows, const int* __restrict__ cols,
    const float* __restrict__ vals, int* __restrict__ cursor,
    int2* __restrict__ edge, int E)
{
    extern __shared__ uint32_t s[];
    const int bid = blockIdx.x;
    if (bid < G1) {
        gemm_cta(bid, s, A, B0, bias0,
                 nullptr, nullptr, nullptr, nullptr, C, nullptr, 1024, M);
    } else if (bid < 2 * G1) {
        gemm_cta(bid - G1, s, A, B1, bias1,
                 nullptr, nullptr, nullptr, nullptr, nullptr, H1, DD, M);
    } else {
        int e = (bid - 2 * G1) * 256 + threadIdx.x;
        if (e < E) {
            int r = rows[e];
            int p = atomicAdd(&cursor[r], 1);
            edge[p] = make_int2(cols[e], __float_as_int(vals[e]));
        }
    }
}

// Final GEMM (standalone, rank-1 epilogue)
__global__ void __launch_bounds__(256, 2) gemm_final(
    const __half* __restrict__ A, const __half* __restrict__ B,
    const float* __restrict__ rowE, const float* __restrict__ colU,
    const float* __restrict__ rowD, const float* __restrict__ colB3,
    float* __restrict__ C, int M)
{
    extern __shared__ uint32_t s[];
    gemm_cta(blockIdx.x, s, A, B, nullptr, rowE, colU, rowD, colB3,
             C, nullptr, 1024, M);
}

// ---------------------------------------------------------------------------
// 3-phase parallel scan
// ---------------------------------------------------------------------------
#define SCB 256

__global__ void __launch_bounds__(SCB) scan_part(
    const int* __restrict__ cnt, int* __restrict__ row_ptr,
    int* __restrict__ partial, int M)
{
    __shared__ int sm[SCB];
    const int tid = threadIdx.x;
    const int i = blockIdx.x * SCB + tid;
    int v = (i < M) ? cnt[i] : 0;
    sm[tid] = v;
    __syncthreads();
    #pragma unroll
    for (int off = 1; off < SCB; off <<= 1) {
        int t = (tid >= off) ? sm[tid - off] : 0;
        __syncthreads();
        sm[tid] += t;
        __syncthreads();
    }
    if (i < M) row_ptr[i] = sm[tid] - v;
    if (tid == SCB - 1) partial[blockIdx.x] = sm[tid];
}

__global__ void __launch_bounds__(256) scan_top(int* __restrict__ partial, int nblk)
{
    __shared__ int sm[256];
    const int tid = threadIdx.x;
    int v = (tid < nblk) ? partial[tid] : 0;
    sm[tid] = v;
    __syncthreads();
    #pragma unroll
    for (int off = 1; off < 256; off <<= 1) {
        int t = (tid >= off) ? sm[tid - off] : 0;
        __syncthreads();
        sm[tid] += t;
        __syncthreads();
    }
    if (tid < nblk) partial[tid] = sm[tid] - v;
}

__global__ void __launch_bounds__(SCB) scan_add(
    int* __restrict__ row_ptr, int* __restrict__ cursor,
    const int* __restrict__ partial, int M, int E)
{
    const int i = blockIdx.x * SCB + threadIdx.x;
    if (i < M) {
        int v = row_ptr[i] + partial[blockIdx.x];
        row_ptr[i] = v;
        cursor[i]  = v;
    }
    if (i == 0) row_ptr[M] = E;
}

// ---------------------------------------------------------------------------
// fp16 CSR SpMM core: 4-edge unrolled, evict_last gathers, fp32 accum
// ---------------------------------------------------------------------------
__device__ __forceinline__ void fma_h4(float4& acc, float v, uint2 r) {
    const float2 a0 = __half22float2(*(const __half2*)&r.x);
    const float2 a1 = __half22float2(*(const __half2*)&r.y);
    acc.x = fmaf(v, a0.x, acc.x); acc.y = fmaf(v, a0.y, acc.y);
    acc.z = fmaf(v, a1.x, acc.z); acc.w = fmaf(v, a1.y, acc.w);
}

__device__ __forceinline__ float4 spmm_row_acc_h(
    const int* __restrict__ row_ptr, const int2* __restrict__ edge,
    const __half* __restrict__ in, int r, int tid, uint64_t pol)
{
    const size_t off = (size_t)tid * 4;
    int e = row_ptr[r];
    const int end = row_ptr[r + 1];
    float4 acc = {0.f, 0.f, 0.f, 0.f};

    for (; e + 4 <= end; e += 4) {
        const int2 E0 = __ldg(edge + e);
        const int2 E1 = __ldg(edge + e + 1);
        const int2 E2 = __ldg(edge + e + 2);
        const int2 E3 = __ldg(edge + e + 3);
        const uint2 R0 = ldg_gather(in + (size_t)E0.x * DD + off, pol);
        const uint2 R1 = ldg_gather(in + (size_t)E1.x * DD + off, pol);
        const uint2 R2 = ldg_gather(in + (size_t)E2.x * DD + off, pol);
        const uint2 R3 = ldg_gather(in + (size_t)E3.x * DD + off, pol);
        fma_h4(acc, __int_as_float(E0.y), R0);
        fma_h4(acc, __int_as_float(E1.y), R1);
        fma_h4(acc, __int_as_float(E2.y), R2);
        fma_h4(acc, __int_as_float(E3.y), R3);
    }
    for (; e < end; e++) {
        const int2 E0 = __ldg(edge + e);
        const uint2 R0 = ldg_gather(in + (size_t)E0.x * DD + off, pol);
        fma_h4(acc, __int_as_float(E0.y), R0);
    }
    return acc;
}

__device__ __forceinline__ uint2 pack_h4(float4 v) {
    uint2 o;
    *(__half2*)&o.x = __float22half2_rn(make_float2(v.x, v.y));
    *(__half2*)&o.y = __float22half2_rn(make_float2(v.z, v.w));
    return o;
}

// fusedC: spmm_mix || rowsum_d
__global__ void __launch_bounds__(128) fusedC(
    const int* __restrict__ row_ptr, const int2* __restrict__ edge,
    const __half* __restrict__ in,
    const float* __restrict__ a0, const float* __restrict__ nvec,
    __half* __restrict__ x1, float* __restrict__ dvec, int M)
{
    const int bid = blockIdx.x;
    const int tid = threadIdx.x;
    if (bid < M) {
        const uint64_t pl = pol_evict_last();
        const uint64_t pf = pol_evict_first();
        float4 acc = spmm_row_acc_h(row_ptr, edge, in, bid, tid, pl);
        const float nv = nvec[bid];
        const float om = 1.f - nv;
        const float4 a = ldg_once_f4(a0 + (size_t)bid * 1024 + (size_t)tid * 4, pf);
        float4 o;
        o.x = a.x * nv + acc.x * om;
        o.y = a.y * nv + acc.y * om;
        o.z = a.z * nv + acc.z * om;
        o.w = a.w * nv + acc.w * om;
        stg_resident(x1 + (size_t)bid * DD + (size_t)tid * 4, pack_h4(o), pl);
    } else {
        const int r = (bid - M) * 4 + (tid >> 5);
        if (r >= M) return;
        const int lane = tid & 31;
        float acc = 0.f;
        for (int e = row_ptr[r] + lane; e < row_ptr[r + 1]; e += 32)
            acc += __int_as_float(__ldg(&edge[e].y));
        #pragma unroll
        for (int o = 16; o; o >>= 1) acc += __shfl_down_sync(0xffffffffu, acc, o);
        if (lane == 0) dvec[r] = acc;
    }
}

// fusedD: spmm (H1 = S·H2) || spmv_e || uvec
__global__ void __launch_bounds__(128) fusedD(
    const int* __restrict__ row_ptr, const int2* __restrict__ edge,
    const __half* __restrict__ in, __half* __restrict__ out,
    const float* __restrict__ dvec, float* __restrict__ evec,
    const float* __restrict__ b2, const float* __restrict__ W3,
    float* __restrict__ u, int M)
{
    const int bid = blockIdx.x;
    const int tid = threadIdx.x;
    const int UB = M + (M + 3) / 4;
    if (bid < M) {
        const uint64_t pl = pol_evict_last();
        float4 acc = spmm_row_acc_h(row_ptr, edge, in, bid, tid, pl);
        stg_resident(out + (size_t)bid * DD + (size_t)tid * 4, pack_h4(acc), pl);
    } else if (bid < UB) {
        const int r = (bid - M) * 4 + (tid >> 5);
        if (r >= M) return;
        const int lane = tid & 31;
        float acc = 0.f;
        for (int e = row_ptr[r] + lane; e < row_ptr[r + 1]; e += 32) {
            const int2 ev2 = __ldg(edge + e);
            acc = fmaf(__int_as_float(ev2.y), dvec[ev2.x], acc);
        }
        #pragma unroll
        for (int o = 16; o; o >>= 1) acc += __shfl_down_sync(0xffffffffu, acc, o);
        if (lane == 0) evec[r] = acc;
    } else {
        const int n = (bid - UB) * 128 + tid;
        float acc = 0.f;
        #pragma unroll 8
        for (int j = 0; j < DD; j++)
            acc = fmaf(b2[j], W3[j * DD + n], acc);
        u[n] = acc;
    }
}

// Plain fp16 SpMM (#3): output read linearly by final GEMM (default store)
__global__ void __launch_bounds__(128) spmm_csr_h(
    const int* __restrict__ row_ptr, const int2* __restrict__ edge,
    const __half* __restrict__ in, __half* __restrict__ out)
{
    const uint64_t pl = pol_evict_last();
    float4 acc = spmm_row_acc_h(row_ptr, edge, in, blockIdx.x, threadIdx.x, pl);
    uint2 o = pack_h4(acc);
    *(uint2*)(out + (size_t)blockIdx.x * DD + (size_t)threadIdx.x * 4) = o;
}

// ---------------------------------------------------------------------------
// L1: W23 = W2@W3 || cnt zeroing
// ---------------------------------------------------------------------------
#define G512 (4 * DD)
__global__ void __launch_bounds__(128) gemm512cnt(
    const float* __restrict__ A, const float* __restrict__ B,
    float* __restrict__ C, int* __restrict__ cnt, int M)
{
    const int bid = blockIdx.x;
    if (bid < G512) {
        const int n = (bid & 3) * 128 + threadIdx.x;
        const int k = bid >> 2;
        float acc = 0.f;
        #pragma unroll 8
        for (int j = 0; j < DD; j++)
            acc = fmaf(A[k * DD + j], B[j * DD + n], acc);
        C[k * DD + n] = acc;
    } else {
        int i = (bid - G512) * 128 + threadIdx.x;
        if (i < M) cnt[i] = 0;
    }
}

// ---------------------------------------------------------------------------
// L2: prep (weight casts + A16 split) || hist
// ---------------------------------------------------------------------------
#define WN (3 * DD * DD)
__global__ void __launch_bounds__(256) prep_hist(
    const float* __restrict__ Lin1, const float* __restrict__ W1,
    const float* __restrict__ W23, const float* __restrict__ A1,
    __half* __restrict__ W16, __half* __restrict__ A16, int M,
    const int* __restrict__ rows, int* __restrict__ cnt, int E, int PB)
{
    const int bid = blockIdx.x;
    if (bid < PB) {
        size_t i = (size_t)bid * 256 + threadIdx.x;
        if (i < WN) {
            int w = (int)(i / (DD * DD));
            int j = (int)(i % (DD * DD));
            int n = j >> 9, k = j & 511;
            const float* src = (w == 0) ? Lin1 : (w == 1) ? W1 : W23;
            W16[i] = __float2half_rn(src[k * DD + n]);
            return;
        }
        size_t j = i - WN;
        if (j < (size_t)M * DD) {
            size_t r = j >> 9;
            int c = (int)(j & 511);
            A16[j] = __float2half_rn(A1[r * 513 + 1 + c]);
        }
    } else {
        int e = (bid - PB) * 256 + threadIdx.x;
        if (e < E) atomicAdd(&cnt[rows[e]], 1);
    }
}

// ---------------------------------------------------------------------------
// Host driver
// ---------------------------------------------------------------------------
extern "C" void kernel_launch(void* const* d_in, const int* in_sizes, int n_in,
                              void* d_out, int out_size)
{
    const float* A1       = (const float*)d_in[0];
    const int*   adj_rows = (const int*)  d_in[1];
    const int*   adj_cols = (const int*)  d_in[2];
    const float* adj_vals = (const float*)d_in[3];
    const float* Lin1     = (const float*)d_in[4];
    const float* Lin1_b   = (const float*)d_in[5];
    const float* nvec     = (const float*)d_in[6];
    const float* W1       = (const float*)d_in[7];
    const float* b1       = (const float*)d_in[8];
    const float* W2       = (const float*)d_in[9];
    const float* b2       = (const float*)d_in[10];
    const float* W3       = (const float*)d_in[11];
    const float* b3       = (const float*)d_in[12];
    float* out = (float*)d_out;

    const int M = in_sizes[6];   // 50000
    const int E = in_sizes[1];   // 1,600,000

    __half *A16, *H1, *H2, *W16;
    float *W23, *uvec, *dv, *ev;
    int *cnt, *rowptr, *cursor, *partial;
    int2 *edge;
    cudaGetSymbolAddress((void**)&A16, g_A16);
    cudaGetSymbolAddress((void**)&H1,  g_H1);
    cudaGetSymbolAddress((void**)&H2,  g_H2);
    cudaGetSymbolAddress((void**)&W16, g_W16);
    cudaGetSymbolAddress((void**)&W23,  g_W23);
    cudaGetSymbolAddress((void**)&uvec, g_uvec);
    cudaGetSymbolAddress((void**)&dv,   g_d);
    cudaGetSymbolAddress((void**)&ev,   g_e);
    cudaGetSymbolAddress((void**)&cnt,     g_cnt);
    cudaGetSymbolAddress((void**)&rowptr,  g_rowptr);
    cudaGetSymbolAddress((void**)&cursor,  g_cursor);
    cudaGetSymbolAddress((void**)&partial, g_partial);
    cudaGetSymbolAddress((void**)&edge,    g_edge);

    cudaFuncSetAttribute(fusedAB,    cudaFuncAttributeMaxDynamicSharedMemorySize, GEMM_SMEM);
    cudaFuncSetAttribute(gemm_final, cudaFuncAttributeMaxDynamicSharedMemorySize, GEMM_SMEM);

    __half* Wp[3] = {W16, W16 + (size_t)DD * DD, W16 + (size_t)2 * DD * DD};

    const int eblk = (E + 255) / 256;
    const int cntB = (M + 127) / 128;
    const size_t prep_total = (size_t)WN + (size_t)M * DD;
    const int PB = (int)((prep_total + 255) / 256);
    const int rsB = (M + 3) / 4;
    const int scanB = (M + SCB - 1) / SCB;

    // L1: W23 = W2@W3 || cnt zero
    gemm512cnt<<<G512 + cntB, 128>>>(W2, W3, W23, cnt, M);
    // L2: weight/input casts || hist
    prep_hist<<<PB + eblk, 256>>>(Lin1, W1, W23, A1, W16, A16, M,
                                  adj_rows, cnt, E, PB);
    // L3-5: parallel scan
    scan_part<<<scanB, SCB>>>(cnt, rowptr, partial, M);
    scan_top<<<1, 256>>>(partial, scanB);
    scan_add<<<scanB, SCB>>>(rowptr, cursor, partial, M, E);
    // L6: a0 GEMM + H1 GEMM || scatter
    fusedAB<<<2 * G1 + eblk, 256, GEMM_SMEM>>>(A16, Wp[0], Wp[1], Lin1_b, b1,
                                               out + 512, H1, M,
                                               adj_rows, adj_cols, adj_vals,
                                               cursor, edge, E);
    // L7: spmm_mix || rowsum_d
    fusedC<<<M + rsB, 128>>>(rowptr, edge, H1, out + 512, nvec, H2, dv, M);
    // L8: spmm #2 || spmv_e || uvec
    fusedD<<<M + rsB + 4, 128>>>(rowptr, edge, H2, H1, dv, ev, b2, W3, uvec, M);
    // L9: spmm #3
    spmm_csr_h<<<M, 128>>>(rowptr, edge, H1, A16);
    // L10: final GEMM: out[:,0:512) = t2 @ W23 + e⊗u + d⊗b3
    gemm_final<<<G1, 256, GEMM_SMEM>>>(A16, Wp[2], ev, uvec, dv, b3, out, M);
}